// round 9
// baseline (speedup 1.0000x reference)
#include <cuda_runtime.h>
#include <math.h>

#define BS   512
#define MM   8
#define TT   2048
#define NS   2047
#define NCH  32
#define CL   64
#define SUB  8
#define TC   208   // fixed Riccati transient length

// Packed maps: W1[t]=[M;G;0] (32x16), W2[t]=[N;D;0] (32x8); rows 24-31 stay 0.
__device__ float g_W1[(size_t)NS * 512];
__device__ float g_W2[(size_t)NS * 256];
__device__ float g_P[NS * 128];        // U_t then P_t [16][8]
__device__ float g_T[NCH * 8 * 256];   // per-(chunk,group) 8-step product
__device__ float g_GS[NCH * 8 * 256];  // group suffixes
__device__ float g_A[NCH * 256];       // chunk products
__device__ float g_b[BS * NCH * 16];
__device__ float g_m0[BS * NCH * 16];
__device__ unsigned char g_nan[BS];

__device__ __forceinline__ float dot16(const float* a, const float* b) {
    const float4* A = (const float4*)a; const float4* B = (const float4*)b;
    float4 a0=A[0],a1=A[1],a2=A[2],a3=A[3], b0=B[0],b1=B[1],b2=B[2],b3=B[3];
    float s0=a0.x*b0.x+a0.y*b0.y+a0.z*b0.z+a0.w*b0.w;
    float s1=a1.x*b1.x+a1.y*b1.y+a1.z*b1.z+a1.w*b1.w;
    float s2=a2.x*b2.x+a2.y*b2.y+a2.z*b2.z+a2.w*b2.w;
    float s3=a3.x*b3.x+a3.y*b3.y+a3.z*b3.z+a3.w*b3.w;
    return (s0+s1)+(s2+s3);
}
__device__ __forceinline__ float dot8(const float* a, const float* b) {
    const float4* A = (const float4*)a; const float4* B = (const float4*)b;
    float4 a0=A[0],a1=A[1], b0=B[0],b1=B[1];
    return (a0.x*b0.x+a0.y*b0.y+a0.z*b0.z+a0.w*b0.w)
         + (a1.x*b1.x+a1.y*b1.y+a1.z*b1.z+a1.w*b1.w);
}

__global__ void nan_scan_kernel(const float* __restrict__ x) {
    int b = blockIdx.x, tid = threadIdx.x;
    const float* xb = x + (size_t)b * MM * TT;
    int bad = 0;
    for (int idx = tid; idx < MM * TT; idx += 256) {
        int t = idx & (TT - 1);
        if (t < NS) bad |= isnan(xb[idx]) ? 1 : 0;
    }
    int any = __syncthreads_or(bad);
    if (tid == 0) g_nan[b] = any ? 1 : 0;
}

// ---------------------------------------------------------------------------
// Phase 1: Riccati, 5 barriers/step, fixed TC steps, contiguous float4 dots.
//   HC=H cov ; S=HC H^T+R ; Sinv via warp0 register GJ
//   FP=F cov H^T ; Nn=FP Sinv ; cov'=F cov F^T+Q-0.5(Nn FP^T+FP Nn^T)
//   M=F-Nn H ; D=H Nn ; G=HF-D H (stored deferred)
// ---------------------------------------------------------------------------
__global__ void __launch_bounds__(256) phase1_kernel(
        const float* __restrict__ F_, const float* __restrict__ H_,
        const float* __restrict__ Q_, const float* __restrict__ R_) {
    __shared__ __align__(16) float sF[256], sH[128], sHT[128], sQ[256], sR[64], sHF[128];
    __shared__ __align__(16) float cov[256], HC[128], W[128], Sv[64], SvT[64];
    __shared__ __align__(16) float X[256], Y[256], FP[128], Nn[128], NnT[128], D[64];

    int tid = threadIdx.x;
    int i = tid >> 4, j = tid & 15;
    sF[tid] = F_[tid];
    sQ[tid] = Q_[tid];
    if (tid < 128) sH[tid] = H_[tid];
    if (tid < 64)  sR[tid] = R_[tid];
    cov[tid] = (i == j) ? 1.f : 0.f;
    __syncthreads();
    if (tid < 128) sHT[tid] = sH[(tid & 7) * 16 + (tid >> 3)];   // HT[j][a]=H[a][j]
    if (tid < 128) {
        int aa = tid >> 4, jj = tid & 15;
        float s = 0.f;
        #pragma unroll
        for (int e = 0; e < 16; e++) s += sH[aa * 16 + e] * sF[e * 16 + jj];
        sHF[tid] = s;
    }
    __syncthreads();

    for (int t = 0; t < TC; t++) {
        // s0: HC + deferred G (thr<128) ; X (thr>=128, x2)
        if (tid < 128) {
            int a = tid >> 4, c = tid & 15;
            HC[tid] = dot16(sH + a * 16, cov + c * 16);   // cov symmetric
            if (t > 0)
                g_W1[(size_t)(t - 1) * 512 + 256 + tid] =
                    sHF[tid] - dot8(D + a * 8, sHT + c * 8);
        } else {
            int u = tid - 128, r = u >> 4, c = u & 15;
            X[u]       = dot16(sF + r * 16,       cov + c * 16);
            X[u + 128] = dot16(sF + (r + 8) * 16, cov + c * 16);
        }
        __syncthreads();
        // s1: W=[S|I] (thr<128) ; FP (thr>=128)
        if (tid < 128) {
            int a = tid >> 4, c = tid & 15;
            W[tid] = (c < 8) ? sR[a * 8 + c] + dot16(HC + a * 16, sH + c * 16)
                             : ((a == c - 8) ? 1.f : 0.f);
        } else {
            int u = tid - 128;
            FP[u] = dot16(sF + (u >> 3) * 16, HC + (u & 7) * 16);
        }
        __syncthreads();
        // s2: warp0 register GJ -> Sv,SvT ; thr>=32 compute Y
        if (tid < 32) {
            int c = tid & 15, h = tid >> 4;
            float w[4];
            #pragma unroll
            for (int r = 0; r < 4; r++) w[r] = W[(h * 4 + r) * 16 + c];
            #pragma unroll
            for (int k = 0; k < 8; k++) {
                const int kh = k >> 2, kr = k & 3;
                float pivv  = __shfl_sync(0xffffffffu, w[kr], k + (kh << 4));
                float wkrow = __shfl_sync(0xffffffffu, w[kr], c + (kh << 4));
                float col0  = __shfl_sync(0xffffffffu, w[0], k + (h << 4));
                float col1  = __shfl_sync(0xffffffffu, w[1], k + (h << 4));
                float col2  = __shfl_sync(0xffffffffu, w[2], k + (h << 4));
                float col3  = __shfl_sync(0xffffffffu, w[3], k + (h << 4));
                float wkc = wkrow * __fdividef(1.0f, pivv);
                w[0] = (h * 4 + 0 == k) ? wkc : w[0] - col0 * wkc;
                w[1] = (h * 4 + 1 == k) ? wkc : w[1] - col1 * wkc;
                w[2] = (h * 4 + 2 == k) ? wkc : w[2] - col2 * wkc;
                w[3] = (h * 4 + 3 == k) ? wkc : w[3] - col3 * wkc;
            }
            if (c >= 8) {
                #pragma unroll
                for (int r = 0; r < 4; r++) {
                    Sv[(h * 4 + r) * 8 + (c - 8)]  = w[r];
                    SvT[(c - 8) * 8 + (h * 4 + r)] = w[r];
                }
            }
        } else {
            int u = tid - 32;
            Y[u] = dot16(X + (u >> 4) * 16, sF + (u & 15) * 16);
            if (u < 32) {
                int u2 = u + 224;
                Y[u2] = dot16(X + (u2 >> 4) * 16, sF + (u2 & 15) * 16);
            }
        }
        __syncthreads();
        // s3: Nn = FP * Sinv (+ transpose)
        if (tid < 128) {
            int r = tid >> 3, c = tid & 7;
            float v = dot8(FP + r * 8, SvT + c * 8);
            Nn[tid] = v;
            NnT[c * 16 + r] = v;
        }
        __syncthreads();
        // s4: cov update + M/N/D stores
        {
            float t1 = dot8(Nn + i * 8, FP + j * 8);
            float t2 = dot8(FP + i * 8, Nn + j * 8);
            float m  = sF[tid] - dot8(Nn + i * 8, sHT + j * 8);
            g_W1[(size_t)t * 512 + tid] = m;
            cov[tid] = Y[tid] + sQ[tid] - 0.5f * (t1 + t2);
        }
        if (tid < 128) {
            g_W2[(size_t)t * 256 + tid] = Nn[tid];
        } else if (tid < 192) {
            int u = tid - 128;
            float d = dot16(sH + (u >> 3) * 16, NnT + (u & 7) * 16);
            D[u] = d;
            g_W2[(size_t)t * 256 + 128 + u] = d;
        }
        __syncthreads();
    }
    if (tid < 128) {   // final deferred G
        int a = tid >> 4;
        g_W1[(size_t)(TC - 1) * 512 + 256 + tid] =
            sHF[tid] - dot8(D + a * 8, sHT + (tid & 15) * 8);
    }
}

// fill frozen tail [TC, NS)
__global__ void fill_kernel() {
    int t = TC + blockIdx.x;
    const int src = TC - 1;
    int tid = threadIdx.x;
    g_W1[(size_t)t * 512 + tid] = g_W1[(size_t)src * 512 + tid];
    if (tid < 128) {
        g_W1[(size_t)t * 512 + 256 + tid] = g_W1[(size_t)src * 512 + 256 + tid];
        g_W2[(size_t)t * 256 + tid] = g_W2[(size_t)src * 256 + tid];
    }
    if (tid < 64)
        g_W2[(size_t)t * 256 + 128 + tid] = g_W2[(size_t)src * 256 + 128 + tid];
}

// 3a: per-(chunk,group) 8-step serial suffix -> U_p in g_P, group product in g_T
__global__ void __launch_bounds__(256) group_serial_kernel() {
    int c = blockIdx.x >> 3, g = blockIdx.x & 7;
    int base = c * CL + g * 8;
    int n = NS - base; if (n > 8) n = 8;
    __shared__ float S[2][256], Mt[256], Nt[128];
    int tid = threadIdx.x;
    int i = tid >> 4, j = tid & 15;
    S[0][tid] = (i == j) ? 1.f : 0.f;
    int par = 0;
    float mreg = g_W1[(size_t)(base + n - 1) * 512 + tid];
    float nreg = (tid < 128) ? g_W2[(size_t)(base + n - 1) * 256 + tid] : 0.f;
    __syncthreads();
    for (int it = n - 1; it >= 0; --it) {
        Mt[tid] = mreg;
        if (tid < 128) Nt[tid] = nreg;
        __syncthreads();
        if (it > 0) {
            mreg = g_W1[(size_t)(base + it - 1) * 512 + tid];
            if (tid < 128) nreg = g_W2[(size_t)(base + it - 1) * 256 + tid];
        }
        if (tid < 128) {
            int r = tid >> 3, cc = tid & 7;
            float s = 0.f;
            #pragma unroll
            for (int e = 0; e < 16; e++) s += S[par][r * 16 + e] * Nt[e * 8 + cc];
            g_P[(base + it) * 128 + tid] = s;
        }
        float sn = 0.f;
        #pragma unroll
        for (int e = 0; e < 16; e++) sn += S[par][i * 16 + e] * Mt[e * 16 + j];
        S[par ^ 1][tid] = sn;
        __syncthreads();
        par ^= 1;
    }
    g_T[(c * 8 + g) * 256 + tid] = S[par][tid];
}

// 3b: per-chunk scan of 8 group products -> GS_g, A_c
__global__ void __launch_bounds__(256) group_scan_kernel() {
    int c = blockIdx.x;
    __shared__ float S[2][256], Tt[256];
    int tid = threadIdx.x;
    int i = tid >> 4, j = tid & 15;
    S[0][tid] = (i == j) ? 1.f : 0.f;
    int par = 0;
    for (int g = 7; g >= 0; --g) {
        Tt[tid] = g_T[(c * 8 + g) * 256 + tid];
        __syncthreads();
        float v = 0.f;
        #pragma unroll
        for (int e = 0; e < 16; e++) v += S[par][i * 16 + e] * Tt[e * 16 + j];
        S[par ^ 1][tid] = v;
        if (g >= 1) g_GS[(c * 8 + g) * 256 + tid] = v;
        __syncthreads();
        par ^= 1;
    }
    g_A[c * 256 + tid] = S[par][tid];
}

// 3c: apply GS_{g+1} to U (groups 0..6; group 7 already final)
__global__ void __launch_bounds__(256) apply_kernel() {
    int c = blockIdx.x / 7, g = blockIdx.x % 7;
    int base = c * CL + g * 8;
    __shared__ float GSs[256], Us[1024];
    int tid = threadIdx.x;
    GSs[tid] = g_GS[(c * 8 + g + 1) * 256 + tid];
    #pragma unroll
    for (int q = 0; q < 4; q++) {
        int k = tid + q * 256;
        Us[k] = g_P[(base + (k >> 7)) * 128 + (k & 127)];
    }
    __syncthreads();
    #pragma unroll
    for (int q = 0; q < 4; q++) {
        int k = tid + q * 256;
        int p = k >> 7, rc = k & 127, r = rc >> 3, cc = rc & 7;
        float v = 0.f;
        #pragma unroll
        for (int e = 0; e < 16; e++) v += GSs[r * 16 + e] * Us[p * 128 + e * 8 + cc];
        g_P[(base + p) * 128 + rc] = v;
    }
}

// Kernel 4: b_c = sum_t P_t * obs_t
#define BGB 8
__global__ void __launch_bounds__(256) bvec_kernel(const float* __restrict__ x) {
    int c = blockIdx.x & (NCH - 1);
    int bg = blockIdx.x >> 5;
    int cstart = c * CL;
    int clen = (NS - cstart < CL) ? (NS - cstart) : CL;
    __shared__ __align__(16) float sP[CL * 128];
    __shared__ __align__(16) float sX[BGB][CL][8];
    int tid = threadIdx.x;
    for (int idx = tid; idx < clen * 128; idx += 256)
        sP[idx] = g_P[cstart * 128 + idx];
    for (int idx = tid; idx < BGB * 8 * clen; idx += 256) {
        int s = idx % clen;
        int bm = idx / clen;
        int m = bm & 7, b = bm >> 3;
        sX[b][s][m] = x[((size_t)(bg * BGB + b) * MM + m) * TT + cstart + s];
    }
    __syncthreads();
    int w = tid >> 5, lane = tid & 31;
    int b = bg * BGB + w;
    if (lane < 16) {
        float acc = 0.f;
        for (int s = 0; s < clen; s++) {
            const float4* pp = (const float4*)&sP[s * 128 + lane * 8];
            float4 p0 = pp[0], p1 = pp[1];
            const float4* op = (const float4*)&sX[w][s][0];
            float4 o0 = op[0], o1 = op[1];
            acc += p0.x*o0.x + p0.y*o0.y + p0.z*o0.z + p0.w*o0.w
                 + p1.x*o1.x + p1.y*o1.y + p1.z*o1.z + p1.w*o1.w;
        }
        g_b[(b * NCH + c) * 16 + lane] = acc;
    }
}

// Kernel 5: serial scan over 32 chunks
__global__ void __launch_bounds__(256) scan_kernel() {
    __shared__ float sA[NCH * 256];
    int tid = threadIdx.x;
    for (int idx = tid; idx < NCH * 256; idx += 256) sA[idx] = g_A[idx];
    __syncthreads();
    int w = tid >> 5, lane = tid & 31;
    int b = blockIdx.x * 8 + w;
    int row = lane & 15;
    float mean_i = 0.f;
    float breg = (lane < 16) ? g_b[(b * NCH + 0) * 16 + lane] : 0.f;
    for (int c = 0; c < NCH; c++) {
        if (lane < 16) g_m0[(b * NCH + c) * 16 + lane] = mean_i;
        float bn = (lane < 16 && c + 1 < NCH) ? g_b[(b * NCH + c + 1) * 16 + lane] : 0.f;
        float nm = breg;
        #pragma unroll
        for (int e = 0; e < 16; e++) {
            float me = __shfl_sync(0xffffffffu, mean_i, e);
            nm += sA[c * 256 + row * 16 + e] * me;
        }
        mean_i = nm;
        breg = bn;
    }
}

// Kernel 6: within-chunk recursion + output
__global__ void __launch_bounds__(512) phase2b_kernel(const float* __restrict__ x,
                                                      float* __restrict__ out) {
    int c = blockIdx.x & (NCH - 1);
    int bg = blockIdx.x >> 5;
    int cstart = c * CL;
    int clen = (NS - cstart < CL) ? (NS - cstart) : CL;
    __shared__ __align__(16) float sW1[SUB][32][20];
    __shared__ __align__(16) float sW2[SUB][32][12];
    __shared__ __align__(16) float sX[16][SUB][8];
    __shared__ __align__(16) float sY[16][8][SUB];
    __shared__ __align__(16) float sMean[16][16];

    int tid = threadIdx.x, w = tid >> 5, lane = tid & 31;
    int b = bg * 16 + w;
    const size_t xbase = (size_t)b * MM * TT;
    if (lane < 16) sMean[w][lane] = g_m0[(b * NCH + c) * 16 + lane];
    if (c == 0 && lane < 8) out[xbase + (size_t)lane * TT] = 0.f;
    __syncwarp();

    for (int t0 = 0; t0 < clen; t0 += SUB) {
        int ns = (clen - t0 < SUB) ? (clen - t0) : SUB;
        __syncthreads();
        for (int idx = tid; idx < ns * 512; idx += 512) {
            int s = idx >> 9, rc = idx & 511;
            sW1[s][rc >> 4][rc & 15] = g_W1[(size_t)(cstart + t0 + s) * 512 + rc];
        }
        for (int idx = tid; idx < ns * 256; idx += 512) {
            int s = idx >> 8, rc = idx & 255;
            sW2[s][rc >> 3][rc & 7] = g_W2[(size_t)(cstart + t0 + s) * 256 + rc];
        }
        for (int idx = tid; idx < 128 * ns; idx += 512) {
            int s = idx % ns;
            int bm = idx / ns;
            int m = bm & 7, bb = bm >> 3;
            sX[bb][s][m] = x[((size_t)(bg * 16 + bb) * MM + m) * TT + cstart + t0 + s];
        }
        __syncthreads();

        for (int s = 0; s < ns; s++) {
            const float4* w1 = (const float4*)&sW1[s][lane][0];
            float4 a0 = w1[0], a1 = w1[1], a2 = w1[2], a3 = w1[3];
            const float4* w2 = (const float4*)&sW2[s][lane][0];
            float4 c0 = w2[0], c1 = w2[1];
            const float4* mp = (const float4*)&sMean[w][0];
            float4 m0 = mp[0], m1 = mp[1], m2 = mp[2], m3 = mp[3];
            const float4* op = (const float4*)&sX[w][s][0];
            float4 o0 = op[0], o1 = op[1];
            float s0 = a0.x*m0.x + a0.y*m0.y + a0.z*m0.z + a0.w*m0.w;
            float s1 = a1.x*m1.x + a1.y*m1.y + a1.z*m1.z + a1.w*m1.w;
            float s2 = a2.x*m2.x + a2.y*m2.y + a2.z*m2.z + a2.w*m2.w;
            float s3 = a3.x*m3.x + a3.y*m3.y + a3.z*m3.z + a3.w*m3.w;
            float s4 = c0.x*o0.x + c0.y*o0.y + c0.z*o0.z + c0.w*o0.w;
            float s5 = c1.x*o1.x + c1.y*o1.y + c1.z*o1.z + c1.w*o1.w;
            float acc = ((s0 + s1) + (s2 + s3)) + (s4 + s5);
            __syncwarp();
            if (lane < 16)      sMean[w][lane] = acc;
            else if (lane < 24) sY[w][lane - 16][s] = acc;
            __syncwarp();
        }
        __syncthreads();
        for (int idx = tid; idx < 128 * ns; idx += 512) {
            int s = idx % ns;
            int bm = idx / ns;
            int m = bm & 7, bb = bm >> 3;
            out[((size_t)(bg * 16 + bb) * MM + m) * TT + cstart + t0 + s + 1] = sY[bb][m][s];
        }
    }
}

// Kernel 7: exact per-batch fallback for NaN-containing batches
__global__ void slow_kernel(const float* __restrict__ x, const float* __restrict__ F_,
                            const float* __restrict__ H_, const float* __restrict__ Q_,
                            const float* __restrict__ R_, float* __restrict__ out) {
    int b = blockIdx.x;
    if (!g_nan[b]) return;
    int tid = threadIdx.x;
    __shared__ float sF[256], sH[128], sQ[256], sR[64];
    __shared__ float cov[256], covn[256], P[128], W[2][128], K[128], CU[256], FC[256];
    __shared__ float mean[16], meanu[16], meanp[16], obs[8], resid[8];
    __shared__ int nanb;

    sF[tid] = F_[tid];
    sQ[tid] = Q_[tid];
    if (tid < 128) sH[tid] = H_[tid];
    if (tid < 64)  sR[tid] = R_[tid];
    cov[tid] = ((tid >> 4) == (tid & 15)) ? 1.f : 0.f;
    if (tid < 16) mean[tid] = 0.f;
    if (tid < 8)  out[((size_t)b * MM + tid) * TT] = 0.f;
    __syncthreads();

    for (int t = 0; t < NS; t++) {
        if (tid == 0) {
            int nb = 0;
            for (int j = 0; j < 8; j++) {
                float v = x[((size_t)b * MM + j) * TT + t];
                if (isnan(v)) { nb = 1; v = 0.f; }
                obs[j] = v;
            }
            nanb = nb;
        }
        __syncthreads();
        if (tid < 128) {
            int i = tid >> 3, j = tid & 7;
            float s = 0.f;
            #pragma unroll
            for (int e = 0; e < 16; e++) s += cov[i * 16 + e] * sH[j * 16 + e];
            P[tid] = s;
        }
        if (tid >= 128 && tid < 136) {
            int j = tid - 128;
            float s = obs[j];
            #pragma unroll
            for (int e = 0; e < 16; e++) s -= sH[j * 16 + e] * mean[e];
            resid[j] = s;
        }
        __syncthreads();
        if (tid < 128) {
            int a = tid >> 4, c = tid & 15;
            float v;
            if (c < 8) {
                float s = sR[a * 8 + c];
                #pragma unroll
                for (int e = 0; e < 16; e++) s += sH[a * 16 + e] * P[e * 8 + c];
                v = s;
            } else v = (a == (c - 8)) ? 1.f : 0.f;
            W[0][a * 16 + c] = v;
        }
        __syncthreads();
        #pragma unroll 1
        for (int k = 0; k < 8; k++) {
            int cur = k & 1;
            if (tid < 128) {
                int a = tid >> 4, c = tid & 15;
                float piv = W[cur][k * 16 + k];
                float wkc = W[cur][k * 16 + c] / piv;
                W[cur ^ 1][a * 16 + c] = (a == k) ? wkc
                                                  : W[cur][a * 16 + c] - W[cur][a * 16 + k] * wkc;
            }
            __syncthreads();
        }
        if (tid < 128) {
            int i = tid >> 3, j = tid & 7;
            float s = 0.f;
            #pragma unroll
            for (int a = 0; a < 8; a++) s += P[i * 8 + a] * W[0][a * 16 + 8 + j];
            K[tid] = s;
        }
        __syncthreads();
        if (tid < 16) {
            float s = mean[tid];
            #pragma unroll
            for (int a = 0; a < 8; a++) s += K[tid * 8 + a] * resid[a];
            meanu[tid] = nanb ? mean[tid] : s;
        }
        {
            int i = tid >> 4, j = tid & 15;
            float s = cov[tid];
            #pragma unroll
            for (int a = 0; a < 8; a++) s -= K[i * 8 + a] * P[j * 8 + a];
            CU[tid] = nanb ? cov[tid] : s;
        }
        __syncthreads();
        {
            int i = tid >> 4, j = tid & 15;
            float s = 0.f;
            #pragma unroll
            for (int e = 0; e < 16; e++)
                s += sF[i * 16 + e] * 0.5f * (CU[e * 16 + j] + CU[j * 16 + e]);
            FC[tid] = s;
        }
        if (tid < 16) {
            float s = 0.f;
            #pragma unroll
            for (int e = 0; e < 16; e++) s += sF[tid * 16 + e] * meanu[e];
            meanp[tid] = s;
        }
        __syncthreads();
        {
            int i = tid >> 4, j = tid & 15;
            float s = sQ[tid];
            #pragma unroll
            for (int e = 0; e < 16; e++) s += FC[i * 16 + e] * sF[j * 16 + e];
            covn[tid] = s;
        }
        if (tid < 8) {
            float s = 0.f;
            #pragma unroll
            for (int e = 0; e < 16; e++) s += sH[tid * 16 + e] * meanp[e];
            out[((size_t)b * MM + tid) * TT + t + 1] = s;
        }
        __syncthreads();
        cov[tid] = covn[tid];
        if (tid < 16) mean[tid] = meanp[tid];
        __syncthreads();
    }
}

extern "C" void kernel_launch(void* const* d_in, const int* in_sizes, int n_in,
                              void* d_out, int out_size) {
    const float* x = (const float*)d_in[0];
    const float* F = (const float*)d_in[1];
    const float* H = (const float*)d_in[2];
    const float* Q = (const float*)d_in[3];
    const float* R = (const float*)d_in[4];
    float* out = (float*)d_out;

    nan_scan_kernel<<<BS, 256>>>(x);
    phase1_kernel<<<1, 256>>>(F, H, Q, R);
    fill_kernel<<<NS - TC, 256>>>();
    group_serial_kernel<<<NCH * 8, 256>>>();
    group_scan_kernel<<<NCH, 256>>>();
    apply_kernel<<<NCH * 7, 256>>>();
    bvec_kernel<<<NCH * (BS / BGB), 256>>>(x);
    scan_kernel<<<BS / 8, 256>>>();
    phase2b_kernel<<<NCH * (BS / 16), 512>>>(x, out);
    slow_kernel<<<BS, 256>>>(x, F, H, Q, R, out);
}

// round 10
// speedup vs baseline: 1.7435x; 1.7435x over previous
#include <cuda_runtime.h>
#include <math.h>

#define BS   512
#define MM   8
#define TT   2048
#define NS   2047
#define NCH  32
#define CL   64
#define SUB  8
#define CONV_EPS 1.5e-3f

// Packed maps: W1[t]=[M;G;0] (32x16), W2[t]=[N;D;0] (32x8); rows 24-31 stay 0.
__device__ float g_W1[(size_t)NS * 512];
__device__ float g_W2[(size_t)NS * 256];
__device__ float g_P[NS * 128];        // U_t then P_t [16][8]
__device__ float g_T[NCH * 8 * 256];   // per-(chunk,group) 8-step product
__device__ float g_GS[NCH * 8 * 256];  // group suffixes
__device__ float g_A[NCH * 256];       // chunk products
__device__ float g_b[BS * NCH * 16];
__device__ float g_m0[BS * NCH * 16];
__device__ int   g_tc;
__device__ unsigned char g_nan[BS];

__global__ void nan_scan_kernel(const float* __restrict__ x) {
    int b = blockIdx.x, tid = threadIdx.x;
    const float* xb = x + (size_t)b * MM * TT;
    int bad = 0;
    for (int idx = tid; idx < MM * TT; idx += 256) {
        int t = idx & (TT - 1);
        if (t < NS) bad |= isnan(xb[idx]) ? 1 : 0;
    }
    int any = __syncthreads_or(bad);
    if (tid == 0) g_nan[b] = any ? 1 : 0;
}

// ---------------------------------------------------------------------------
// Phase 1 (R7-proven structure): 6 barriers/step, warp0 register GJ in the
// shadow of F*cov / F*P / Y products. Convergence exit, eps=1.5e-3.
// ---------------------------------------------------------------------------
__global__ void __launch_bounds__(256) phase1_kernel(
        const float* __restrict__ F_, const float* __restrict__ H_,
        const float* __restrict__ Q_, const float* __restrict__ R_) {
    __shared__ float sF[256], sH[128], sQ[256], sR[64];
    __shared__ float cov[256];
    __shared__ float P[128];       // cov H^T
    __shared__ float W[128];       // [S | I]
    __shared__ float Sv[64];
    __shared__ float X[256];       // F cov
    __shared__ float Y[256];       // X F^T
    __shared__ float FP[128];
    __shared__ float Nn[128];
    __shared__ float Mm[256];
    __shared__ float covn[256];

    int tid = threadIdx.x;
    int i = tid >> 4, j = tid & 15;
    sF[tid] = F_[tid];
    sQ[tid] = Q_[tid];
    if (tid < 128) sH[tid] = H_[tid];
    if (tid < 64)  sR[tid] = R_[tid];
    cov[tid] = (i == j) ? 1.f : 0.f;
    __syncthreads();

    int tc = NS;
    for (int t = 0; t < NS; t++) {
        // s0: P = cov H^T (tid<128) ; X rows 0-7 (tid>=128)
        if (tid < 128) {
            int r = tid >> 3, c = tid & 7;
            float a0 = 0.f, a1 = 0.f;
            #pragma unroll
            for (int e = 0; e < 16; e += 2) {
                a0 += cov[r * 16 + e]     * sH[c * 16 + e];
                a1 += cov[r * 16 + e + 1] * sH[c * 16 + e + 1];
            }
            P[tid] = a0 + a1;
        } else {
            int u = tid - 128;
            int r = u >> 4, c = u & 15;
            float a0 = 0.f, a1 = 0.f;
            #pragma unroll
            for (int e = 0; e < 16; e += 2) {
                a0 += sF[r * 16 + e]     * cov[c * 16 + e];
                a1 += sF[r * 16 + e + 1] * cov[c * 16 + e + 1];
            }
            X[u] = a0 + a1;
        }
        __syncthreads();
        // s1: W=[S|I] (tid<128) ; X rows 8-15
        if (tid < 128) {
            int a = tid >> 4, c = tid & 15;
            float v;
            if (c < 8) {
                float s0 = sR[a * 8 + c], s1 = 0.f;
                #pragma unroll
                for (int e = 0; e < 16; e += 2) {
                    s0 += sH[a * 16 + e]     * P[e * 8 + c];
                    s1 += sH[a * 16 + e + 1] * P[(e + 1) * 8 + c];
                }
                v = s0 + s1;
            } else {
                v = (a == (c - 8)) ? 1.f : 0.f;
            }
            W[a * 16 + c] = v;
        } else {
            int r = tid >> 4, c = tid & 15;
            float a0 = 0.f, a1 = 0.f;
            #pragma unroll
            for (int e = 0; e < 16; e += 2) {
                a0 += sF[r * 16 + e]     * cov[c * 16 + e];
                a1 += sF[r * 16 + e + 1] * cov[c * 16 + e + 1];
            }
            X[tid] = a0 + a1;
        }
        __syncthreads();
        // s2: warp0 register GJ ; warps1-3 FP ; warps4-7 Y rows 0-7
        if (tid < 32) {
            int c = tid & 15, h = tid >> 4;
            float w[4];
            #pragma unroll
            for (int r = 0; r < 4; r++) w[r] = W[(h * 4 + r) * 16 + c];
            #pragma unroll
            for (int k = 0; k < 8; k++) {
                const int kh = k >> 2, kr = k & 3;
                float pivv  = __shfl_sync(0xffffffffu, w[kr], k + (kh << 4));
                float wkrow = __shfl_sync(0xffffffffu, w[kr], c + (kh << 4));
                float col0  = __shfl_sync(0xffffffffu, w[0], k + (h << 4));
                float col1  = __shfl_sync(0xffffffffu, w[1], k + (h << 4));
                float col2  = __shfl_sync(0xffffffffu, w[2], k + (h << 4));
                float col3  = __shfl_sync(0xffffffffu, w[3], k + (h << 4));
                float wkc = wkrow * __fdividef(1.0f, pivv);
                w[0] = (h * 4 + 0 == k) ? wkc : w[0] - col0 * wkc;
                w[1] = (h * 4 + 1 == k) ? wkc : w[1] - col1 * wkc;
                w[2] = (h * 4 + 2 == k) ? wkc : w[2] - col2 * wkc;
                w[3] = (h * 4 + 3 == k) ? wkc : w[3] - col3 * wkc;
            }
            if (c >= 8) {
                #pragma unroll
                for (int r = 0; r < 4; r++)
                    Sv[(h * 4 + r) * 8 + (c - 8)] = w[r];
            }
        } else if (tid < 128) {
            int u = tid - 32;
            {
                int r = u >> 3, c = u & 7;
                float a0 = 0.f, a1 = 0.f;
                #pragma unroll
                for (int e = 0; e < 16; e += 2) {
                    a0 += sF[r * 16 + e]     * P[e * 8 + c];
                    a1 += sF[r * 16 + e + 1] * P[(e + 1) * 8 + c];
                }
                FP[u] = a0 + a1;
            }
            if (u < 32) {
                int u2 = u + 96;
                int r = u2 >> 3, c = u2 & 7;
                float a0 = 0.f, a1 = 0.f;
                #pragma unroll
                for (int e = 0; e < 16; e += 2) {
                    a0 += sF[r * 16 + e]     * P[e * 8 + c];
                    a1 += sF[r * 16 + e + 1] * P[(e + 1) * 8 + c];
                }
                FP[u2] = a0 + a1;
            }
        } else {
            int u = tid - 128;
            int r = u >> 4, c = u & 15;
            float a0 = 0.f, a1 = 0.f;
            #pragma unroll
            for (int e = 0; e < 16; e += 2) {
                a0 += X[r * 16 + e]     * sF[c * 16 + e];
                a1 += X[r * 16 + e + 1] * sF[c * 16 + e + 1];
            }
            Y[u] = a0 + a1;
        }
        __syncthreads();
        // s3: Nn = FP * Sinv (tid<128) ; Y rows 8-15
        if (tid < 128) {
            int r = tid >> 3, c = tid & 7;
            float s0 = 0.f, s1 = 0.f;
            #pragma unroll
            for (int a = 0; a < 8; a += 2) {
                s0 += FP[r * 8 + a]     * Sv[a * 8 + c];
                s1 += FP[r * 8 + a + 1] * Sv[(a + 1) * 8 + c];
            }
            Nn[tid] = s0 + s1;
        } else {
            int r = tid >> 4, c = tid & 15;
            float a0 = 0.f, a1 = 0.f;
            #pragma unroll
            for (int e = 0; e < 16; e += 2) {
                a0 += X[r * 16 + e]     * sF[c * 16 + e];
                a1 += X[r * 16 + e + 1] * sF[c * 16 + e + 1];
            }
            Y[tid] = a0 + a1;
        }
        __syncthreads();
        // s4: covn and Mm
        {
            float t1 = 0.f, t2 = 0.f, m = sF[tid];
            #pragma unroll
            for (int a = 0; a < 8; a++) {
                float ni = Nn[i * 8 + a], fi = FP[i * 8 + a];
                t1 += ni * FP[j * 8 + a];
                t2 += fi * Nn[j * 8 + a];
                m  -= ni * sH[a * 16 + j];
            }
            covn[tid] = Y[tid] + sQ[tid] - 0.5f * (t1 + t2);
            Mm[tid] = m;
        }
        __syncthreads();
        // s5: W1/W2 stores + convergence
        g_W1[(size_t)t * 512 + tid] = Mm[tid];
        if (tid < 128) {
            g_W2[(size_t)t * 256 + tid] = Nn[tid];
            int a = tid >> 4, jj = tid & 15;
            float s0 = 0.f, s1 = 0.f;
            #pragma unroll
            for (int e = 0; e < 16; e += 2) {
                s0 += sH[a * 16 + e]     * Mm[e * 16 + jj];
                s1 += sH[a * 16 + e + 1] * Mm[(e + 1) * 16 + jj];
            }
            g_W1[(size_t)t * 512 + 256 + tid] = s0 + s1;
        } else if (tid < 192) {
            int u = tid - 128, a = u >> 3, jj = u & 7;
            float s0 = 0.f, s1 = 0.f;
            #pragma unroll
            for (int e = 0; e < 16; e += 2) {
                s0 += sH[a * 16 + e]     * Nn[e * 8 + jj];
                s1 += sH[a * 16 + e + 1] * Nn[(e + 1) * 8 + jj];
            }
            g_W2[(size_t)t * 256 + 128 + u] = s0 + s1;
        }
        float oldc = cov[tid];
        float dlt = fabsf(covn[tid] - oldc);
        cov[tid] = covn[tid];
        int any = __syncthreads_or(dlt > CONV_EPS * (fabsf(oldc) + 1e-2f));
        if (!any) { tc = t + 1; break; }
    }
    if (tid == 0) g_tc = tc;
}

// fill frozen tail [g_tc, NS)
__global__ void fill_kernel() {
    int t = blockIdx.x;
    int tc = g_tc;
    if (t < tc) return;
    int src = tc - 1;
    int tid = threadIdx.x;
    g_W1[(size_t)t * 512 + tid] = g_W1[(size_t)src * 512 + tid];
    if (tid < 128) {
        g_W1[(size_t)t * 512 + 256 + tid] = g_W1[(size_t)src * 512 + 256 + tid];
        g_W2[(size_t)t * 256 + tid] = g_W2[(size_t)src * 256 + tid];
    }
    if (tid < 64)
        g_W2[(size_t)t * 256 + 128 + tid] = g_W2[(size_t)src * 256 + 128 + tid];
}

// 3a: per-(chunk,group) 8-step serial suffix -> U_p in g_P, group product g_T
__global__ void __launch_bounds__(256) group_serial_kernel() {
    int c = blockIdx.x >> 3, g = blockIdx.x & 7;
    int base = c * CL + g * 8;
    int n = NS - base; if (n > 8) n = 8;
    __shared__ float S[2][256], Mt[256], Nt[128];
    int tid = threadIdx.x;
    int i = tid >> 4, j = tid & 15;
    S[0][tid] = (i == j) ? 1.f : 0.f;
    int par = 0;
    float mreg = g_W1[(size_t)(base + n - 1) * 512 + tid];
    float nreg = (tid < 128) ? g_W2[(size_t)(base + n - 1) * 256 + tid] : 0.f;
    __syncthreads();
    for (int it = n - 1; it >= 0; --it) {
        Mt[tid] = mreg;
        if (tid < 128) Nt[tid] = nreg;
        __syncthreads();
        if (it > 0) {
            mreg = g_W1[(size_t)(base + it - 1) * 512 + tid];
            if (tid < 128) nreg = g_W2[(size_t)(base + it - 1) * 256 + tid];
        }
        if (tid < 128) {
            int r = tid >> 3, cc = tid & 7;
            float s = 0.f;
            #pragma unroll
            for (int e = 0; e < 16; e++) s += S[par][r * 16 + e] * Nt[e * 8 + cc];
            g_P[(base + it) * 128 + tid] = s;
        }
        float sn = 0.f;
        #pragma unroll
        for (int e = 0; e < 16; e++) sn += S[par][i * 16 + e] * Mt[e * 16 + j];
        S[par ^ 1][tid] = sn;
        __syncthreads();
        par ^= 1;
    }
    g_T[(c * 8 + g) * 256 + tid] = S[par][tid];
}

// 3b: per-chunk scan of 8 group products -> GS_g, A_c
__global__ void __launch_bounds__(256) group_scan_kernel() {
    int c = blockIdx.x;
    __shared__ float S[2][256], Tt[256];
    int tid = threadIdx.x;
    int i = tid >> 4, j = tid & 15;
    S[0][tid] = (i == j) ? 1.f : 0.f;
    int par = 0;
    for (int g = 7; g >= 0; --g) {
        Tt[tid] = g_T[(c * 8 + g) * 256 + tid];
        __syncthreads();
        float v = 0.f;
        #pragma unroll
        for (int e = 0; e < 16; e++) v += S[par][i * 16 + e] * Tt[e * 16 + j];
        S[par ^ 1][tid] = v;
        if (g >= 1) g_GS[(c * 8 + g) * 256 + tid] = v;
        __syncthreads();
        par ^= 1;
    }
    g_A[c * 256 + tid] = S[par][tid];
}

// 3c: apply GS_{g+1} to U (groups 0..6)
__global__ void __launch_bounds__(256) apply_kernel() {
    int c = blockIdx.x / 7, g = blockIdx.x % 7;
    int base = c * CL + g * 8;
    __shared__ float GSs[256], Us[1024];
    int tid = threadIdx.x;
    GSs[tid] = g_GS[(c * 8 + g + 1) * 256 + tid];
    #pragma unroll
    for (int q = 0; q < 4; q++) {
        int k = tid + q * 256;
        Us[k] = g_P[(base + (k >> 7)) * 128 + (k & 127)];
    }
    __syncthreads();
    #pragma unroll
    for (int q = 0; q < 4; q++) {
        int k = tid + q * 256;
        int p = k >> 7, rc = k & 127, r = rc >> 3, cc = rc & 7;
        float v = 0.f;
        #pragma unroll
        for (int e = 0; e < 16; e++) v += GSs[r * 16 + e] * Us[p * 128 + e * 8 + cc];
        g_P[(base + p) * 128 + rc] = v;
    }
}

// Kernel 4: b_c = sum_t P_t * obs_t
#define BGB 8
__global__ void __launch_bounds__(256) bvec_kernel(const float* __restrict__ x) {
    int c = blockIdx.x & (NCH - 1);
    int bg = blockIdx.x >> 5;
    int cstart = c * CL;
    int clen = (NS - cstart < CL) ? (NS - cstart) : CL;
    __shared__ __align__(16) float sP[CL * 128];
    __shared__ __align__(16) float sX[BGB][CL][8];
    int tid = threadIdx.x;
    for (int idx = tid; idx < clen * 128; idx += 256)
        sP[idx] = g_P[cstart * 128 + idx];
    for (int idx = tid; idx < BGB * 8 * clen; idx += 256) {
        int s = idx % clen;
        int bm = idx / clen;
        int m = bm & 7, b = bm >> 3;
        sX[b][s][m] = x[((size_t)(bg * BGB + b) * MM + m) * TT + cstart + s];
    }
    __syncthreads();
    int w = tid >> 5, lane = tid & 31;
    int b = bg * BGB + w;
    if (lane < 16) {
        float acc = 0.f;
        for (int s = 0; s < clen; s++) {
            const float4* pp = (const float4*)&sP[s * 128 + lane * 8];
            float4 p0 = pp[0], p1 = pp[1];
            const float4* op = (const float4*)&sX[w][s][0];
            float4 o0 = op[0], o1 = op[1];
            acc += p0.x*o0.x + p0.y*o0.y + p0.z*o0.z + p0.w*o0.w
                 + p1.x*o1.x + p1.y*o1.y + p1.z*o1.z + p1.w*o1.w;
        }
        g_b[(b * NCH + c) * 16 + lane] = acc;
    }
}

// Kernel 5: serial scan over 32 chunks
__global__ void __launch_bounds__(256) scan_kernel() {
    __shared__ float sA[NCH * 256];
    int tid = threadIdx.x;
    for (int idx = tid; idx < NCH * 256; idx += 256) sA[idx] = g_A[idx];
    __syncthreads();
    int w = tid >> 5, lane = tid & 31;
    int b = blockIdx.x * 8 + w;
    int row = lane & 15;
    float mean_i = 0.f;
    float breg = (lane < 16) ? g_b[(b * NCH + 0) * 16 + lane] : 0.f;
    for (int c = 0; c < NCH; c++) {
        if (lane < 16) g_m0[(b * NCH + c) * 16 + lane] = mean_i;
        float bn = (lane < 16 && c + 1 < NCH) ? g_b[(b * NCH + c + 1) * 16 + lane] : 0.f;
        float nm = breg;
        #pragma unroll
        for (int e = 0; e < 16; e++) {
            float me = __shfl_sync(0xffffffffu, mean_i, e);
            nm += sA[c * 256 + row * 16 + e] * me;
        }
        mean_i = nm;
        breg = bn;
    }
}

// Kernel 6: within-chunk recursion + output
__global__ void __launch_bounds__(512) phase2b_kernel(const float* __restrict__ x,
                                                      float* __restrict__ out) {
    int c = blockIdx.x & (NCH - 1);
    int bg = blockIdx.x >> 5;
    int cstart = c * CL;
    int clen = (NS - cstart < CL) ? (NS - cstart) : CL;
    __shared__ __align__(16) float sW1[SUB][32][20];
    __shared__ __align__(16) float sW2[SUB][32][12];
    __shared__ __align__(16) float sX[16][SUB][8];
    __shared__ __align__(16) float sY[16][8][SUB];
    __shared__ __align__(16) float sMean[16][16];

    int tid = threadIdx.x, w = tid >> 5, lane = tid & 31;
    int b = bg * 16 + w;
    const size_t xbase = (size_t)b * MM * TT;
    if (lane < 16) sMean[w][lane] = g_m0[(b * NCH + c) * 16 + lane];
    if (c == 0 && lane < 8) out[xbase + (size_t)lane * TT] = 0.f;
    __syncwarp();

    for (int t0 = 0; t0 < clen; t0 += SUB) {
        int ns = (clen - t0 < SUB) ? (clen - t0) : SUB;
        __syncthreads();
        for (int idx = tid; idx < ns * 512; idx += 512) {
            int s = idx >> 9, rc = idx & 511;
            sW1[s][rc >> 4][rc & 15] = g_W1[(size_t)(cstart + t0 + s) * 512 + rc];
        }
        for (int idx = tid; idx < ns * 256; idx += 512) {
            int s = idx >> 8, rc = idx & 255;
            sW2[s][rc >> 3][rc & 7] = g_W2[(size_t)(cstart + t0 + s) * 256 + rc];
        }
        for (int idx = tid; idx < 128 * ns; idx += 512) {
            int s = idx % ns;
            int bm = idx / ns;
            int m = bm & 7, bb = bm >> 3;
            sX[bb][s][m] = x[((size_t)(bg * 16 + bb) * MM + m) * TT + cstart + t0 + s];
        }
        __syncthreads();

        for (int s = 0; s < ns; s++) {
            const float4* w1 = (const float4*)&sW1[s][lane][0];
            float4 a0 = w1[0], a1 = w1[1], a2 = w1[2], a3 = w1[3];
            const float4* w2 = (const float4*)&sW2[s][lane][0];
            float4 c0 = w2[0], c1 = w2[1];
            const float4* mp = (const float4*)&sMean[w][0];
            float4 m0 = mp[0], m1 = mp[1], m2 = mp[2], m3 = mp[3];
            const float4* op = (const float4*)&sX[w][s][0];
            float4 o0 = op[0], o1 = op[1];
            float s0 = a0.x*m0.x + a0.y*m0.y + a0.z*m0.z + a0.w*m0.w;
            float s1 = a1.x*m1.x + a1.y*m1.y + a1.z*m1.z + a1.w*m1.w;
            float s2 = a2.x*m2.x + a2.y*m2.y + a2.z*m2.z + a2.w*m2.w;
            float s3 = a3.x*m3.x + a3.y*m3.y + a3.z*m3.z + a3.w*m3.w;
            float s4 = c0.x*o0.x + c0.y*o0.y + c0.z*o0.z + c0.w*o0.w;
            float s5 = c1.x*o1.x + c1.y*o1.y + c1.z*o1.z + c1.w*o1.w;
            float acc = ((s0 + s1) + (s2 + s3)) + (s4 + s5);
            __syncwarp();
            if (lane < 16)      sMean[w][lane] = acc;
            else if (lane < 24) sY[w][lane - 16][s] = acc;
            __syncwarp();
        }
        __syncthreads();
        for (int idx = tid; idx < 128 * ns; idx += 512) {
            int s = idx % ns;
            int bm = idx / ns;
            int m = bm & 7, bb = bm >> 3;
            out[((size_t)(bg * 16 + bb) * MM + m) * TT + cstart + t0 + s + 1] = sY[bb][m][s];
        }
    }
}

// Kernel 7: exact per-batch fallback for NaN-containing batches
__global__ void slow_kernel(const float* __restrict__ x, const float* __restrict__ F_,
                            const float* __restrict__ H_, const float* __restrict__ Q_,
                            const float* __restrict__ R_, float* __restrict__ out) {
    int b = blockIdx.x;
    if (!g_nan[b]) return;
    int tid = threadIdx.x;
    __shared__ float sF[256], sH[128], sQ[256], sR[64];
    __shared__ float cov[256], covn[256], P[128], W[2][128], K[128], CU[256], FC[256];
    __shared__ float mean[16], meanu[16], meanp[16], obs[8], resid[8];
    __shared__ int nanb;

    sF[tid] = F_[tid];
    sQ[tid] = Q_[tid];
    if (tid < 128) sH[tid] = H_[tid];
    if (tid < 64)  sR[tid] = R_[tid];
    cov[tid] = ((tid >> 4) == (tid & 15)) ? 1.f : 0.f;
    if (tid < 16) mean[tid] = 0.f;
    if (tid < 8)  out[((size_t)b * MM + tid) * TT] = 0.f;
    __syncthreads();

    for (int t = 0; t < NS; t++) {
        if (tid == 0) {
            int nb = 0;
            for (int j = 0; j < 8; j++) {
                float v = x[((size_t)b * MM + j) * TT + t];
                if (isnan(v)) { nb = 1; v = 0.f; }
                obs[j] = v;
            }
            nanb = nb;
        }
        __syncthreads();
        if (tid < 128) {
            int i = tid >> 3, j = tid & 7;
            float s = 0.f;
            #pragma unroll
            for (int e = 0; e < 16; e++) s += cov[i * 16 + e] * sH[j * 16 + e];
            P[tid] = s;
        }
        if (tid >= 128 && tid < 136) {
            int j = tid - 128;
            float s = obs[j];
            #pragma unroll
            for (int e = 0; e < 16; e++) s -= sH[j * 16 + e] * mean[e];
            resid[j] = s;
        }
        __syncthreads();
        if (tid < 128) {
            int a = tid >> 4, c = tid & 15;
            float v;
            if (c < 8) {
                float s = sR[a * 8 + c];
                #pragma unroll
                for (int e = 0; e < 16; e++) s += sH[a * 16 + e] * P[e * 8 + c];
                v = s;
            } else v = (a == (c - 8)) ? 1.f : 0.f;
            W[0][a * 16 + c] = v;
        }
        __syncthreads();
        #pragma unroll 1
        for (int k = 0; k < 8; k++) {
            int cur = k & 1;
            if (tid < 128) {
                int a = tid >> 4, c = tid & 15;
                float piv = W[cur][k * 16 + k];
                float wkc = W[cur][k * 16 + c] / piv;
                W[cur ^ 1][a * 16 + c] = (a == k) ? wkc
                                                  : W[cur][a * 16 + c] - W[cur][a * 16 + k] * wkc;
            }
            __syncthreads();
        }
        if (tid < 128) {
            int i = tid >> 3, j = tid & 7;
            float s = 0.f;
            #pragma unroll
            for (int a = 0; a < 8; a++) s += P[i * 8 + a] * W[0][a * 16 + 8 + j];
            K[tid] = s;
        }
        __syncthreads();
        if (tid < 16) {
            float s = mean[tid];
            #pragma unroll
            for (int a = 0; a < 8; a++) s += K[tid * 8 + a] * resid[a];
            meanu[tid] = nanb ? mean[tid] : s;
        }
        {
            int i = tid >> 4, j = tid & 15;
            float s = cov[tid];
            #pragma unroll
            for (int a = 0; a < 8; a++) s -= K[i * 8 + a] * P[j * 8 + a];
            CU[tid] = nanb ? cov[tid] : s;
        }
        __syncthreads();
        {
            int i = tid >> 4, j = tid & 15;
            float s = 0.f;
            #pragma unroll
            for (int e = 0; e < 16; e++)
                s += sF[i * 16 + e] * 0.5f * (CU[e * 16 + j] + CU[j * 16 + e]);
            FC[tid] = s;
        }
        if (tid < 16) {
            float s = 0.f;
            #pragma unroll
            for (int e = 0; e < 16; e++) s += sF[tid * 16 + e] * meanu[e];
            meanp[tid] = s;
        }
        __syncthreads();
        {
            int i = tid >> 4, j = tid & 15;
            float s = sQ[tid];
            #pragma unroll
            for (int e = 0; e < 16; e++) s += FC[i * 16 + e] * sF[j * 16 + e];
            covn[tid] = s;
        }
        if (tid < 8) {
            float s = 0.f;
            #pragma unroll
            for (int e = 0; e < 16; e++) s += sH[tid * 16 + e] * meanp[e];
            out[((size_t)b * MM + tid) * TT + t + 1] = s;
        }
        __syncthreads();
        cov[tid] = covn[tid];
        if (tid < 16) mean[tid] = meanp[tid];
        __syncthreads();
    }
}

extern "C" void kernel_launch(void* const* d_in, const int* in_sizes, int n_in,
                              void* d_out, int out_size) {
    const float* x = (const float*)d_in[0];
    const float* F = (const float*)d_in[1];
    const float* H = (const float*)d_in[2];
    const float* Q = (const float*)d_in[3];
    const float* R = (const float*)d_in[4];
    float* out = (float*)d_out;

    nan_scan_kernel<<<BS, 256>>>(x);
    phase1_kernel<<<1, 256>>>(F, H, Q, R);
    fill_kernel<<<NS, 256>>>();
    group_serial_kernel<<<NCH * 8, 256>>>();
    group_scan_kernel<<<NCH, 256>>>();
    apply_kernel<<<NCH * 7, 256>>>();
    bvec_kernel<<<NCH * (BS / BGB), 256>>>(x);
    scan_kernel<<<BS / 8, 256>>>();
    phase2b_kernel<<<NCH * (BS / 16), 512>>>(x, out);
    slow_kernel<<<BS, 256>>>(x, F, H, Q, R, out);
}

// round 11
// speedup vs baseline: 1.8607x; 1.0672x over previous
#include <cuda_runtime.h>
#include <math.h>

#define BS   512
#define MM   8
#define TT   2048
#define NS   2047
#define NCH  32
#define CL   64
#define SUB  8
#define CONV_EPS 1.5e-3f

// Packed maps: W1[t]=[M;G;0] (32x16), W2[t]=[N;D;0] (32x8); rows 24-31 stay 0.
__device__ float g_W1[(size_t)NS * 512];
__device__ float g_W2[(size_t)NS * 256];
__device__ float g_P[NS * 128];        // U_t then P_t [16][8]
__device__ float g_T[NCH * 8 * 256];   // per-(chunk,group) 8-step product
__device__ float g_GS[NCH * 8 * 256];  // group suffixes
__device__ float g_A[NCH * 256];       // chunk products
__device__ float g_b[BS * NCH * 16];
__device__ float g_m0[BS * NCH * 16];
__device__ int   g_tc;
__device__ unsigned char g_nan[BS];

__global__ void nan_scan_kernel(const float* __restrict__ x) {
    int b = blockIdx.x, tid = threadIdx.x;
    const float* xb = x + (size_t)b * MM * TT;
    int bad = 0;
    for (int idx = tid; idx < MM * TT; idx += 256) {
        int t = idx & (TT - 1);
        if (t < NS) bad |= isnan(xb[idx]) ? 1 : 0;
    }
    int any = __syncthreads_or(bad);
    if (tid == 0) g_nan[b] = any ? 1 : 0;
}

// ---------------------------------------------------------------------------
// Phase 1 (R7-proven structure): 6 barriers/step, warp0 register GJ in the
// shadow of F*cov / F*P / Y products. Convergence exit, eps=1.5e-3.
// ---------------------------------------------------------------------------
__global__ void __launch_bounds__(256) phase1_kernel(
        const float* __restrict__ F_, const float* __restrict__ H_,
        const float* __restrict__ Q_, const float* __restrict__ R_) {
    __shared__ float sF[256], sH[128], sQ[256], sR[64];
    __shared__ float cov[256];
    __shared__ float P[128];
    __shared__ float W[128];
    __shared__ float Sv[64];
    __shared__ float X[256];
    __shared__ float Y[256];
    __shared__ float FP[128];
    __shared__ float Nn[128];
    __shared__ float Mm[256];
    __shared__ float covn[256];

    int tid = threadIdx.x;
    int i = tid >> 4, j = tid & 15;
    sF[tid] = F_[tid];
    sQ[tid] = Q_[tid];
    if (tid < 128) sH[tid] = H_[tid];
    if (tid < 64)  sR[tid] = R_[tid];
    cov[tid] = (i == j) ? 1.f : 0.f;
    __syncthreads();

    int tc = NS;
    for (int t = 0; t < NS; t++) {
        if (tid < 128) {
            int r = tid >> 3, c = tid & 7;
            float a0 = 0.f, a1 = 0.f;
            #pragma unroll
            for (int e = 0; e < 16; e += 2) {
                a0 += cov[r * 16 + e]     * sH[c * 16 + e];
                a1 += cov[r * 16 + e + 1] * sH[c * 16 + e + 1];
            }
            P[tid] = a0 + a1;
        } else {
            int u = tid - 128;
            int r = u >> 4, c = u & 15;
            float a0 = 0.f, a1 = 0.f;
            #pragma unroll
            for (int e = 0; e < 16; e += 2) {
                a0 += sF[r * 16 + e]     * cov[c * 16 + e];
                a1 += sF[r * 16 + e + 1] * cov[c * 16 + e + 1];
            }
            X[u] = a0 + a1;
        }
        __syncthreads();
        if (tid < 128) {
            int a = tid >> 4, c = tid & 15;
            float v;
            if (c < 8) {
                float s0 = sR[a * 8 + c], s1 = 0.f;
                #pragma unroll
                for (int e = 0; e < 16; e += 2) {
                    s0 += sH[a * 16 + e]     * P[e * 8 + c];
                    s1 += sH[a * 16 + e + 1] * P[(e + 1) * 8 + c];
                }
                v = s0 + s1;
            } else {
                v = (a == (c - 8)) ? 1.f : 0.f;
            }
            W[a * 16 + c] = v;
        } else {
            int r = tid >> 4, c = tid & 15;
            float a0 = 0.f, a1 = 0.f;
            #pragma unroll
            for (int e = 0; e < 16; e += 2) {
                a0 += sF[r * 16 + e]     * cov[c * 16 + e];
                a1 += sF[r * 16 + e + 1] * cov[c * 16 + e + 1];
            }
            X[tid] = a0 + a1;
        }
        __syncthreads();
        if (tid < 32) {
            int c = tid & 15, h = tid >> 4;
            float w[4];
            #pragma unroll
            for (int r = 0; r < 4; r++) w[r] = W[(h * 4 + r) * 16 + c];
            #pragma unroll
            for (int k = 0; k < 8; k++) {
                const int kh = k >> 2, kr = k & 3;
                float pivv  = __shfl_sync(0xffffffffu, w[kr], k + (kh << 4));
                float wkrow = __shfl_sync(0xffffffffu, w[kr], c + (kh << 4));
                float col0  = __shfl_sync(0xffffffffu, w[0], k + (h << 4));
                float col1  = __shfl_sync(0xffffffffu, w[1], k + (h << 4));
                float col2  = __shfl_sync(0xffffffffu, w[2], k + (h << 4));
                float col3  = __shfl_sync(0xffffffffu, w[3], k + (h << 4));
                float wkc = wkrow * __fdividef(1.0f, pivv);
                w[0] = (h * 4 + 0 == k) ? wkc : w[0] - col0 * wkc;
                w[1] = (h * 4 + 1 == k) ? wkc : w[1] - col1 * wkc;
                w[2] = (h * 4 + 2 == k) ? wkc : w[2] - col2 * wkc;
                w[3] = (h * 4 + 3 == k) ? wkc : w[3] - col3 * wkc;
            }
            if (c >= 8) {
                #pragma unroll
                for (int r = 0; r < 4; r++)
                    Sv[(h * 4 + r) * 8 + (c - 8)] = w[r];
            }
        } else if (tid < 128) {
            int u = tid - 32;
            {
                int r = u >> 3, c = u & 7;
                float a0 = 0.f, a1 = 0.f;
                #pragma unroll
                for (int e = 0; e < 16; e += 2) {
                    a0 += sF[r * 16 + e]     * P[e * 8 + c];
                    a1 += sF[r * 16 + e + 1] * P[(e + 1) * 8 + c];
                }
                FP[u] = a0 + a1;
            }
            if (u < 32) {
                int u2 = u + 96;
                int r = u2 >> 3, c = u2 & 7;
                float a0 = 0.f, a1 = 0.f;
                #pragma unroll
                for (int e = 0; e < 16; e += 2) {
                    a0 += sF[r * 16 + e]     * P[e * 8 + c];
                    a1 += sF[r * 16 + e + 1] * P[(e + 1) * 8 + c];
                }
                FP[u2] = a0 + a1;
            }
        } else {
            int u = tid - 128;
            int r = u >> 4, c = u & 15;
            float a0 = 0.f, a1 = 0.f;
            #pragma unroll
            for (int e = 0; e < 16; e += 2) {
                a0 += X[r * 16 + e]     * sF[c * 16 + e];
                a1 += X[r * 16 + e + 1] * sF[c * 16 + e + 1];
            }
            Y[u] = a0 + a1;
        }
        __syncthreads();
        if (tid < 128) {
            int r = tid >> 3, c = tid & 7;
            float s0 = 0.f, s1 = 0.f;
            #pragma unroll
            for (int a = 0; a < 8; a += 2) {
                s0 += FP[r * 8 + a]     * Sv[a * 8 + c];
                s1 += FP[r * 8 + a + 1] * Sv[(a + 1) * 8 + c];
            }
            Nn[tid] = s0 + s1;
        } else {
            int r = tid >> 4, c = tid & 15;
            float a0 = 0.f, a1 = 0.f;
            #pragma unroll
            for (int e = 0; e < 16; e += 2) {
                a0 += X[r * 16 + e]     * sF[c * 16 + e];
                a1 += X[r * 16 + e + 1] * sF[c * 16 + e + 1];
            }
            Y[tid] = a0 + a1;
        }
        __syncthreads();
        {
            float t1 = 0.f, t2 = 0.f, m = sF[tid];
            #pragma unroll
            for (int a = 0; a < 8; a++) {
                float ni = Nn[i * 8 + a], fi = FP[i * 8 + a];
                t1 += ni * FP[j * 8 + a];
                t2 += fi * Nn[j * 8 + a];
                m  -= ni * sH[a * 16 + j];
            }
            covn[tid] = Y[tid] + sQ[tid] - 0.5f * (t1 + t2);
            Mm[tid] = m;
        }
        __syncthreads();
        g_W1[(size_t)t * 512 + tid] = Mm[tid];
        if (tid < 128) {
            g_W2[(size_t)t * 256 + tid] = Nn[tid];
            int a = tid >> 4, jj = tid & 15;
            float s0 = 0.f, s1 = 0.f;
            #pragma unroll
            for (int e = 0; e < 16; e += 2) {
                s0 += sH[a * 16 + e]     * Mm[e * 16 + jj];
                s1 += sH[a * 16 + e + 1] * Mm[(e + 1) * 16 + jj];
            }
            g_W1[(size_t)t * 512 + 256 + tid] = s0 + s1;
        } else if (tid < 192) {
            int u = tid - 128, a = u >> 3, jj = u & 7;
            float s0 = 0.f, s1 = 0.f;
            #pragma unroll
            for (int e = 0; e < 16; e += 2) {
                s0 += sH[a * 16 + e]     * Nn[e * 8 + jj];
                s1 += sH[a * 16 + e + 1] * Nn[(e + 1) * 8 + jj];
            }
            g_W2[(size_t)t * 256 + 128 + u] = s0 + s1;
        }
        float oldc = cov[tid];
        float dlt = fabsf(covn[tid] - oldc);
        cov[tid] = covn[tid];
        int any = __syncthreads_or(dlt > CONV_EPS * (fabsf(oldc) + 1e-2f));
        if (!any) { tc = t + 1; break; }
    }
    if (tid == 0) g_tc = tc;
}

// fill frozen tail [g_tc, NS)
__global__ void fill_kernel() {
    int t = blockIdx.x;
    int tc = g_tc;
    if (t < tc) return;
    int src = tc - 1;
    int tid = threadIdx.x;
    g_W1[(size_t)t * 512 + tid] = g_W1[(size_t)src * 512 + tid];
    if (tid < 128) {
        g_W1[(size_t)t * 512 + 256 + tid] = g_W1[(size_t)src * 512 + 256 + tid];
        g_W2[(size_t)t * 256 + tid] = g_W2[(size_t)src * 256 + tid];
    }
    if (tid < 64)
        g_W2[(size_t)t * 256 + 128 + tid] = g_W2[(size_t)src * 256 + 128 + tid];
}

// 3a: per-(chunk,group) 8-step serial suffix -> U_p in g_P, group product g_T
__global__ void __launch_bounds__(256) group_serial_kernel() {
    int c = blockIdx.x >> 3, g = blockIdx.x & 7;
    int base = c * CL + g * 8;
    int n = NS - base; if (n > 8) n = 8;
    __shared__ float S[2][256], Mt[256], Nt[128];
    int tid = threadIdx.x;
    int i = tid >> 4, j = tid & 15;
    S[0][tid] = (i == j) ? 1.f : 0.f;
    int par = 0;
    float mreg = g_W1[(size_t)(base + n - 1) * 512 + tid];
    float nreg = (tid < 128) ? g_W2[(size_t)(base + n - 1) * 256 + tid] : 0.f;
    __syncthreads();
    for (int it = n - 1; it >= 0; --it) {
        Mt[tid] = mreg;
        if (tid < 128) Nt[tid] = nreg;
        __syncthreads();
        if (it > 0) {
            mreg = g_W1[(size_t)(base + it - 1) * 512 + tid];
            if (tid < 128) nreg = g_W2[(size_t)(base + it - 1) * 256 + tid];
        }
        if (tid < 128) {
            int r = tid >> 3, cc = tid & 7;
            float s = 0.f;
            #pragma unroll
            for (int e = 0; e < 16; e++) s += S[par][r * 16 + e] * Nt[e * 8 + cc];
            g_P[(base + it) * 128 + tid] = s;
        }
        float sn = 0.f;
        #pragma unroll
        for (int e = 0; e < 16; e++) sn += S[par][i * 16 + e] * Mt[e * 16 + j];
        S[par ^ 1][tid] = sn;
        __syncthreads();
        par ^= 1;
    }
    g_T[(c * 8 + g) * 256 + tid] = S[par][tid];
}

// 3b: per-chunk scan of 8 group products -> GS_g, A_c
__global__ void __launch_bounds__(256) group_scan_kernel() {
    int c = blockIdx.x;
    __shared__ float S[2][256], Tt[256];
    int tid = threadIdx.x;
    int i = tid >> 4, j = tid & 15;
    S[0][tid] = (i == j) ? 1.f : 0.f;
    int par = 0;
    for (int g = 7; g >= 0; --g) {
        Tt[tid] = g_T[(c * 8 + g) * 256 + tid];
        __syncthreads();
        float v = 0.f;
        #pragma unroll
        for (int e = 0; e < 16; e++) v += S[par][i * 16 + e] * Tt[e * 16 + j];
        S[par ^ 1][tid] = v;
        if (g >= 1) g_GS[(c * 8 + g) * 256 + tid] = v;
        __syncthreads();
        par ^= 1;
    }
    g_A[c * 256 + tid] = S[par][tid];
}

// 3c: apply GS_{g+1} to U (groups 0..6)
__global__ void __launch_bounds__(256) apply_kernel() {
    int c = blockIdx.x / 7, g = blockIdx.x % 7;
    int base = c * CL + g * 8;
    __shared__ float GSs[256], Us[1024];
    int tid = threadIdx.x;
    GSs[tid] = g_GS[(c * 8 + g + 1) * 256 + tid];
    #pragma unroll
    for (int q = 0; q < 4; q++) {
        int k = tid + q * 256;
        Us[k] = g_P[(base + (k >> 7)) * 128 + (k & 127)];
    }
    __syncthreads();
    #pragma unroll
    for (int q = 0; q < 4; q++) {
        int k = tid + q * 256;
        int p = k >> 7, rc = k & 127, r = rc >> 3, cc = rc & 7;
        float v = 0.f;
        #pragma unroll
        for (int e = 0; e < 16; e++) v += GSs[r * 16 + e] * Us[p * 128 + e * 8 + cc];
        g_P[(base + p) * 128 + rc] = v;
    }
}

// Kernel 4: b_c = sum_t P_t * obs_t
#define BGB 8
__global__ void __launch_bounds__(256) bvec_kernel(const float* __restrict__ x) {
    int c = blockIdx.x & (NCH - 1);
    int bg = blockIdx.x >> 5;
    int cstart = c * CL;
    int clen = (NS - cstart < CL) ? (NS - cstart) : CL;
    __shared__ __align__(16) float sP[CL * 128];
    __shared__ __align__(16) float sX[BGB][CL][8];
    int tid = threadIdx.x;
    for (int idx = tid; idx < clen * 128; idx += 256)
        sP[idx] = g_P[cstart * 128 + idx];
    for (int idx = tid; idx < BGB * 8 * clen; idx += 256) {
        int s = idx % clen;
        int bm = idx / clen;
        int m = bm & 7, b = bm >> 3;
        sX[b][s][m] = x[((size_t)(bg * BGB + b) * MM + m) * TT + cstart + s];
    }
    __syncthreads();
    int w = tid >> 5, lane = tid & 31;
    int b = bg * BGB + w;
    if (lane < 16) {
        float acc = 0.f;
        for (int s = 0; s < clen; s++) {
            const float4* pp = (const float4*)&sP[s * 128 + lane * 8];
            float4 p0 = pp[0], p1 = pp[1];
            const float4* op = (const float4*)&sX[w][s][0];
            float4 o0 = op[0], o1 = op[1];
            acc += p0.x*o0.x + p0.y*o0.y + p0.z*o0.z + p0.w*o0.w
                 + p1.x*o1.x + p1.y*o1.y + p1.z*o1.z + p1.w*o1.w;
        }
        g_b[(b * NCH + c) * 16 + lane] = acc;
    }
}

// Kernel 5: serial scan over 32 chunks
__global__ void __launch_bounds__(256) scan_kernel() {
    __shared__ float sA[NCH * 256];
    int tid = threadIdx.x;
    for (int idx = tid; idx < NCH * 256; idx += 256) sA[idx] = g_A[idx];
    __syncthreads();
    int w = tid >> 5, lane = tid & 31;
    int b = blockIdx.x * 8 + w;
    int row = lane & 15;
    float mean_i = 0.f;
    float breg = (lane < 16) ? g_b[(b * NCH + 0) * 16 + lane] : 0.f;
    for (int c = 0; c < NCH; c++) {
        if (lane < 16) g_m0[(b * NCH + c) * 16 + lane] = mean_i;
        float bn = (lane < 16 && c + 1 < NCH) ? g_b[(b * NCH + c + 1) * 16 + lane] : 0.f;
        float nm = breg;
        #pragma unroll
        for (int e = 0; e < 16; e++) {
            float me = __shfl_sync(0xffffffffu, mean_i, e);
            nm += sA[c * 256 + row * 16 + e] * me;
        }
        mean_i = nm;
        breg = bn;
    }
}

// ---------------------------------------------------------------------------
// Kernel 6: within-chunk recursion + output.
// FROZEN FAST PATH: if all steps of the chunk are >= g_tc, every step uses the
// SAME matrices -> keep rows in registers, shuffles for mean/obs broadcast,
// direct LDG for obs and STG for y. No smem, no block syncs.
// Transient chunks (cstart < g_tc) use the original smem-staged path.
// ---------------------------------------------------------------------------
__global__ void __launch_bounds__(512) phase2b_kernel(const float* __restrict__ x,
                                                      float* __restrict__ out) {
    int c = blockIdx.x & (NCH - 1);
    int bg = blockIdx.x >> 5;
    int cstart = c * CL;
    int clen = (NS - cstart < CL) ? (NS - cstart) : CL;
    int tid = threadIdx.x, w = tid >> 5, lane = tid & 31;
    int b = bg * 16 + w;

    if (cstart >= g_tc) {
        // ---- frozen fast path (warp-local) ----
        const float* xb = x + (size_t)b * MM * TT;
        float* ob = out + (size_t)b * MM * TT;
        const float4* W1p = (const float4*)(g_W1 + (size_t)cstart * 512 + lane * 16);
        float4 A0 = W1p[0], A1 = W1p[1], A2 = W1p[2], A3 = W1p[3];
        const float4* W2p = (const float4*)(g_W2 + (size_t)cstart * 256 + lane * 8);
        float4 C0 = W2p[0], C1 = W2p[1];

        float mval = (lane < 16) ? g_m0[(b * NCH + c) * 16 + lane] : 0.f;
        float mean[16];
        #pragma unroll
        for (int e = 0; e < 16; e++) mean[e] = __shfl_sync(0xffffffffu, mval, e);

        float nextobs = (lane >= 24) ? xb[(size_t)(lane - 24) * TT + cstart] : 0.f;
        int tend = cstart + clen;
        for (int t = cstart; t < tend; t++) {
            float obs[8];
            #pragma unroll
            for (int j2 = 0; j2 < 8; j2++)
                obs[j2] = __shfl_sync(0xffffffffu, nextobs, 24 + j2);
            if (lane >= 24 && t + 1 < tend)
                nextobs = xb[(size_t)(lane - 24) * TT + t + 1];

            float s0 = A0.x*mean[0]  + A0.y*mean[1]  + A0.z*mean[2]  + A0.w*mean[3];
            float s1 = A1.x*mean[4]  + A1.y*mean[5]  + A1.z*mean[6]  + A1.w*mean[7];
            float s2 = A2.x*mean[8]  + A2.y*mean[9]  + A2.z*mean[10] + A2.w*mean[11];
            float s3 = A3.x*mean[12] + A3.y*mean[13] + A3.z*mean[14] + A3.w*mean[15];
            float s4 = C0.x*obs[0] + C0.y*obs[1] + C0.z*obs[2] + C0.w*obs[3];
            float s5 = C1.x*obs[4] + C1.y*obs[5] + C1.z*obs[6] + C1.w*obs[7];
            float acc = ((s0 + s1) + (s2 + s3)) + (s4 + s5);

            if (lane >= 16 && lane < 24)
                ob[(size_t)(lane - 16) * TT + t + 1] = acc;
            #pragma unroll
            for (int e = 0; e < 16; e++) mean[e] = __shfl_sync(0xffffffffu, acc, e);
        }
        return;
    }

    // ---- transient smem path (original) ----
    __shared__ __align__(16) float sW1[SUB][32][20];
    __shared__ __align__(16) float sW2[SUB][32][12];
    __shared__ __align__(16) float sX[16][SUB][8];
    __shared__ __align__(16) float sY[16][8][SUB];
    __shared__ __align__(16) float sMean[16][16];

    const size_t xbase = (size_t)b * MM * TT;
    if (lane < 16) sMean[w][lane] = g_m0[(b * NCH + c) * 16 + lane];
    if (c == 0 && lane < 8) out[xbase + (size_t)lane * TT] = 0.f;
    __syncwarp();

    for (int t0 = 0; t0 < clen; t0 += SUB) {
        int ns = (clen - t0 < SUB) ? (clen - t0) : SUB;
        __syncthreads();
        for (int idx = tid; idx < ns * 512; idx += 512) {
            int s = idx >> 9, rc = idx & 511;
            sW1[s][rc >> 4][rc & 15] = g_W1[(size_t)(cstart + t0 + s) * 512 + rc];
        }
        for (int idx = tid; idx < ns * 256; idx += 512) {
            int s = idx >> 8, rc = idx & 255;
            sW2[s][rc >> 3][rc & 7] = g_W2[(size_t)(cstart + t0 + s) * 256 + rc];
        }
        for (int idx = tid; idx < 128 * ns; idx += 512) {
            int s = idx % ns;
            int bm = idx / ns;
            int m = bm & 7, bb = bm >> 3;
            sX[bb][s][m] = x[((size_t)(bg * 16 + bb) * MM + m) * TT + cstart + t0 + s];
        }
        __syncthreads();

        for (int s = 0; s < ns; s++) {
            const float4* w1 = (const float4*)&sW1[s][lane][0];
            float4 a0 = w1[0], a1 = w1[1], a2 = w1[2], a3 = w1[3];
            const float4* w2 = (const float4*)&sW2[s][lane][0];
            float4 c0 = w2[0], c1 = w2[1];
            const float4* mp = (const float4*)&sMean[w][0];
            float4 m0 = mp[0], m1 = mp[1], m2 = mp[2], m3 = mp[3];
            const float4* op = (const float4*)&sX[w][s][0];
            float4 o0 = op[0], o1 = op[1];
            float s0 = a0.x*m0.x + a0.y*m0.y + a0.z*m0.z + a0.w*m0.w;
            float s1 = a1.x*m1.x + a1.y*m1.y + a1.z*m1.z + a1.w*m1.w;
            float s2 = a2.x*m2.x + a2.y*m2.y + a2.z*m2.z + a2.w*m2.w;
            float s3 = a3.x*m3.x + a3.y*m3.y + a3.z*m3.z + a3.w*m3.w;
            float s4 = c0.x*o0.x + c0.y*o0.y + c0.z*o0.z + c0.w*o0.w;
            float s5 = c1.x*o1.x + c1.y*o1.y + c1.z*o1.z + c1.w*o1.w;
            float acc = ((s0 + s1) + (s2 + s3)) + (s4 + s5);
            __syncwarp();
            if (lane < 16)      sMean[w][lane] = acc;
            else if (lane < 24) sY[w][lane - 16][s] = acc;
            __syncwarp();
        }
        __syncthreads();
        for (int idx = tid; idx < 128 * ns; idx += 512) {
            int s = idx % ns;
            int bm = idx / ns;
            int m = bm & 7, bb = bm >> 3;
            out[((size_t)(bg * 16 + bb) * MM + m) * TT + cstart + t0 + s + 1] = sY[bb][m][s];
        }
    }
}

// Kernel 7: exact per-batch fallback for NaN-containing batches
__global__ void slow_kernel(const float* __restrict__ x, const float* __restrict__ F_,
                            const float* __restrict__ H_, const float* __restrict__ Q_,
                            const float* __restrict__ R_, float* __restrict__ out) {
    int b = blockIdx.x;
    if (!g_nan[b]) return;
    int tid = threadIdx.x;
    __shared__ float sF[256], sH[128], sQ[256], sR[64];
    __shared__ float cov[256], covn[256], P[128], W[2][128], K[128], CU[256], FC[256];
    __shared__ float mean[16], meanu[16], meanp[16], obs[8], resid[8];
    __shared__ int nanb;

    sF[tid] = F_[tid];
    sQ[tid] = Q_[tid];
    if (tid < 128) sH[tid] = H_[tid];
    if (tid < 64)  sR[tid] = R_[tid];
    cov[tid] = ((tid >> 4) == (tid & 15)) ? 1.f : 0.f;
    if (tid < 16) mean[tid] = 0.f;
    if (tid < 8)  out[((size_t)b * MM + tid) * TT] = 0.f;
    __syncthreads();

    for (int t = 0; t < NS; t++) {
        if (tid == 0) {
            int nb = 0;
            for (int j = 0; j < 8; j++) {
                float v = x[((size_t)b * MM + j) * TT + t];
                if (isnan(v)) { nb = 1; v = 0.f; }
                obs[j] = v;
            }
            nanb = nb;
        }
        __syncthreads();
        if (tid < 128) {
            int i = tid >> 3, j = tid & 7;
            float s = 0.f;
            #pragma unroll
            for (int e = 0; e < 16; e++) s += cov[i * 16 + e] * sH[j * 16 + e];
            P[tid] = s;
        }
        if (tid >= 128 && tid < 136) {
            int j = tid - 128;
            float s = obs[j];
            #pragma unroll
            for (int e = 0; e < 16; e++) s -= sH[j * 16 + e] * mean[e];
            resid[j] = s;
        }
        __syncthreads();
        if (tid < 128) {
            int a = tid >> 4, c = tid & 15;
            float v;
            if (c < 8) {
                float s = sR[a * 8 + c];
                #pragma unroll
                for (int e = 0; e < 16; e++) s += sH[a * 16 + e] * P[e * 8 + c];
                v = s;
            } else v = (a == (c - 8)) ? 1.f : 0.f;
            W[0][a * 16 + c] = v;
        }
        __syncthreads();
        #pragma unroll 1
        for (int k = 0; k < 8; k++) {
            int cur = k & 1;
            if (tid < 128) {
                int a = tid >> 4, c = tid & 15;
                float piv = W[cur][k * 16 + k];
                float wkc = W[cur][k * 16 + c] / piv;
                W[cur ^ 1][a * 16 + c] = (a == k) ? wkc
                                                  : W[cur][a * 16 + c] - W[cur][a * 16 + k] * wkc;
            }
            __syncthreads();
        }
        if (tid < 128) {
            int i = tid >> 3, j = tid & 7;
            float s = 0.f;
            #pragma unroll
            for (int a = 0; a < 8; a++) s += P[i * 8 + a] * W[0][a * 16 + 8 + j];
            K[tid] = s;
        }
        __syncthreads();
        if (tid < 16) {
            float s = mean[tid];
            #pragma unroll
            for (int a = 0; a < 8; a++) s += K[tid * 8 + a] * resid[a];
            meanu[tid] = nanb ? mean[tid] : s;
        }
        {
            int i = tid >> 4, j = tid & 15;
            float s = cov[tid];
            #pragma unroll
            for (int a = 0; a < 8; a++) s -= K[i * 8 + a] * P[j * 8 + a];
            CU[tid] = nanb ? cov[tid] : s;
        }
        __syncthreads();
        {
            int i = tid >> 4, j = tid & 15;
            float s = 0.f;
            #pragma unroll
            for (int e = 0; e < 16; e++)
                s += sF[i * 16 + e] * 0.5f * (CU[e * 16 + j] + CU[j * 16 + e]);
            FC[tid] = s;
        }
        if (tid < 16) {
            float s = 0.f;
            #pragma unroll
            for (int e = 0; e < 16; e++) s += sF[tid * 16 + e] * meanu[e];
            meanp[tid] = s;
        }
        __syncthreads();
        {
            int i = tid >> 4, j = tid & 15;
            float s = sQ[tid];
            #pragma unroll
            for (int e = 0; e < 16; e++) s += FC[i * 16 + e] * sF[j * 16 + e];
            covn[tid] = s;
        }
        if (tid < 8) {
            float s = 0.f;
            #pragma unroll
            for (int e = 0; e < 16; e++) s += sH[tid * 16 + e] * meanp[e];
            out[((size_t)b * MM + tid) * TT + t + 1] = s;
        }
        __syncthreads();
        cov[tid] = covn[tid];
        if (tid < 16) mean[tid] = meanp[tid];
        __syncthreads();
    }
}

extern "C" void kernel_launch(void* const* d_in, const int* in_sizes, int n_in,
                              void* d_out, int out_size) {
    const float* x = (const float*)d_in[0];
    const float* F = (const float*)d_in[1];
    const float* H = (const float*)d_in[2];
    const float* Q = (const float*)d_in[3];
    const float* R = (const float*)d_in[4];
    float* out = (float*)d_out;

    nan_scan_kernel<<<BS, 256>>>(x);
    phase1_kernel<<<1, 256>>>(F, H, Q, R);
    fill_kernel<<<NS, 256>>>();
    group_serial_kernel<<<NCH * 8, 256>>>();
    group_scan_kernel<<<NCH, 256>>>();
    apply_kernel<<<NCH * 7, 256>>>();
    bvec_kernel<<<NCH * (BS / BGB), 256>>>(x);
    scan_kernel<<<BS / 8, 256>>>();
    phase2b_kernel<<<NCH * (BS / 16), 512>>>(x, out);
    slow_kernel<<<BS, 256>>>(x, F, H, Q, R, out);
}

// round 12
// speedup vs baseline: 2.3999x; 1.2898x over previous
#include <cuda_runtime.h>
#include <math.h>

#define BS   512
#define MM   8
#define TT   2048
#define NS   2047
#define NCH  32
#define CL   64
#define SUB  8
#define CONV_EPS 4e-3f

#define P17(r,c) ((r)*17+(c))
#define P9(r,c)  ((r)*9+(c))

// Packed maps: W1[t]=[M;G;0] (32x16), W2[t]=[N;D;0] (32x8); rows 24-31 stay 0
// (never written -> static zero-init, deterministic across replays).
__device__ float g_W1[(size_t)NS * 512];
__device__ float g_W2[(size_t)NS * 256];
__device__ float g_F[1024];            // fused frozen rows [32][32]
__device__ float g_P[NS * 128];
__device__ float g_T[NCH * 8 * 256];
__device__ float g_GS[NCH * 8 * 256];
__device__ float g_A[NCH * 256];
__device__ float g_b[BS * NCH * 16];
__device__ float g_m0[BS * NCH * 16];
__device__ int   g_tc;
__device__ unsigned char g_nan[BS];

__global__ void nan_scan_kernel(const float* __restrict__ x) {
    int b = blockIdx.x, tid = threadIdx.x;
    const float* xb = x + (size_t)b * MM * TT;
    int bad = 0;
    for (int idx = tid; idx < MM * TT; idx += 256) {
        int t = idx & (TT - 1);
        if (t < NS) bad |= isnan(xb[idx]) ? 1 : 0;
    }
    int any = __syncthreads_or(bad);
    if (tid == 0) g_nan[b] = any ? 1 : 0;
}

// ---------------------------------------------------------------------------
// Phase 1: Riccati, conflict-free padded smem (stride 17 / 9), 6 barriers/step,
// warp0 register GJ overlapped with F*cov / F*P / Y.
// ---------------------------------------------------------------------------
__global__ void __launch_bounds__(256) phase1_kernel(
        const float* __restrict__ F_, const float* __restrict__ H_,
        const float* __restrict__ Q_, const float* __restrict__ R_) {
    __shared__ float sF[272], sH[136], sQ[256], sR[64];
    __shared__ float cov[272];
    __shared__ float P[144];
    __shared__ float W[136];
    __shared__ float Sv[64];
    __shared__ float X[272];
    __shared__ float Y[272];
    __shared__ float FP[144];
    __shared__ float Nn[144];
    __shared__ float Mm[272];

    int tid = threadIdx.x;
    int i = tid >> 4, j = tid & 15;
    sF[P17(i, j)] = F_[tid];
    sQ[tid] = Q_[tid];
    if (tid < 128) sH[P17(tid >> 4, tid & 15)] = H_[tid];
    if (tid < 64)  sR[tid] = R_[tid];
    cov[P17(i, j)] = (i == j) ? 1.f : 0.f;
    __syncthreads();

    int tc = NS;
    for (int t = 0; t < NS; t++) {
        // s0: P = cov H^T (tid<128) ; X rows 0-7 (tid>=128; cov symmetric)
        if (tid < 128) {
            int r = tid >> 3, c = tid & 7;
            float s = 0.f;
            #pragma unroll
            for (int e = 0; e < 16; e++) s += cov[P17(r, e)] * sH[P17(c, e)];
            P[P9(r, c)] = s;
        } else {
            int u = tid - 128;
            int r = u >> 4, c = u & 15;
            float s = 0.f;
            #pragma unroll
            for (int e = 0; e < 16; e++) s += sF[P17(r, e)] * cov[P17(c, e)];
            X[P17(r, c)] = s;
        }
        __syncthreads();
        // s1: W=[S|I] (tid<128) ; X rows 8-15 (tid>=128)
        if (tid < 128) {
            int a = tid >> 4, c = tid & 15;
            float v;
            if (c < 8) {
                float s = sR[a * 8 + c];
                #pragma unroll
                for (int e = 0; e < 16; e++) s += sH[P17(a, e)] * P[P9(e, c)];
                v = s;
            } else {
                v = (a == (c - 8)) ? 1.f : 0.f;
            }
            W[P17(a, c)] = v;
        } else {
            int r = tid >> 4, c = tid & 15;   // r in 8..15
            float s = 0.f;
            #pragma unroll
            for (int e = 0; e < 16; e++) s += sF[P17(r, e)] * cov[P17(c, e)];
            X[P17(r, c)] = s;
        }
        __syncthreads();
        // s2: warp0 register GJ ; warps1-3 FP ; warps4-7 Y rows 0-7
        if (tid < 32) {
            int c = tid & 15, h = tid >> 4;
            float w[4];
            #pragma unroll
            for (int r = 0; r < 4; r++) w[r] = W[P17(h * 4 + r, c)];
            #pragma unroll
            for (int k = 0; k < 8; k++) {
                const int kh = k >> 2, kr = k & 3;
                float pivv  = __shfl_sync(0xffffffffu, w[kr], k + (kh << 4));
                float wkrow = __shfl_sync(0xffffffffu, w[kr], c + (kh << 4));
                float col0  = __shfl_sync(0xffffffffu, w[0], k + (h << 4));
                float col1  = __shfl_sync(0xffffffffu, w[1], k + (h << 4));
                float col2  = __shfl_sync(0xffffffffu, w[2], k + (h << 4));
                float col3  = __shfl_sync(0xffffffffu, w[3], k + (h << 4));
                float wkc = wkrow * __fdividef(1.0f, pivv);
                w[0] = (h * 4 + 0 == k) ? wkc : w[0] - col0 * wkc;
                w[1] = (h * 4 + 1 == k) ? wkc : w[1] - col1 * wkc;
                w[2] = (h * 4 + 2 == k) ? wkc : w[2] - col2 * wkc;
                w[3] = (h * 4 + 3 == k) ? wkc : w[3] - col3 * wkc;
            }
            if (c >= 8) {
                #pragma unroll
                for (int r = 0; r < 4; r++)
                    Sv[(h * 4 + r) * 8 + (c - 8)] = w[r];
            }
        } else if (tid < 128) {
            int u = tid - 32;
            {
                int r = u >> 3, c = u & 7;
                float s = 0.f;
                #pragma unroll
                for (int e = 0; e < 16; e++) s += sF[P17(r, e)] * P[P9(e, c)];
                FP[P9(r, c)] = s;
            }
            if (u < 32) {
                int u2 = u + 96;
                int r = u2 >> 3, c = u2 & 7;
                float s = 0.f;
                #pragma unroll
                for (int e = 0; e < 16; e++) s += sF[P17(r, e)] * P[P9(e, c)];
                FP[P9(r, c)] = s;
            }
        } else {
            int u = tid - 128;
            int r = u >> 4, c = u & 15;
            float s = 0.f;
            #pragma unroll
            for (int e = 0; e < 16; e++) s += X[P17(r, e)] * sF[P17(c, e)];
            Y[P17(r, c)] = s;
        }
        __syncthreads();
        // s3: Nn = FP * Sinv (tid<128) ; Y rows 8-15
        if (tid < 128) {
            int r = tid >> 3, c = tid & 7;
            float s = 0.f;
            #pragma unroll
            for (int a = 0; a < 8; a++) s += FP[P9(r, a)] * Sv[a * 8 + c];
            Nn[P9(r, c)] = s;
        } else {
            int r = tid >> 4, c = tid & 15;   // r in 8..15
            float s = 0.f;
            #pragma unroll
            for (int e = 0; e < 16; e++) s += X[P17(r, e)] * sF[P17(c, e)];
            Y[P17(r, c)] = s;
        }
        __syncthreads();
        // s4: cnew (register) and Mm
        float cnew;
        {
            float t1 = 0.f, t2 = 0.f, m = sF[P17(i, j)];
            #pragma unroll
            for (int a = 0; a < 8; a++) {
                float ni = Nn[P9(i, a)], fi = FP[P9(i, a)];
                t1 += ni * FP[P9(j, a)];
                t2 += fi * Nn[P9(j, a)];
                m  -= ni * sH[P17(a, j)];
            }
            cnew = Y[P17(i, j)] + sQ[tid] - 0.5f * (t1 + t2);
            Mm[P17(i, j)] = m;
        }
        __syncthreads();
        // s5: W1/W2 stores + cov update + convergence
        g_W1[(size_t)t * 512 + tid] = Mm[P17(i, j)];
        if (tid < 128) {
            g_W2[(size_t)t * 256 + tid] = Nn[P9(tid >> 3, tid & 7)];
            int a = tid >> 4, jj = tid & 15;
            float s = 0.f;
            #pragma unroll
            for (int e = 0; e < 16; e++) s += sH[P17(a, e)] * Mm[P17(e, jj)];
            g_W1[(size_t)t * 512 + 256 + tid] = s;
        } else if (tid < 192) {
            int u = tid - 128, a = u >> 3, jj = u & 7;
            float s = 0.f;
            #pragma unroll
            for (int e = 0; e < 16; e++) s += sH[P17(a, e)] * Nn[P9(e, jj)];
            g_W2[(size_t)t * 256 + 128 + u] = s;
        }
        float oldc = cov[P17(i, j)];
        float dlt = fabsf(cnew - oldc);
        cov[P17(i, j)] = cnew;
        int any = __syncthreads_or(dlt > CONV_EPS * (fabsf(oldc) + 1e-2f));
        if (!any) { tc = t + 1; break; }
    }
    if (tid == 0) g_tc = tc;
}

// ---------------------------------------------------------------------------
// fuse_kernel: build fused frozen 2-step rows from step (g_tc-1):
//   rows 0-15 : [M^2 | M*N | N]
//   rows 16-23: [G   | D   | 0]
//   rows 24-31: [G*M | G*N | D]
// ---------------------------------------------------------------------------
__global__ void fuse_kernel() {
    __shared__ float Ms[256], Ns[128], Gs[128], Ds[64];
    int tid = threadIdx.x;
    int src = g_tc - 1;
    Ms[tid] = g_W1[(size_t)src * 512 + tid];
    if (tid < 128) {
        Gs[tid] = g_W1[(size_t)src * 512 + 256 + tid];
        Ns[tid] = g_W2[(size_t)src * 256 + tid];
    }
    if (tid < 64) Ds[tid] = g_W2[(size_t)src * 256 + 128 + tid];
    __syncthreads();
    for (int idx = tid; idx < 1024; idx += 256) {
        int r = idx >> 5, c = idx & 31;
        float v = 0.f;
        if (r < 16) {
            if (c < 16) {
                #pragma unroll
                for (int e = 0; e < 16; e++) v += Ms[r * 16 + e] * Ms[e * 16 + c];
            } else if (c < 24) {
                #pragma unroll
                for (int e = 0; e < 16; e++) v += Ms[r * 16 + e] * Ns[e * 8 + (c - 16)];
            } else {
                v = Ns[r * 8 + (c - 24)];
            }
        } else if (r < 24) {
            int jj = r - 16;
            if (c < 16) v = Gs[jj * 16 + c];
            else if (c < 24) v = Ds[jj * 8 + (c - 16)];
        } else {
            int jj = r - 24;
            if (c < 16) {
                #pragma unroll
                for (int e = 0; e < 16; e++) v += Gs[jj * 16 + e] * Ms[e * 16 + c];
            } else if (c < 24) {
                #pragma unroll
                for (int e = 0; e < 16; e++) v += Gs[jj * 16 + e] * Ns[e * 8 + (c - 16)];
            } else {
                v = Ds[jj * 8 + (c - 24)];
            }
        }
        g_F[idx] = v;
    }
}

// 3a: per-(chunk,group) 8-step serial suffix -> U_p in g_P, group product g_T
// Reads matrices at clamped index min(t, g_tc-1)  (no fill kernel).
__global__ void __launch_bounds__(256) group_serial_kernel() {
    int c = blockIdx.x >> 3, g = blockIdx.x & 7;
    int base = c * CL + g * 8;
    int n = NS - base; if (n > 8) n = 8;
    int tcl = g_tc - 1;
    __shared__ float S[2][256], Mt[256], Nt[128];
    int tid = threadIdx.x;
    int i = tid >> 4, j = tid & 15;
    S[0][tid] = (i == j) ? 1.f : 0.f;
    int par = 0;
    int ts = base + n - 1; if (ts > tcl) ts = tcl;
    float mreg = g_W1[(size_t)ts * 512 + tid];
    float nreg = (tid < 128) ? g_W2[(size_t)ts * 256 + tid] : 0.f;
    __syncthreads();
    for (int it = n - 1; it >= 0; --it) {
        Mt[tid] = mreg;
        if (tid < 128) Nt[tid] = nreg;
        __syncthreads();
        if (it > 0) {
            int t2 = base + it - 1; if (t2 > tcl) t2 = tcl;
            mreg = g_W1[(size_t)t2 * 512 + tid];
            if (tid < 128) nreg = g_W2[(size_t)t2 * 256 + tid];
        }
        if (tid < 128) {
            int r = tid >> 3, cc = tid & 7;
            float s = 0.f;
            #pragma unroll
            for (int e = 0; e < 16; e++) s += S[par][r * 16 + e] * Nt[e * 8 + cc];
            g_P[(base + it) * 128 + tid] = s;
        }
        float sn = 0.f;
        #pragma unroll
        for (int e = 0; e < 16; e++) sn += S[par][i * 16 + e] * Mt[e * 16 + j];
        S[par ^ 1][tid] = sn;
        __syncthreads();
        par ^= 1;
    }
    g_T[(c * 8 + g) * 256 + tid] = S[par][tid];
}

// 3b: per-chunk scan of 8 group products -> GS_g, A_c
__global__ void __launch_bounds__(256) group_scan_kernel() {
    int c = blockIdx.x;
    __shared__ float S[2][256], Tt[256];
    int tid = threadIdx.x;
    int i = tid >> 4, j = tid & 15;
    S[0][tid] = (i == j) ? 1.f : 0.f;
    int par = 0;
    for (int g = 7; g >= 0; --g) {
        Tt[tid] = g_T[(c * 8 + g) * 256 + tid];
        __syncthreads();
        float v = 0.f;
        #pragma unroll
        for (int e = 0; e < 16; e++) v += S[par][i * 16 + e] * Tt[e * 16 + j];
        S[par ^ 1][tid] = v;
        if (g >= 1) g_GS[(c * 8 + g) * 256 + tid] = v;
        __syncthreads();
        par ^= 1;
    }
    g_A[c * 256 + tid] = S[par][tid];
}

// 3c: apply GS_{g+1} to U (groups 0..6)
__global__ void __launch_bounds__(256) apply_kernel() {
    int c = blockIdx.x / 7, g = blockIdx.x % 7;
    int base = c * CL + g * 8;
    __shared__ float GSs[256], Us[1024];
    int tid = threadIdx.x;
    GSs[tid] = g_GS[(c * 8 + g + 1) * 256 + tid];
    #pragma unroll
    for (int q = 0; q < 4; q++) {
        int k = tid + q * 256;
        Us[k] = g_P[(base + (k >> 7)) * 128 + (k & 127)];
    }
    __syncthreads();
    #pragma unroll
    for (int q = 0; q < 4; q++) {
        int k = tid + q * 256;
        int p = k >> 7, rc = k & 127, r = rc >> 3, cc = rc & 7;
        float v = 0.f;
        #pragma unroll
        for (int e = 0; e < 16; e++) v += GSs[r * 16 + e] * Us[p * 128 + e * 8 + cc];
        g_P[(base + p) * 128 + rc] = v;
    }
}

// Kernel 4: b_c = sum_t P_t * obs_t
#define BGB 8
__global__ void __launch_bounds__(256) bvec_kernel(const float* __restrict__ x) {
    int c = blockIdx.x & (NCH - 1);
    int bg = blockIdx.x >> 5;
    int cstart = c * CL;
    int clen = (NS - cstart < CL) ? (NS - cstart) : CL;
    __shared__ __align__(16) float sP[CL * 128];
    __shared__ __align__(16) float sX[BGB][CL][8];
    int tid = threadIdx.x;
    for (int idx = tid; idx < clen * 128; idx += 256)
        sP[idx] = g_P[cstart * 128 + idx];
    for (int idx = tid; idx < BGB * 8 * clen; idx += 256) {
        int s = idx % clen;
        int bm = idx / clen;
        int m = bm & 7, b = bm >> 3;
        sX[b][s][m] = x[((size_t)(bg * BGB + b) * MM + m) * TT + cstart + s];
    }
    __syncthreads();
    int w = tid >> 5, lane = tid & 31;
    int b = bg * BGB + w;
    if (lane < 16) {
        float acc = 0.f;
        for (int s = 0; s < clen; s++) {
            const float4* pp = (const float4*)&sP[s * 128 + lane * 8];
            float4 p0 = pp[0], p1 = pp[1];
            const float4* op = (const float4*)&sX[w][s][0];
            float4 o0 = op[0], o1 = op[1];
            acc += p0.x*o0.x + p0.y*o0.y + p0.z*o0.z + p0.w*o0.w
                 + p1.x*o1.x + p1.y*o1.y + p1.z*o1.z + p1.w*o1.w;
        }
        g_b[(b * NCH + c) * 16 + lane] = acc;
    }
}

// Kernel 5: serial scan over 32 chunks
__global__ void __launch_bounds__(256) scan_kernel() {
    __shared__ float sA[NCH * 256];
    int tid = threadIdx.x;
    for (int idx = tid; idx < NCH * 256; idx += 256) sA[idx] = g_A[idx];
    __syncthreads();
    int w = tid >> 5, lane = tid & 31;
    int b = blockIdx.x * 8 + w;
    int row = lane & 15;
    float mean_i = 0.f;
    float breg = (lane < 16) ? g_b[(b * NCH + 0) * 16 + lane] : 0.f;
    for (int c = 0; c < NCH; c++) {
        if (lane < 16) g_m0[(b * NCH + c) * 16 + lane] = mean_i;
        float bn = (lane < 16 && c + 1 < NCH) ? g_b[(b * NCH + c + 1) * 16 + lane] : 0.f;
        float nm = breg;
        #pragma unroll
        for (int e = 0; e < 16; e++) {
            float me = __shfl_sync(0xffffffffu, mean_i, e);
            nm += sA[c * 256 + row * 16 + e] * me;
        }
        mean_i = nm;
        breg = bn;
    }
}

// ---------------------------------------------------------------------------
// Kernel 6: within-chunk recursion + output. 256 threads = 8 warps = 8 batches.
// Frozen chunks: fused 2-step register path (g_F). Transient: smem path with
// clamped matrix reads.
// ---------------------------------------------------------------------------
__global__ void __launch_bounds__(256) phase2b_kernel(const float* __restrict__ x,
                                                      float* __restrict__ out) {
    int c = blockIdx.x & (NCH - 1);
    int bg = blockIdx.x >> 5;            // 64 batch groups of 8
    int cstart = c * CL;
    int clen = (NS - cstart < CL) ? (NS - cstart) : CL;
    int tid = threadIdx.x, w = tid >> 5, lane = tid & 31;
    int b = bg * 8 + w;
    int tcl = g_tc;

    if (cstart >= tcl) {
        // ---- fused 2-step frozen fast path ----
        const float* xb = x + (size_t)b * MM * TT;
        float* ob = out + (size_t)b * MM * TT;
        const float4* Fp = (const float4*)(g_F + lane * 32);
        float4 R0 = Fp[0], R1 = Fp[1], R2 = Fp[2], R3 = Fp[3];
        float4 R4 = Fp[4], R5 = Fp[5], R6 = Fp[6], R7 = Fp[7];

        float mval = (lane < 16) ? g_m0[(b * NCH + c) * 16 + lane] : 0.f;
        float mean[16];
        #pragma unroll
        for (int e = 0; e < 16; e++) mean[e] = __shfl_sync(0xffffffffu, mval, e);

        int m = lane & 7;
        int tend = cstart + clen;
        float nextobs = 0.f;
        if (lane >= 16)
            nextobs = xb[(size_t)m * TT + cstart + ((lane >= 24) ? 1 : 0)];

        int t = cstart;
        int nd = clen >> 1;
        for (int it = 0; it < nd; it++, t += 2) {
            float o1[8], o2[8];
            #pragma unroll
            for (int q = 0; q < 8; q++) {
                o1[q] = __shfl_sync(0xffffffffu, nextobs, 16 + q);
                o2[q] = __shfl_sync(0xffffffffu, nextobs, 24 + q);
            }
            if (lane >= 16) {
                int tn = t + 2 + ((lane >= 24) ? 1 : 0);
                if (tn < tend) nextobs = xb[(size_t)m * TT + tn];
            }
            float s0 = R0.x*mean[0]  + R0.y*mean[1]  + R0.z*mean[2]  + R0.w*mean[3];
            float s1 = R1.x*mean[4]  + R1.y*mean[5]  + R1.z*mean[6]  + R1.w*mean[7];
            float s2 = R2.x*mean[8]  + R2.y*mean[9]  + R2.z*mean[10] + R2.w*mean[11];
            float s3 = R3.x*mean[12] + R3.y*mean[13] + R3.z*mean[14] + R3.w*mean[15];
            float s4 = R4.x*o1[0] + R4.y*o1[1] + R4.z*o1[2] + R4.w*o1[3];
            float s5 = R5.x*o1[4] + R5.y*o1[5] + R5.z*o1[6] + R5.w*o1[7];
            float s6 = R6.x*o2[0] + R6.y*o2[1] + R6.z*o2[2] + R6.w*o2[3];
            float s7 = R7.x*o2[4] + R7.y*o2[5] + R7.z*o2[6] + R7.w*o2[7];
            float acc = ((s0 + s1) + (s2 + s3)) + ((s4 + s5) + (s6 + s7));

            if (lane >= 16)
                ob[(size_t)m * TT + t + ((lane >= 24) ? 2 : 1)] = acc;
            #pragma unroll
            for (int e = 0; e < 16; e++) mean[e] = __shfl_sync(0xffffffffu, acc, e);
        }
        if (clen & 1) {
            // final single step at t = tend-1: y_{t+1} from rows 16-23 ([G|D|0])
            float o1[8], o2[8];
            #pragma unroll
            for (int q = 0; q < 8; q++) {
                o1[q] = __shfl_sync(0xffffffffu, nextobs, 16 + q);
                o2[q] = __shfl_sync(0xffffffffu, nextobs, 24 + q);  // x0 for rows 16-23
            }
            float s0 = R0.x*mean[0]  + R0.y*mean[1]  + R0.z*mean[2]  + R0.w*mean[3];
            float s1 = R1.x*mean[4]  + R1.y*mean[5]  + R1.z*mean[6]  + R1.w*mean[7];
            float s2 = R2.x*mean[8]  + R2.y*mean[9]  + R2.z*mean[10] + R2.w*mean[11];
            float s3 = R3.x*mean[12] + R3.y*mean[13] + R3.z*mean[14] + R3.w*mean[15];
            float s4 = R4.x*o1[0] + R4.y*o1[1] + R4.z*o1[2] + R4.w*o1[3];
            float s5 = R5.x*o1[4] + R5.y*o1[5] + R5.z*o1[6] + R5.w*o1[7];
            float s6 = R6.x*o2[0] + R6.y*o2[1] + R6.z*o2[2] + R6.w*o2[3];
            float s7 = R7.x*o2[4] + R7.y*o2[5] + R7.z*o2[6] + R7.w*o2[7];
            float acc = ((s0 + s1) + (s2 + s3)) + ((s4 + s5) + (s6 + s7));
            if (lane >= 16 && lane < 24)
                ob[(size_t)m * TT + t + 1] = acc;
        }
        return;
    }

    // ---- transient smem path (clamped matrix reads) ----
    __shared__ __align__(16) float sW1[SUB][32][20];
    __shared__ __align__(16) float sW2[SUB][32][12];
    __shared__ __align__(16) float sX[8][SUB][8];
    __shared__ __align__(16) float sY[8][8][SUB];
    __shared__ __align__(16) float sMean[8][16];

    const size_t xbase = (size_t)b * MM * TT;
    if (lane < 16) sMean[w][lane] = g_m0[(b * NCH + c) * 16 + lane];
    if (c == 0 && lane < 8) out[xbase + (size_t)lane * TT] = 0.f;
    __syncwarp();

    for (int t0 = 0; t0 < clen; t0 += SUB) {
        int ns = (clen - t0 < SUB) ? (clen - t0) : SUB;
        __syncthreads();
        for (int idx = tid; idx < ns * 512; idx += 256) {
            int s = idx >> 9, rc = idx & 511;
            int ts = cstart + t0 + s; if (ts >= tcl) ts = tcl - 1;
            sW1[s][rc >> 4][rc & 15] = g_W1[(size_t)ts * 512 + rc];
        }
        for (int idx = tid; idx < ns * 256; idx += 256) {
            int s = idx >> 8, rc = idx & 255;
            int ts = cstart + t0 + s; if (ts >= tcl) ts = tcl - 1;
            sW2[s][rc >> 3][rc & 7] = g_W2[(size_t)ts * 256 + rc];
        }
        for (int idx = tid; idx < 64 * ns; idx += 256) {
            int s = idx % ns;
            int bm = idx / ns;
            int m = bm & 7, bb = bm >> 3;
            sX[bb][s][m] = x[((size_t)(bg * 8 + bb) * MM + m) * TT + cstart + t0 + s];
        }
        __syncthreads();

        for (int s = 0; s < ns; s++) {
            const float4* w1 = (const float4*)&sW1[s][lane][0];
            float4 a0 = w1[0], a1 = w1[1], a2 = w1[2], a3 = w1[3];
            const float4* w2 = (const float4*)&sW2[s][lane][0];
            float4 c0 = w2[0], c1 = w2[1];
            const float4* mp = (const float4*)&sMean[w][0];
            float4 m0 = mp[0], m1 = mp[1], m2 = mp[2], m3 = mp[3];
            const float4* op = (const float4*)&sX[w][s][0];
            float4 o0 = op[0], o1 = op[1];
            float s0 = a0.x*m0.x + a0.y*m0.y + a0.z*m0.z + a0.w*m0.w;
            float s1 = a1.x*m1.x + a1.y*m1.y + a1.z*m1.z + a1.w*m1.w;
            float s2 = a2.x*m2.x + a2.y*m2.y + a2.z*m2.z + a2.w*m2.w;
            float s3 = a3.x*m3.x + a3.y*m3.y + a3.z*m3.z + a3.w*m3.w;
            float s4 = c0.x*o0.x + c0.y*o0.y + c0.z*o0.z + c0.w*o0.w;
            float s5 = c1.x*o1.x + c1.y*o1.y + c1.z*o1.z + c1.w*o1.w;
            float acc = ((s0 + s1) + (s2 + s3)) + (s4 + s5);
            __syncwarp();
            if (lane < 16)      sMean[w][lane] = acc;
            else if (lane < 24) sY[w][lane - 16][s] = acc;
            __syncwarp();
        }
        __syncthreads();
        for (int idx = tid; idx < 64 * ns; idx += 256) {
            int s = idx % ns;
            int bm = idx / ns;
            int m = bm & 7, bb = bm >> 3;
            out[((size_t)(bg * 8 + bb) * MM + m) * TT + cstart + t0 + s + 1] = sY[bb][m][s];
        }
    }
}

// Kernel 7: exact per-batch fallback for NaN-containing batches
__global__ void slow_kernel(const float* __restrict__ x, const float* __restrict__ F_,
                            const float* __restrict__ H_, const float* __restrict__ Q_,
                            const float* __restrict__ R_, float* __restrict__ out) {
    int b = blockIdx.x;
    if (!g_nan[b]) return;
    int tid = threadIdx.x;
    __shared__ float sF[256], sH[128], sQ[256], sR[64];
    __shared__ float cov[256], covn[256], P[128], W[2][128], K[128], CU[256], FC[256];
    __shared__ float mean[16], meanu[16], meanp[16], obs[8], resid[8];
    __shared__ int nanb;

    sF[tid] = F_[tid];
    sQ[tid] = Q_[tid];
    if (tid < 128) sH[tid] = H_[tid];
    if (tid < 64)  sR[tid] = R_[tid];
    cov[tid] = ((tid >> 4) == (tid & 15)) ? 1.f : 0.f;
    if (tid < 16) mean[tid] = 0.f;
    if (tid < 8)  out[((size_t)b * MM + tid) * TT] = 0.f;
    __syncthreads();

    for (int t = 0; t < NS; t++) {
        if (tid == 0) {
            int nb = 0;
            for (int j = 0; j < 8; j++) {
                float v = x[((size_t)b * MM + j) * TT + t];
                if (isnan(v)) { nb = 1; v = 0.f; }
                obs[j] = v;
            }
            nanb = nb;
        }
        __syncthreads();
        if (tid < 128) {
            int i = tid >> 3, j = tid & 7;
            float s = 0.f;
            #pragma unroll
            for (int e = 0; e < 16; e++) s += cov[i * 16 + e] * sH[j * 16 + e];
            P[tid] = s;
        }
        if (tid >= 128 && tid < 136) {
            int j = tid - 128;
            float s = obs[j];
            #pragma unroll
            for (int e = 0; e < 16; e++) s -= sH[j * 16 + e] * mean[e];
            resid[j] = s;
        }
        __syncthreads();
        if (tid < 128) {
            int a = tid >> 4, c = tid & 15;
            float v;
            if (c < 8) {
                float s = sR[a * 8 + c];
                #pragma unroll
                for (int e = 0; e < 16; e++) s += sH[a * 16 + e] * P[e * 8 + c];
                v = s;
            } else v = (a == (c - 8)) ? 1.f : 0.f;
            W[0][a * 16 + c] = v;
        }
        __syncthreads();
        #pragma unroll 1
        for (int k = 0; k < 8; k++) {
            int cur = k & 1;
            if (tid < 128) {
                int a = tid >> 4, c = tid & 15;
                float piv = W[cur][k * 16 + k];
                float wkc = W[cur][k * 16 + c] / piv;
                W[cur ^ 1][a * 16 + c] = (a == k) ? wkc
                                                  : W[cur][a * 16 + c] - W[cur][a * 16 + k] * wkc;
            }
            __syncthreads();
        }
        if (tid < 128) {
            int i = tid >> 3, j = tid & 7;
            float s = 0.f;
            #pragma unroll
            for (int a = 0; a < 8; a++) s += P[i * 8 + a] * W[0][a * 16 + 8 + j];
            K[tid] = s;
        }
        __syncthreads();
        if (tid < 16) {
            float s = mean[tid];
            #pragma unroll
            for (int a = 0; a < 8; a++) s += K[tid * 8 + a] * resid[a];
            meanu[tid] = nanb ? mean[tid] : s;
        }
        {
            int i = tid >> 4, j = tid & 15;
            float s = cov[tid];
            #pragma unroll
            for (int a = 0; a < 8; a++) s -= K[i * 8 + a] * P[j * 8 + a];
            CU[tid] = nanb ? cov[tid] : s;
        }
        __syncthreads();
        {
            int i = tid >> 4, j = tid & 15;
            float s = 0.f;
            #pragma unroll
            for (int e = 0; e < 16; e++)
                s += sF[i * 16 + e] * 0.5f * (CU[e * 16 + j] + CU[j * 16 + e]);
            FC[tid] = s;
        }
        if (tid < 16) {
            float s = 0.f;
            #pragma unroll
            for (int e = 0; e < 16; e++) s += sF[tid * 16 + e] * meanu[e];
            meanp[tid] = s;
        }
        __syncthreads();
        {
            int i = tid >> 4, j = tid & 15;
            float s = sQ[tid];
            #pragma unroll
            for (int e = 0; e < 16; e++) s += FC[i * 16 + e] * sF[j * 16 + e];
            covn[tid] = s;
        }
        if (tid < 8) {
            float s = 0.f;
            #pragma unroll
            for (int e = 0; e < 16; e++) s += sH[tid * 16 + e] * meanp[e];
            out[((size_t)b * MM + tid) * TT + t + 1] = s;
        }
        __syncthreads();
        cov[tid] = covn[tid];
        if (tid < 16) mean[tid] = meanp[tid];
        __syncthreads();
    }
}

extern "C" void kernel_launch(void* const* d_in, const int* in_sizes, int n_in,
                              void* d_out, int out_size) {
    const float* x = (const float*)d_in[0];
    const float* F = (const float*)d_in[1];
    const float* H = (const float*)d_in[2];
    const float* Q = (const float*)d_in[3];
    const float* R = (const float*)d_in[4];
    float* out = (float*)d_out;

    nan_scan_kernel<<<BS, 256>>>(x);
    phase1_kernel<<<1, 256>>>(F, H, Q, R);
    fuse_kernel<<<1, 256>>>();
    group_serial_kernel<<<NCH * 8, 256>>>();
    group_scan_kernel<<<NCH, 256>>>();
    apply_kernel<<<NCH * 7, 256>>>();
    bvec_kernel<<<NCH * (BS / BGB), 256>>>(x);
    scan_kernel<<<BS / 8, 256>>>();
    phase2b_kernel<<<NCH * (BS / 8), 256>>>(x, out);
    slow_kernel<<<BS, 256>>>(x, F, H, Q, R, out);
}

// round 13
// speedup vs baseline: 2.5513x; 1.0631x over previous
#include <cuda_runtime.h>
#include <math.h>

#define BS   512
#define MM   8
#define TT   2048
#define NS   2047
#define NCH  32
#define CL   64
#define SUB  8
#define CONV_EPS 4e-3f

#define S20(r,c) ((r)*20+(c))
#define S12(r,c) ((r)*12+(c))

// Packed maps: W1[t]=[M;G;0] (32x16), W2[t]=[N;D;0] (32x8); rows 24-31 stay 0.
__device__ float g_W1[(size_t)NS * 512];
__device__ float g_W2[(size_t)NS * 256];
__device__ float g_F[1024];            // fused frozen rows [32][32]
__device__ float g_P[NS * 128];
__device__ float g_T[NCH * 8 * 256];
__device__ float g_A[NCH * 256];
__device__ float g_b[BS * NCH * 16];
__device__ float g_m0[BS * NCH * 16];
__device__ int   g_tc;
__device__ unsigned char g_nan[BS];

__device__ __forceinline__ float dot16(const float* a, const float* b) {
    const float4* A = (const float4*)a; const float4* B = (const float4*)b;
    float4 a0=A[0],a1=A[1],a2=A[2],a3=A[3], b0=B[0],b1=B[1],b2=B[2],b3=B[3];
    float s0=a0.x*b0.x+a0.y*b0.y+a0.z*b0.z+a0.w*b0.w;
    float s1=a1.x*b1.x+a1.y*b1.y+a1.z*b1.z+a1.w*b1.w;
    float s2=a2.x*b2.x+a2.y*b2.y+a2.z*b2.z+a2.w*b2.w;
    float s3=a3.x*b3.x+a3.y*b3.y+a3.z*b3.z+a3.w*b3.w;
    return (s0+s1)+(s2+s3);
}
__device__ __forceinline__ float dot8(const float* a, const float* b) {
    const float4* A = (const float4*)a; const float4* B = (const float4*)b;
    float4 a0=A[0],a1=A[1], b0=B[0],b1=B[1];
    return (a0.x*b0.x+a0.y*b0.y+a0.z*b0.z+a0.w*b0.w)
         + (a1.x*b1.x+a1.y*b1.y+a1.z*b1.z+a1.w*b1.w);
}

__global__ void nan_scan_kernel(const float* __restrict__ x) {
    int b = blockIdx.x, tid = threadIdx.x;
    const float* xb = x + (size_t)b * MM * TT;
    int bad = 0;
    for (int idx = tid; idx < MM * TT; idx += 256) {
        int t = idx & (TT - 1);
        if (t < NS) bad |= isnan(xb[idx]) ? 1 : 0;
    }
    int any = __syncthreads_or(bad);
    if (tid == 0) g_nan[b] = any ? 1 : 0;
}

// ---------------------------------------------------------------------------
// Phase 1: Riccati; every dot is contiguous row*row (float4), padded rows
// (stride 20 floats for 16-wide, 12 for 8-wide -> 16B aligned, <=2-way conf).
//   HC = H*cov ; S = HC*H^T + R ; Sinv via warp0 register GJ (writes SvT)
//   FP = F*cov*H^T = rowdot(F, HC) ; Nn = rowdot(FP, SvT)
//   cov' = Y + Q - 0.5(t1+t2), Y = X*F^T, X = F*cov
//   M = F - rowdot(Nn, HT) ; D = rowdot(H, NnT) ; G = HF - rowdot(D, HT)
// G for step t is stored in step t+1's s0 (deferred), final one after loop.
// ---------------------------------------------------------------------------
__global__ void __launch_bounds__(256) phase1_kernel(
        const float* __restrict__ F_, const float* __restrict__ H_,
        const float* __restrict__ Q_, const float* __restrict__ R_) {
    __shared__ __align__(16) float sF[320], cov[320], X[320], Y[320];
    __shared__ __align__(16) float sH[160], sHF[160], HC[160], NnT[160];
    __shared__ __align__(16) float sHT[192], FP[192], Nn[192];
    __shared__ __align__(16) float SvT[96], D[96];
    __shared__ float W[128], sQ[256], sR[64];

    int tid = threadIdx.x;
    int i = tid >> 4, j = tid & 15;
    sF[S20(i, j)] = F_[tid];
    sQ[tid] = Q_[tid];
    if (tid < 128) sH[S20(tid >> 4, tid & 15)] = H_[tid];
    if (tid < 64)  sR[tid] = R_[tid];
    cov[S20(i, j)] = (i == j) ? 1.f : 0.f;
    __syncthreads();
    if (tid < 128) {              // HT[j][a] = H[a][j]
        int jj = tid >> 3, aa = tid & 7;
        sHT[S12(jj, aa)] = sH[S20(aa, jj)];
    } else {                      // HF[a][j] = sum_e H[a,e] F[e,j]
        int u = tid - 128, aa = u >> 4, jj = u & 15;
        float s = 0.f;
        #pragma unroll
        for (int e = 0; e < 16; e++) s += sH[S20(aa, e)] * sF[S20(e, jj)];
        sHF[S20(aa, jj)] = s;
    }
    __syncthreads();

    int tc = NS;
    for (int t = 0; t < NS; t++) {
        // s0: HC (tid<128) + deferred G ; X (tid>=128, two rows)
        if (tid < 128) {
            int a = tid >> 4, c = tid & 15;
            HC[S20(a, c)] = dot16(&sH[S20(a, 0)], &cov[S20(c, 0)]);  // cov sym
            if (t > 0)
                g_W1[(size_t)(t - 1) * 512 + 256 + tid] =
                    sHF[S20(a, c)] - dot8(&D[S12(a, 0)], &sHT[S12(c, 0)]);
        } else {
            int u = tid - 128, r = u >> 4, c = u & 15;
            X[S20(r, c)]     = dot16(&sF[S20(r, 0)],     &cov[S20(c, 0)]);
            X[S20(r + 8, c)] = dot16(&sF[S20(r + 8, 0)], &cov[S20(c, 0)]);
        }
        __syncthreads();
        // s1: W=[S|I] (tid<128) ; FP (tid>=128)
        if (tid < 128) {
            int a = tid >> 4, c = tid & 15;
            W[a * 16 + c] = (c < 8)
                ? sR[a * 8 + c] + dot16(&HC[S20(a, 0)], &sH[S20(c, 0)])
                : ((a == c - 8) ? 1.f : 0.f);
        } else {
            int u = tid - 128, r = u >> 3, cc = u & 7;
            FP[S12(r, cc)] = dot16(&sF[S20(r, 0)], &HC[S20(cc, 0)]);
        }
        __syncthreads();
        // s2: warp0 register GJ -> SvT ; tid>=32: Y (all 256 outputs)
        if (tid < 32) {
            int c = tid & 15, h = tid >> 4;
            float w[4];
            #pragma unroll
            for (int r = 0; r < 4; r++) w[r] = W[(h * 4 + r) * 16 + c];
            #pragma unroll
            for (int k = 0; k < 8; k++) {
                const int kh = k >> 2, kr = k & 3;
                float pivv  = __shfl_sync(0xffffffffu, w[kr], k + (kh << 4));
                float wkrow = __shfl_sync(0xffffffffu, w[kr], c + (kh << 4));
                float col0  = __shfl_sync(0xffffffffu, w[0], k + (h << 4));
                float col1  = __shfl_sync(0xffffffffu, w[1], k + (h << 4));
                float col2  = __shfl_sync(0xffffffffu, w[2], k + (h << 4));
                float col3  = __shfl_sync(0xffffffffu, w[3], k + (h << 4));
                float wkc = wkrow * __fdividef(1.0f, pivv);
                w[0] = (h * 4 + 0 == k) ? wkc : w[0] - col0 * wkc;
                w[1] = (h * 4 + 1 == k) ? wkc : w[1] - col1 * wkc;
                w[2] = (h * 4 + 2 == k) ? wkc : w[2] - col2 * wkc;
                w[3] = (h * 4 + 3 == k) ? wkc : w[3] - col3 * wkc;
            }
            if (c >= 8) {
                #pragma unroll
                for (int r = 0; r < 4; r++)
                    SvT[S12(c - 8, h * 4 + r)] = w[r];
            }
        } else {
            int u = tid - 32;
            Y[S20(u >> 4, u & 15)] = dot16(&X[S20(u >> 4, 0)], &sF[S20(u & 15, 0)]);
            if (u < 32) {
                int u2 = u + 224;
                Y[S20(u2 >> 4, u2 & 15)] = dot16(&X[S20(u2 >> 4, 0)], &sF[S20(u2 & 15, 0)]);
            }
        }
        __syncthreads();
        // s3: Nn = rowdot(FP, SvT) (+NnT)
        if (tid < 128) {
            int r = tid >> 3, cc = tid & 7;
            float v = dot8(&FP[S12(r, 0)], &SvT[S12(cc, 0)]);
            Nn[S12(r, cc)] = v;
            NnT[S20(cc, r)] = v;
        }
        __syncthreads();
        // s4: cov update, M store, N/D stores
        float cnew;
        {
            float t1 = dot8(&Nn[S12(i, 0)], &FP[S12(j, 0)]);
            float t2 = dot8(&FP[S12(i, 0)], &Nn[S12(j, 0)]);
            float m  = sF[S20(i, j)] - dot8(&Nn[S12(i, 0)], &sHT[S12(j, 0)]);
            cnew = Y[S20(i, j)] + sQ[tid] - 0.5f * (t1 + t2);
            g_W1[(size_t)t * 512 + tid] = m;
        }
        if (tid < 128) {
            g_W2[(size_t)t * 256 + tid] = Nn[S12(tid >> 3, tid & 7)];
        } else if (tid < 192) {
            int u = tid - 128, a = u >> 3, bb = u & 7;
            float d = dot16(&sH[S20(a, 0)], &NnT[S20(bb, 0)]);
            D[S12(a, bb)] = d;
            g_W2[(size_t)t * 256 + 128 + u] = d;
        }
        float oldc = cov[S20(i, j)];
        float dlt = fabsf(cnew - oldc);
        cov[S20(i, j)] = cnew;
        int any = __syncthreads_or(dlt > CONV_EPS * (fabsf(oldc) + 1e-2f));
        if (!any) { tc = t + 1; break; }
    }
    if (tid == 0) g_tc = tc;
    // final deferred G for step tc-1 (D of tc-1 still in smem)
    if (tid < 128) {
        int a = tid >> 4, c = tid & 15;
        g_W1[(size_t)(tc - 1) * 512 + 256 + tid] =
            sHF[S20(a, c)] - dot8(&D[S12(a, 0)], &sHT[S12(c, 0)]);
    }
}

// ---------------------------------------------------------------------------
// fuse_kernel: fused frozen 2-step rows from step (g_tc-1):
//   rows 0-15 : [M^2 | M*N | N] ; rows 16-23: [G|D|0] ; rows 24-31: [GM|GN|D]
// ---------------------------------------------------------------------------
__global__ void fuse_kernel() {
    __shared__ float Ms[256], Ns[128], Gs[128], Ds[64];
    int tid = threadIdx.x;
    int src = g_tc - 1;
    Ms[tid] = g_W1[(size_t)src * 512 + tid];
    if (tid < 128) {
        Gs[tid] = g_W1[(size_t)src * 512 + 256 + tid];
        Ns[tid] = g_W2[(size_t)src * 256 + tid];
    }
    if (tid < 64) Ds[tid] = g_W2[(size_t)src * 256 + 128 + tid];
    __syncthreads();
    for (int idx = tid; idx < 1024; idx += 256) {
        int r = idx >> 5, c = idx & 31;
        float v = 0.f;
        if (r < 16) {
            if (c < 16) {
                #pragma unroll
                for (int e = 0; e < 16; e++) v += Ms[r * 16 + e] * Ms[e * 16 + c];
            } else if (c < 24) {
                #pragma unroll
                for (int e = 0; e < 16; e++) v += Ms[r * 16 + e] * Ns[e * 8 + (c - 16)];
            } else {
                v = Ns[r * 8 + (c - 24)];
            }
        } else if (r < 24) {
            int jj = r - 16;
            if (c < 16) v = Gs[jj * 16 + c];
            else if (c < 24) v = Ds[jj * 8 + (c - 16)];
        } else {
            int jj = r - 24;
            if (c < 16) {
                #pragma unroll
                for (int e = 0; e < 16; e++) v += Gs[jj * 16 + e] * Ms[e * 16 + c];
            } else if (c < 24) {
                #pragma unroll
                for (int e = 0; e < 16; e++) v += Gs[jj * 16 + e] * Ns[e * 8 + (c - 16)];
            } else {
                v = Ds[jj * 8 + (c - 24)];
            }
        }
        g_F[idx] = v;
    }
}

// 3a: per-(chunk,group) 8-step serial suffix (clamped reads, no fill kernel)
__global__ void __launch_bounds__(256) group_serial_kernel() {
    int c = blockIdx.x >> 3, g = blockIdx.x & 7;
    int base = c * CL + g * 8;
    int n = NS - base; if (n > 8) n = 8;
    int tcl = g_tc - 1;
    __shared__ float S[2][256], Mt[256], Nt[128];
    int tid = threadIdx.x;
    int i = tid >> 4, j = tid & 15;
    S[0][tid] = (i == j) ? 1.f : 0.f;
    int par = 0;
    int ts = base + n - 1; if (ts > tcl) ts = tcl;
    float mreg = g_W1[(size_t)ts * 512 + tid];
    float nreg = (tid < 128) ? g_W2[(size_t)ts * 256 + tid] : 0.f;
    __syncthreads();
    for (int it = n - 1; it >= 0; --it) {
        Mt[tid] = mreg;
        if (tid < 128) Nt[tid] = nreg;
        __syncthreads();
        if (it > 0) {
            int t2 = base + it - 1; if (t2 > tcl) t2 = tcl;
            mreg = g_W1[(size_t)t2 * 512 + tid];
            if (tid < 128) nreg = g_W2[(size_t)t2 * 256 + tid];
        }
        if (tid < 128) {
            int r = tid >> 3, cc = tid & 7;
            float s = 0.f;
            #pragma unroll
            for (int e = 0; e < 16; e++) s += S[par][r * 16 + e] * Nt[e * 8 + cc];
            g_P[(base + it) * 128 + tid] = s;
        }
        float sn = 0.f;
        #pragma unroll
        for (int e = 0; e < 16; e++) sn += S[par][i * 16 + e] * Mt[e * 16 + j];
        S[par ^ 1][tid] = sn;
        __syncthreads();
        par ^= 1;
    }
    g_T[(c * 8 + g) * 256 + tid] = S[par][tid];
}

// 3bc merged: per-chunk scan of group products, then apply suffixes to U.
__global__ void __launch_bounds__(256) scan_apply_kernel() {
    int c = blockIdx.x;
    __shared__ float S[2][256], Tt[256];
    __shared__ float sGS[8][256];
    __shared__ float Us[1024];
    int tid = threadIdx.x;
    int i = tid >> 4, j = tid & 15;
    S[0][tid] = (i == j) ? 1.f : 0.f;
    int par = 0;
    for (int g = 7; g >= 0; --g) {
        Tt[tid] = g_T[(c * 8 + g) * 256 + tid];
        __syncthreads();
        float v = 0.f;
        #pragma unroll
        for (int e = 0; e < 16; e++) v += S[par][i * 16 + e] * Tt[e * 16 + j];
        S[par ^ 1][tid] = v;
        if (g >= 1) sGS[g][tid] = v;
        __syncthreads();
        par ^= 1;
    }
    g_A[c * 256 + tid] = S[par][tid];
    // apply GS_{g+1} to groups 0..6
    for (int g = 0; g < 7; g++) {
        int base = c * CL + g * 8;
        #pragma unroll
        for (int q = 0; q < 4; q++) {
            int k = tid + q * 256;
            Us[k] = g_P[(base + (k >> 7)) * 128 + (k & 127)];
        }
        __syncthreads();
        #pragma unroll
        for (int q = 0; q < 4; q++) {
            int k = tid + q * 256;
            int p = k >> 7, rc = k & 127, r = rc >> 3, cc = rc & 7;
            float v = 0.f;
            #pragma unroll
            for (int e = 0; e < 16; e++)
                v += sGS[g + 1][r * 16 + e] * Us[p * 128 + e * 8 + cc];
            g_P[(base + p) * 128 + rc] = v;
        }
        __syncthreads();
    }
}

// Kernel 4: b_c = sum_t P_t * obs_t
#define BGB 8
__global__ void __launch_bounds__(256) bvec_kernel(const float* __restrict__ x) {
    int c = blockIdx.x & (NCH - 1);
    int bg = blockIdx.x >> 5;
    int cstart = c * CL;
    int clen = (NS - cstart < CL) ? (NS - cstart) : CL;
    __shared__ __align__(16) float sP[CL * 128];
    __shared__ __align__(16) float sX[BGB][CL][8];
    int tid = threadIdx.x;
    for (int idx = tid; idx < clen * 128; idx += 256)
        sP[idx] = g_P[cstart * 128 + idx];
    for (int idx = tid; idx < BGB * 8 * clen; idx += 256) {
        int s = idx % clen;
        int bm = idx / clen;
        int m = bm & 7, b = bm >> 3;
        sX[b][s][m] = x[((size_t)(bg * BGB + b) * MM + m) * TT + cstart + s];
    }
    __syncthreads();
    int w = tid >> 5, lane = tid & 31;
    int b = bg * BGB + w;
    if (lane < 16) {
        float acc = 0.f;
        for (int s = 0; s < clen; s++) {
            const float4* pp = (const float4*)&sP[s * 128 + lane * 8];
            float4 p0 = pp[0], p1 = pp[1];
            const float4* op = (const float4*)&sX[w][s][0];
            float4 o0 = op[0], o1 = op[1];
            acc += p0.x*o0.x + p0.y*o0.y + p0.z*o0.z + p0.w*o0.w
                 + p1.x*o1.x + p1.y*o1.y + p1.z*o1.z + p1.w*o1.w;
        }
        g_b[(b * NCH + c) * 16 + lane] = acc;
    }
}

// Kernel 5: serial scan over 32 chunks
__global__ void __launch_bounds__(256) scan_kernel() {
    __shared__ float sA[NCH * 256];
    int tid = threadIdx.x;
    for (int idx = tid; idx < NCH * 256; idx += 256) sA[idx] = g_A[idx];
    __syncthreads();
    int w = tid >> 5, lane = tid & 31;
    int b = blockIdx.x * 8 + w;
    int row = lane & 15;
    float mean_i = 0.f;
    float breg = (lane < 16) ? g_b[(b * NCH + 0) * 16 + lane] : 0.f;
    for (int c = 0; c < NCH; c++) {
        if (lane < 16) g_m0[(b * NCH + c) * 16 + lane] = mean_i;
        float bn = (lane < 16 && c + 1 < NCH) ? g_b[(b * NCH + c + 1) * 16 + lane] : 0.f;
        float nm = breg;
        #pragma unroll
        for (int e = 0; e < 16; e++) {
            float me = __shfl_sync(0xffffffffu, mean_i, e);
            nm += sA[c * 256 + row * 16 + e] * me;
        }
        mean_i = nm;
        breg = bn;
    }
}

// ---------------------------------------------------------------------------
// Kernel 6: within-chunk recursion + output. 256 thr = 8 warps = 8 batches.
// Frozen chunks: fused 2-step register path with per-warp smem broadcast
// (no shuffles). Transient chunks: smem path with clamped matrix reads.
// ---------------------------------------------------------------------------
__global__ void __launch_bounds__(256) phase2b_kernel(const float* __restrict__ x,
                                                      float* __restrict__ out) {
    int c = blockIdx.x & (NCH - 1);
    int bg = blockIdx.x >> 5;            // 64 batch groups of 8
    int cstart = c * CL;
    int clen = (NS - cstart < CL) ? (NS - cstart) : CL;
    int tid = threadIdx.x, w = tid >> 5, lane = tid & 31;
    int b = bg * 8 + w;
    int tcl = g_tc;

    __shared__ __align__(16) float sB[8][32];   // per-warp: mean[16]|o1[8]|o2[8]

    if (cstart >= tcl) {
        const float* xb = x + (size_t)b * MM * TT;
        float* ob = out + (size_t)b * MM * TT;
        const float4* Fp = (const float4*)(g_F + lane * 32);
        float4 R0 = Fp[0], R1 = Fp[1], R2 = Fp[2], R3 = Fp[3];
        float4 R4 = Fp[4], R5 = Fp[5], R6 = Fp[6], R7 = Fp[7];

        if (lane < 16) sB[w][lane] = g_m0[(b * NCH + c) * 16 + lane];

        int m = lane & 7;
        int tend = cstart + clen;
        float nextobs = 0.f;
        if (lane >= 16)
            nextobs = xb[(size_t)m * TT + cstart + ((lane >= 24) ? 1 : 0)];

        int t = cstart;
        int nd = clen >> 1;
        for (int it = 0; it < nd; it++, t += 2) {
            if (lane >= 16) sB[w][lane] = nextobs;
            __syncwarp();
            const float4* bp = (const float4*)&sB[w][0];
            float4 m0 = bp[0], m1 = bp[1], m2 = bp[2], m3 = bp[3];
            float4 oa = bp[4], obv = bp[5], oc = bp[6], od = bp[7];
            if (lane >= 16) {
                int tn = t + 2 + ((lane >= 24) ? 1 : 0);
                if (tn < tend) nextobs = xb[(size_t)m * TT + tn];
            }
            float s0 = R0.x*m0.x + R0.y*m0.y + R0.z*m0.z + R0.w*m0.w;
            float s1 = R1.x*m1.x + R1.y*m1.y + R1.z*m1.z + R1.w*m1.w;
            float s2 = R2.x*m2.x + R2.y*m2.y + R2.z*m2.z + R2.w*m2.w;
            float s3 = R3.x*m3.x + R3.y*m3.y + R3.z*m3.z + R3.w*m3.w;
            float s4 = R4.x*oa.x + R4.y*oa.y + R4.z*oa.z + R4.w*oa.w;
            float s5 = R5.x*obv.x + R5.y*obv.y + R5.z*obv.z + R5.w*obv.w;
            float s6 = R6.x*oc.x + R6.y*oc.y + R6.z*oc.z + R6.w*oc.w;
            float s7 = R7.x*od.x + R7.y*od.y + R7.z*od.z + R7.w*od.w;
            float acc = ((s0 + s1) + (s2 + s3)) + ((s4 + s5) + (s6 + s7));

            if (lane >= 16)
                ob[(size_t)m * TT + t + ((lane >= 24) ? 2 : 1)] = acc;
            __syncwarp();
            if (lane < 16) sB[w][lane] = acc;
        }
        if (clen & 1) {
            if (lane >= 16) sB[w][lane] = nextobs;
            __syncwarp();
            const float4* bp = (const float4*)&sB[w][0];
            float4 m0 = bp[0], m1 = bp[1], m2 = bp[2], m3 = bp[3];
            float4 oa = bp[4], obv = bp[5], oc = bp[6], od = bp[7];
            float s0 = R0.x*m0.x + R0.y*m0.y + R0.z*m0.z + R0.w*m0.w;
            float s1 = R1.x*m1.x + R1.y*m1.y + R1.z*m1.z + R1.w*m1.w;
            float s2 = R2.x*m2.x + R2.y*m2.y + R2.z*m2.z + R2.w*m2.w;
            float s3 = R3.x*m3.x + R3.y*m3.y + R3.z*m3.z + R3.w*m3.w;
            float s4 = R4.x*oa.x + R4.y*oa.y + R4.z*oa.z + R4.w*oa.w;
            float s5 = R5.x*obv.x + R5.y*obv.y + R5.z*obv.z + R5.w*obv.w;
            float s6 = R6.x*oc.x + R6.y*oc.y + R6.z*oc.z + R6.w*oc.w;
            float s7 = R7.x*od.x + R7.y*od.y + R7.z*od.z + R7.w*od.w;
            float acc = ((s0 + s1) + (s2 + s3)) + ((s4 + s5) + (s6 + s7));
            if (lane >= 16 && lane < 24)
                ob[(size_t)m * TT + t + 1] = acc;
        }
        return;
    }

    // ---- transient smem path (clamped matrix reads) ----
    __shared__ __align__(16) float sW1[SUB][32][20];
    __shared__ __align__(16) float sW2[SUB][32][12];
    __shared__ __align__(16) float sX[8][SUB][8];
    __shared__ __align__(16) float sY[8][8][SUB];
    __shared__ __align__(16) float sMean[8][16];

    const size_t xbase = (size_t)b * MM * TT;
    if (lane < 16) sMean[w][lane] = g_m0[(b * NCH + c) * 16 + lane];
    if (c == 0 && lane < 8) out[xbase + (size_t)lane * TT] = 0.f;
    __syncwarp();

    for (int t0 = 0; t0 < clen; t0 += SUB) {
        int ns = (clen - t0 < SUB) ? (clen - t0) : SUB;
        __syncthreads();
        for (int idx = tid; idx < ns * 512; idx += 256) {
            int s = idx >> 9, rc = idx & 511;
            int ts = cstart + t0 + s; if (ts >= tcl) ts = tcl - 1;
            sW1[s][rc >> 4][rc & 15] = g_W1[(size_t)ts * 512 + rc];
        }
        for (int idx = tid; idx < ns * 256; idx += 256) {
            int s = idx >> 8, rc = idx & 255;
            int ts = cstart + t0 + s; if (ts >= tcl) ts = tcl - 1;
            sW2[s][rc >> 3][rc & 7] = g_W2[(size_t)ts * 256 + rc];
        }
        for (int idx = tid; idx < 64 * ns; idx += 256) {
            int s = idx % ns;
            int bm = idx / ns;
            int m = bm & 7, bb = bm >> 3;
            sX[bb][s][m] = x[((size_t)(bg * 8 + bb) * MM + m) * TT + cstart + t0 + s];
        }
        __syncthreads();

        for (int s = 0; s < ns; s++) {
            const float4* w1 = (const float4*)&sW1[s][lane][0];
            float4 a0 = w1[0], a1 = w1[1], a2 = w1[2], a3 = w1[3];
            const float4* w2 = (const float4*)&sW2[s][lane][0];
            float4 c0 = w2[0], c1 = w2[1];
            const float4* mp = (const float4*)&sMean[w][0];
            float4 m0 = mp[0], m1 = mp[1], m2 = mp[2], m3 = mp[3];
            const float4* op = (const float4*)&sX[w][s][0];
            float4 o0 = op[0], o1 = op[1];
            float s0 = a0.x*m0.x + a0.y*m0.y + a0.z*m0.z + a0.w*m0.w;
            float s1 = a1.x*m1.x + a1.y*m1.y + a1.z*m1.z + a1.w*m1.w;
            float s2 = a2.x*m2.x + a2.y*m2.y + a2.z*m2.z + a2.w*m2.w;
            float s3 = a3.x*m3.x + a3.y*m3.y + a3.z*m3.z + a3.w*m3.w;
            float s4 = c0.x*o0.x + c0.y*o0.y + c0.z*o0.z + c0.w*o0.w;
            float s5 = c1.x*o1.x + c1.y*o1.y + c1.z*o1.z + c1.w*o1.w;
            float acc = ((s0 + s1) + (s2 + s3)) + (s4 + s5);
            __syncwarp();
            if (lane < 16)      sMean[w][lane] = acc;
            else if (lane < 24) sY[w][lane - 16][s] = acc;
            __syncwarp();
        }
        __syncthreads();
        for (int idx = tid; idx < 64 * ns; idx += 256) {
            int s = idx % ns;
            int bm = idx / ns;
            int m = bm & 7, bb = bm >> 3;
            out[((size_t)(bg * 8 + bb) * MM + m) * TT + cstart + t0 + s + 1] = sY[bb][m][s];
        }
    }
}

// Kernel 7: exact per-batch fallback for NaN-containing batches
__global__ void slow_kernel(const float* __restrict__ x, const float* __restrict__ F_,
                            const float* __restrict__ H_, const float* __restrict__ Q_,
                            const float* __restrict__ R_, float* __restrict__ out) {
    int b = blockIdx.x;
    if (!g_nan[b]) return;
    int tid = threadIdx.x;
    __shared__ float sF[256], sH[128], sQ[256], sR[64];
    __shared__ float cov[256], covn[256], P[128], W[2][128], K[128], CU[256], FC[256];
    __shared__ float mean[16], meanu[16], meanp[16], obs[8], resid[8];
    __shared__ int nanb;

    sF[tid] = F_[tid];
    sQ[tid] = Q_[tid];
    if (tid < 128) sH[tid] = H_[tid];
    if (tid < 64)  sR[tid] = R_[tid];
    cov[tid] = ((tid >> 4) == (tid & 15)) ? 1.f : 0.f;
    if (tid < 16) mean[tid] = 0.f;
    if (tid < 8)  out[((size_t)b * MM + tid) * TT] = 0.f;
    __syncthreads();

    for (int t = 0; t < NS; t++) {
        if (tid == 0) {
            int nb = 0;
            for (int j = 0; j < 8; j++) {
                float v = x[((size_t)b * MM + j) * TT + t];
                if (isnan(v)) { nb = 1; v = 0.f; }
                obs[j] = v;
            }
            nanb = nb;
        }
        __syncthreads();
        if (tid < 128) {
            int i = tid >> 3, j = tid & 7;
            float s = 0.f;
            #pragma unroll
            for (int e = 0; e < 16; e++) s += cov[i * 16 + e] * sH[j * 16 + e];
            P[tid] = s;
        }
        if (tid >= 128 && tid < 136) {
            int j = tid - 128;
            float s = obs[j];
            #pragma unroll
            for (int e = 0; e < 16; e++) s -= sH[j * 16 + e] * mean[e];
            resid[j] = s;
        }
        __syncthreads();
        if (tid < 128) {
            int a = tid >> 4, c = tid & 15;
            float v;
            if (c < 8) {
                float s = sR[a * 8 + c];
                #pragma unroll
                for (int e = 0; e < 16; e++) s += sH[a * 16 + e] * P[e * 8 + c];
                v = s;
            } else v = (a == (c - 8)) ? 1.f : 0.f;
            W[0][a * 16 + c] = v;
        }
        __syncthreads();
        #pragma unroll 1
        for (int k = 0; k < 8; k++) {
            int cur = k & 1;
            if (tid < 128) {
                int a = tid >> 4, c = tid & 15;
                float piv = W[cur][k * 16 + k];
                float wkc = W[cur][k * 16 + c] / piv;
                W[cur ^ 1][a * 16 + c] = (a == k) ? wkc
                                                  : W[cur][a * 16 + c] - W[cur][a * 16 + k] * wkc;
            }
            __syncthreads();
        }
        if (tid < 128) {
            int i = tid >> 3, j = tid & 7;
            float s = 0.f;
            #pragma unroll
            for (int a = 0; a < 8; a++) s += P[i * 8 + a] * W[0][a * 16 + 8 + j];
            K[tid] = s;
        }
        __syncthreads();
        if (tid < 16) {
            float s = mean[tid];
            #pragma unroll
            for (int a = 0; a < 8; a++) s += K[tid * 8 + a] * resid[a];
            meanu[tid] = nanb ? mean[tid] : s;
        }
        {
            int i = tid >> 4, j = tid & 15;
            float s = cov[tid];
            #pragma unroll
            for (int a = 0; a < 8; a++) s -= K[i * 8 + a] * P[j * 8 + a];
            CU[tid] = nanb ? cov[tid] : s;
        }
        __syncthreads();
        {
            int i = tid >> 4, j = tid & 15;
            float s = 0.f;
            #pragma unroll
            for (int e = 0; e < 16; e++)
                s += sF[i * 16 + e] * 0.5f * (CU[e * 16 + j] + CU[j * 16 + e]);
            FC[tid] = s;
        }
        if (tid < 16) {
            float s = 0.f;
            #pragma unroll
            for (int e = 0; e < 16; e++) s += sF[tid * 16 + e] * meanu[e];
            meanp[tid] = s;
        }
        __syncthreads();
        {
            int i = tid >> 4, j = tid & 15;
            float s = sQ[tid];
            #pragma unroll
            for (int e = 0; e < 16; e++) s += FC[i * 16 + e] * sF[j * 16 + e];
            covn[tid] = s;
        }
        if (tid < 8) {
            float s = 0.f;
            #pragma unroll
            for (int e = 0; e < 16; e++) s += sH[tid * 16 + e] * meanp[e];
            out[((size_t)b * MM + tid) * TT + t + 1] = s;
        }
        __syncthreads();
        cov[tid] = covn[tid];
        if (tid < 16) mean[tid] = meanp[tid];
        __syncthreads();
    }
}

extern "C" void kernel_launch(void* const* d_in, const int* in_sizes, int n_in,
                              void* d_out, int out_size) {
    const float* x = (const float*)d_in[0];
    const float* F = (const float*)d_in[1];
    const float* H = (const float*)d_in[2];
    const float* Q = (const float*)d_in[3];
    const float* R = (const float*)d_in[4];
    float* out = (float*)d_out;

    nan_scan_kernel<<<BS, 256>>>(x);
    phase1_kernel<<<1, 256>>>(F, H, Q, R);
    fuse_kernel<<<1, 256>>>();
    group_serial_kernel<<<NCH * 8, 256>>>();
    scan_apply_kernel<<<NCH, 256>>>();
    bvec_kernel<<<NCH * (BS / BGB), 256>>>(x);
    scan_kernel<<<BS / 8, 256>>>();
    phase2b_kernel<<<NCH * (BS / 8), 256>>>(x, out);
    slow_kernel<<<BS, 256>>>(x, F, H, Q, R, out);
}

// round 14
// speedup vs baseline: 2.6206x; 1.0271x over previous
#include <cuda_runtime.h>
#include <math.h>

#define BS   512
#define MM   8
#define TT   2048
#define NS   2047
#define NCH  32
#define CL   64
#define SUB  8
#define CONV_EPS 4e-3f

#define S20(r,c) ((r)*20+(c))
#define S12(r,c) ((r)*12+(c))

// Packed maps: W1[t]=[M;G;0] (32x16), W2[t]=[N;D;0] (32x8); rows 24-31 stay 0.
__device__ float g_W1[(size_t)NS * 512];
__device__ float g_W2[(size_t)NS * 256];
__device__ float g_F[1024];            // fused frozen rows [32][32]
__device__ float g_P[NS * 128];
__device__ float g_T[NCH * 8 * 256];
__device__ float g_A[NCH * 256];
__device__ float g_b[BS * NCH * 16];
__device__ float g_m0[BS * NCH * 16];
__device__ int   g_tc;
__device__ unsigned char g_nan[BS];

__device__ __forceinline__ float dot16(const float* a, const float* b) {
    const float4* A = (const float4*)a; const float4* B = (const float4*)b;
    float4 a0=A[0],a1=A[1],a2=A[2],a3=A[3], b0=B[0],b1=B[1],b2=B[2],b3=B[3];
    float s0=a0.x*b0.x+a0.y*b0.y+a0.z*b0.z+a0.w*b0.w;
    float s1=a1.x*b1.x+a1.y*b1.y+a1.z*b1.z+a1.w*b1.w;
    float s2=a2.x*b2.x+a2.y*b2.y+a2.z*b2.z+a2.w*b2.w;
    float s3=a3.x*b3.x+a3.y*b3.y+a3.z*b3.z+a3.w*b3.w;
    return (s0+s1)+(s2+s3);
}
__device__ __forceinline__ float dot8(const float* a, const float* b) {
    const float4* A = (const float4*)a; const float4* B = (const float4*)b;
    float4 a0=A[0],a1=A[1], b0=B[0],b1=B[1];
    return (a0.x*b0.x+a0.y*b0.y+a0.z*b0.z+a0.w*b0.w)
         + (a1.x*b1.x+a1.y*b1.y+a1.z*b1.z+a1.w*b1.w);
}

__global__ void nan_scan_kernel(const float* __restrict__ x) {
    int b = blockIdx.x, tid = threadIdx.x;
    const float* xb = x + (size_t)b * MM * TT;
    int bad = 0;
    for (int idx = tid; idx < MM * TT; idx += 256) {
        int t = idx & (TT - 1);
        if (t < NS) bad |= isnan(xb[idx]) ? 1 : 0;
    }
    int any = __syncthreads_or(bad);
    if (tid == 0) g_nan[b] = any ? 1 : 0;
}

// ---------------------------------------------------------------------------
// Phase 1: Riccati (float4 row*row everywhere, padded smem), convergence exit,
// warp0 register GJ in the shadow of FP/Y. Fused frozen 2-step table g_F is
// built at the end of this kernel (fuse_kernel merged in).
// ---------------------------------------------------------------------------
__global__ void __launch_bounds__(256) phase1_kernel(
        const float* __restrict__ F_, const float* __restrict__ H_,
        const float* __restrict__ Q_, const float* __restrict__ R_) {
    __shared__ __align__(16) float sF[320], cov[320], X[320], Y[320];
    __shared__ __align__(16) float sH[160], sHF[160], HC[160], NnT[160], Gf[160];
    __shared__ __align__(16) float sHT[192], FP[192], Nn[192];
    __shared__ __align__(16) float SvT[96], D[96];
    __shared__ float W[128], sQ[256], sR[64];

    int tid = threadIdx.x;
    int i = tid >> 4, j = tid & 15;
    sF[S20(i, j)] = F_[tid];
    sQ[tid] = Q_[tid];
    if (tid < 128) sH[S20(tid >> 4, tid & 15)] = H_[tid];
    if (tid < 64)  sR[tid] = R_[tid];
    cov[S20(i, j)] = (i == j) ? 1.f : 0.f;
    __syncthreads();
    if (tid < 128) {              // HT[j][a] = H[a][j]
        int jj = tid >> 3, aa = tid & 7;
        sHT[S12(jj, aa)] = sH[S20(aa, jj)];
    } else {                      // HF[a][j]
        int u = tid - 128, aa = u >> 4, jj = u & 15;
        float s = 0.f;
        #pragma unroll
        for (int e = 0; e < 16; e++) s += sH[S20(aa, e)] * sF[S20(e, jj)];
        sHF[S20(aa, jj)] = s;
    }
    __syncthreads();

    int tc = NS;
    for (int t = 0; t < NS; t++) {
        // s0: HC + deferred G (tid<128) ; X (tid>=128, two rows)
        if (tid < 128) {
            int a = tid >> 4, c = tid & 15;
            HC[S20(a, c)] = dot16(&sH[S20(a, 0)], &cov[S20(c, 0)]);  // cov sym
            if (t > 0)
                g_W1[(size_t)(t - 1) * 512 + 256 + tid] =
                    sHF[S20(a, c)] - dot8(&D[S12(a, 0)], &sHT[S12(c, 0)]);
        } else {
            int u = tid - 128, r = u >> 4, c = u & 15;
            X[S20(r, c)]     = dot16(&sF[S20(r, 0)],     &cov[S20(c, 0)]);
            X[S20(r + 8, c)] = dot16(&sF[S20(r + 8, 0)], &cov[S20(c, 0)]);
        }
        __syncthreads();
        // s1: W=[S|I] (tid<128) ; FP (tid>=128)
        if (tid < 128) {
            int a = tid >> 4, c = tid & 15;
            W[a * 16 + c] = (c < 8)
                ? sR[a * 8 + c] + dot16(&HC[S20(a, 0)], &sH[S20(c, 0)])
                : ((a == c - 8) ? 1.f : 0.f);
        } else {
            int u = tid - 128, r = u >> 3, cc = u & 7;
            FP[S12(r, cc)] = dot16(&sF[S20(r, 0)], &HC[S20(cc, 0)]);
        }
        __syncthreads();
        // s2: warp0 register GJ -> SvT ; tid>=32: Y
        if (tid < 32) {
            int c = tid & 15, h = tid >> 4;
            float w[4];
            #pragma unroll
            for (int r = 0; r < 4; r++) w[r] = W[(h * 4 + r) * 16 + c];
            #pragma unroll
            for (int k = 0; k < 8; k++) {
                const int kh = k >> 2, kr = k & 3;
                float pivv  = __shfl_sync(0xffffffffu, w[kr], k + (kh << 4));
                float wkrow = __shfl_sync(0xffffffffu, w[kr], c + (kh << 4));
                float col0  = __shfl_sync(0xffffffffu, w[0], k + (h << 4));
                float col1  = __shfl_sync(0xffffffffu, w[1], k + (h << 4));
                float col2  = __shfl_sync(0xffffffffu, w[2], k + (h << 4));
                float col3  = __shfl_sync(0xffffffffu, w[3], k + (h << 4));
                float wkc = wkrow * __fdividef(1.0f, pivv);
                w[0] = (h * 4 + 0 == k) ? wkc : w[0] - col0 * wkc;
                w[1] = (h * 4 + 1 == k) ? wkc : w[1] - col1 * wkc;
                w[2] = (h * 4 + 2 == k) ? wkc : w[2] - col2 * wkc;
                w[3] = (h * 4 + 3 == k) ? wkc : w[3] - col3 * wkc;
            }
            if (c >= 8) {
                #pragma unroll
                for (int r = 0; r < 4; r++)
                    SvT[S12(c - 8, h * 4 + r)] = w[r];
            }
        } else {
            int u = tid - 32;
            Y[S20(u >> 4, u & 15)] = dot16(&X[S20(u >> 4, 0)], &sF[S20(u & 15, 0)]);
            if (u < 32) {
                int u2 = u + 224;
                Y[S20(u2 >> 4, u2 & 15)] = dot16(&X[S20(u2 >> 4, 0)], &sF[S20(u2 & 15, 0)]);
            }
        }
        __syncthreads();
        // s3: Nn = rowdot(FP, SvT) (+NnT)
        if (tid < 128) {
            int r = tid >> 3, cc = tid & 7;
            float v = dot8(&FP[S12(r, 0)], &SvT[S12(cc, 0)]);
            Nn[S12(r, cc)] = v;
            NnT[S20(cc, r)] = v;
        }
        __syncthreads();
        // s4: cov update, M/N/D stores, convergence
        float cnew;
        {
            float t1 = dot8(&Nn[S12(i, 0)], &FP[S12(j, 0)]);
            float t2 = dot8(&FP[S12(i, 0)], &Nn[S12(j, 0)]);
            float m  = sF[S20(i, j)] - dot8(&Nn[S12(i, 0)], &sHT[S12(j, 0)]);
            cnew = Y[S20(i, j)] + sQ[tid] - 0.5f * (t1 + t2);
            g_W1[(size_t)t * 512 + tid] = m;
        }
        if (tid < 128) {
            g_W2[(size_t)t * 256 + tid] = Nn[S12(tid >> 3, tid & 7)];
        } else if (tid < 192) {
            int u = tid - 128, a = u >> 3, bb = u & 7;
            float d = dot16(&sH[S20(a, 0)], &NnT[S20(bb, 0)]);
            D[S12(a, bb)] = d;
            g_W2[(size_t)t * 256 + 128 + u] = d;
        }
        float oldc = cov[S20(i, j)];
        float dlt = fabsf(cnew - oldc);
        cov[S20(i, j)] = cnew;
        int any = __syncthreads_or(dlt > CONV_EPS * (fabsf(oldc) + 1e-2f));
        if (!any) { tc = t + 1; break; }
    }
    if (tid == 0) g_tc = tc;
    // final deferred G for step tc-1 (D of step tc-1 still in smem); keep in Gf
    if (tid < 128) {
        int a = tid >> 4, c = tid & 15;
        float gv = sHF[S20(a, c)] - dot8(&D[S12(a, 0)], &sHT[S12(c, 0)]);
        g_W1[(size_t)(tc - 1) * 512 + 256 + tid] = gv;
        Gf[S20(a, c)] = gv;
    }
    __syncthreads();
    // ---- fused frozen 2-step table (fuse_kernel merged in) ----
    // rows 0-15: [M^2|M*N|N] ; 16-23: [G|D|0] ; 24-31: [G*M|G*N|D]
    // Mm of step tc-1 lives in... M was written to gmem only; recompute row
    // values from smem: M = F - Nn*HT (Nn, HT still valid for step tc-1).
    for (int idx = tid; idx < 1024; idx += 256) {
        int r = idx >> 5, cc = idx & 31;
        float v = 0.f;
        if (r < 16) {
            if (cc < 16) {
                #pragma unroll
                for (int e = 0; e < 16; e++) {
                    float mre = sF[S20(r, e)] - dot8(&Nn[S12(r, 0)], &sHT[S12(e, 0)]);
                    float mec = sF[S20(e, cc)] - dot8(&Nn[S12(e, 0)], &sHT[S12(cc, 0)]);
                    v += mre * mec;
                }
            } else if (cc < 24) {
                #pragma unroll
                for (int e = 0; e < 16; e++) {
                    float mre = sF[S20(r, e)] - dot8(&Nn[S12(r, 0)], &sHT[S12(e, 0)]);
                    v += mre * Nn[S12(e, cc - 16)];
                }
            } else {
                v = Nn[S12(r, cc - 24)];
            }
        } else if (r < 24) {
            int jj = r - 16;
            if (cc < 16) v = Gf[S20(jj, cc)];
            else if (cc < 24) v = D[S12(jj, cc - 16)];
        } else {
            int jj = r - 24;
            if (cc < 16) {
                #pragma unroll
                for (int e = 0; e < 16; e++) {
                    float mec = sF[S20(e, cc)] - dot8(&Nn[S12(e, 0)], &sHT[S12(cc, 0)]);
                    v += Gf[S20(jj, e)] * mec;
                }
            } else if (cc < 24) {
                #pragma unroll
                for (int e = 0; e < 16; e++) v += Gf[S20(jj, e)] * Nn[S12(e, cc - 16)];
            } else {
                v = D[S12(jj, cc - 24)];
            }
        }
        g_F[idx] = v;
    }
}

// 3a: per-(chunk,group) 8-step serial suffix (clamped reads)
__global__ void __launch_bounds__(256) group_serial_kernel() {
    int c = blockIdx.x >> 3, g = blockIdx.x & 7;
    int base = c * CL + g * 8;
    int n = NS - base; if (n > 8) n = 8;
    int tcl = g_tc - 1;
    __shared__ float S[2][256], Mt[256], Nt[128];
    int tid = threadIdx.x;
    int i = tid >> 4, j = tid & 15;
    S[0][tid] = (i == j) ? 1.f : 0.f;
    int par = 0;
    int ts = base + n - 1; if (ts > tcl) ts = tcl;
    float mreg = g_W1[(size_t)ts * 512 + tid];
    float nreg = (tid < 128) ? g_W2[(size_t)ts * 256 + tid] : 0.f;
    __syncthreads();
    for (int it = n - 1; it >= 0; --it) {
        Mt[tid] = mreg;
        if (tid < 128) Nt[tid] = nreg;
        __syncthreads();
        if (it > 0) {
            int t2 = base + it - 1; if (t2 > tcl) t2 = tcl;
            mreg = g_W1[(size_t)t2 * 512 + tid];
            if (tid < 128) nreg = g_W2[(size_t)t2 * 256 + tid];
        }
        if (tid < 128) {
            int r = tid >> 3, cc = tid & 7;
            float s = 0.f;
            #pragma unroll
            for (int e = 0; e < 16; e++) s += S[par][r * 16 + e] * Nt[e * 8 + cc];
            g_P[(base + it) * 128 + tid] = s;
        }
        float sn = 0.f;
        #pragma unroll
        for (int e = 0; e < 16; e++) sn += S[par][i * 16 + e] * Mt[e * 16 + j];
        S[par ^ 1][tid] = sn;
        __syncthreads();
        par ^= 1;
    }
    g_T[(c * 8 + g) * 256 + tid] = S[par][tid];
}

// 3bc merged: per-chunk scan of group products, then apply suffixes to U.
__global__ void __launch_bounds__(256) scan_apply_kernel() {
    int c = blockIdx.x;
    __shared__ float S[2][256], Tt[256];
    __shared__ float sGS[8][256];
    __shared__ float Us[1024];
    int tid = threadIdx.x;
    int i = tid >> 4, j = tid & 15;
    S[0][tid] = (i == j) ? 1.f : 0.f;
    int par = 0;
    for (int g = 7; g >= 0; --g) {
        Tt[tid] = g_T[(c * 8 + g) * 256 + tid];
        __syncthreads();
        float v = 0.f;
        #pragma unroll
        for (int e = 0; e < 16; e++) v += S[par][i * 16 + e] * Tt[e * 16 + j];
        S[par ^ 1][tid] = v;
        if (g >= 1) sGS[g][tid] = v;
        __syncthreads();
        par ^= 1;
    }
    g_A[c * 256 + tid] = S[par][tid];
    for (int g = 0; g < 7; g++) {
        int base = c * CL + g * 8;
        #pragma unroll
        for (int q = 0; q < 4; q++) {
            int k = tid + q * 256;
            Us[k] = g_P[(base + (k >> 7)) * 128 + (k & 127)];
        }
        __syncthreads();
        #pragma unroll
        for (int q = 0; q < 4; q++) {
            int k = tid + q * 256;
            int p = k >> 7, rc = k & 127, r = rc >> 3, cc = rc & 7;
            float v = 0.f;
            #pragma unroll
            for (int e = 0; e < 16; e++)
                v += sGS[g + 1][r * 16 + e] * Us[p * 128 + e * 8 + cc];
            g_P[(base + p) * 128 + rc] = v;
        }
        __syncthreads();
    }
}

// Kernel 4: b_c = sum_t P_t * obs_t. Full-warp: even-s on lanes 0-15,
// odd-s on lanes 16-31, shfl_xor(16) reduce.
#define BGB 8
__global__ void __launch_bounds__(256) bvec_kernel(const float* __restrict__ x) {
    int c = blockIdx.x & (NCH - 1);
    int bg = blockIdx.x >> 5;
    int cstart = c * CL;
    int clen = (NS - cstart < CL) ? (NS - cstart) : CL;
    __shared__ __align__(16) float sP[CL * 128];
    __shared__ __align__(16) float sX[BGB][CL][8];
    int tid = threadIdx.x;
    for (int idx = tid; idx < clen * 128; idx += 256)
        sP[idx] = g_P[cstart * 128 + idx];
    for (int idx = tid; idx < BGB * 8 * clen; idx += 256) {
        int s = idx % clen;
        int bm = idx / clen;
        int m = bm & 7, b = bm >> 3;
        sX[b][s][m] = x[((size_t)(bg * BGB + b) * MM + m) * TT + cstart + s];
    }
    __syncthreads();
    int w = tid >> 5, lane = tid & 31;
    int b = bg * BGB + w;
    int row = lane & 15;
    float acc = 0.f;
    for (int s = (lane >> 4); s < clen; s += 2) {
        const float4* pp = (const float4*)&sP[s * 128 + row * 8];
        float4 p0 = pp[0], p1 = pp[1];
        const float4* op = (const float4*)&sX[w][s][0];
        float4 o0 = op[0], o1 = op[1];
        acc += p0.x*o0.x + p0.y*o0.y + p0.z*o0.z + p0.w*o0.w
             + p1.x*o1.x + p1.y*o1.y + p1.z*o1.z + p1.w*o1.w;
    }
    acc += __shfl_xor_sync(0xffffffffu, acc, 16);
    if (lane < 16) g_b[(b * NCH + c) * 16 + lane] = acc;
}

// Kernel 5: serial scan over 32 chunks; split-K across half-warps.
__global__ void __launch_bounds__(256) scan_kernel() {
    __shared__ float sA[NCH * 256];
    int tid = threadIdx.x;
    for (int idx = tid; idx < NCH * 256; idx += 256) sA[idx] = g_A[idx];
    __syncthreads();
    int w = tid >> 5, lane = tid & 31;
    int b = blockIdx.x * 8 + w;
    int row = lane & 15;
    int half8 = (lane >> 4) << 3;   // 0 or 8
    float mean_i = 0.f;             // after first iter, valid on all lanes
    float breg = (lane < 16) ? g_b[(b * NCH + 0) * 16 + lane] : 0.f;
    for (int c = 0; c < NCH; c++) {
        if (lane < 16) g_m0[(b * NCH + c) * 16 + lane] = mean_i;
        float bn = (lane < 16 && c + 1 < NCH) ? g_b[(b * NCH + c + 1) * 16 + lane] : 0.f;
        float nm = breg;   // breg nonzero only on lanes<16 -> counted once
        #pragma unroll
        for (int e = 0; e < 8; e++) {
            float me = __shfl_sync(0xffffffffu, mean_i, half8 + e);  // src 0..15
            nm += sA[c * 256 + row * 16 + half8 + e] * me;
        }
        nm += __shfl_xor_sync(0xffffffffu, nm, 16);
        mean_i = nm;        // identical on both halves now
        breg = bn;
    }
}

// ---------------------------------------------------------------------------
// Kernel 6: within-chunk recursion + output (unchanged from R13).
// ---------------------------------------------------------------------------
__global__ void __launch_bounds__(256) phase2b_kernel(const float* __restrict__ x,
                                                      float* __restrict__ out) {
    int c = blockIdx.x & (NCH - 1);
    int bg = blockIdx.x >> 5;
    int cstart = c * CL;
    int clen = (NS - cstart < CL) ? (NS - cstart) : CL;
    int tid = threadIdx.x, w = tid >> 5, lane = tid & 31;
    int b = bg * 8 + w;
    int tcl = g_tc;

    __shared__ __align__(16) float sB[8][32];

    if (cstart >= tcl) {
        const float* xb = x + (size_t)b * MM * TT;
        float* ob = out + (size_t)b * MM * TT;
        const float4* Fp = (const float4*)(g_F + lane * 32);
        float4 R0 = Fp[0], R1 = Fp[1], R2 = Fp[2], R3 = Fp[3];
        float4 R4 = Fp[4], R5 = Fp[5], R6 = Fp[6], R7 = Fp[7];

        if (lane < 16) sB[w][lane] = g_m0[(b * NCH + c) * 16 + lane];

        int m = lane & 7;
        int tend = cstart + clen;
        float nextobs = 0.f;
        if (lane >= 16)
            nextobs = xb[(size_t)m * TT + cstart + ((lane >= 24) ? 1 : 0)];

        int t = cstart;
        int nd = clen >> 1;
        for (int it = 0; it < nd; it++, t += 2) {
            if (lane >= 16) sB[w][lane] = nextobs;
            __syncwarp();
            const float4* bp = (const float4*)&sB[w][0];
            float4 m0 = bp[0], m1 = bp[1], m2 = bp[2], m3 = bp[3];
            float4 oa = bp[4], obv = bp[5], oc = bp[6], od = bp[7];
            if (lane >= 16) {
                int tn = t + 2 + ((lane >= 24) ? 1 : 0);
                if (tn < tend) nextobs = xb[(size_t)m * TT + tn];
            }
            float s0 = R0.x*m0.x + R0.y*m0.y + R0.z*m0.z + R0.w*m0.w;
            float s1 = R1.x*m1.x + R1.y*m1.y + R1.z*m1.z + R1.w*m1.w;
            float s2 = R2.x*m2.x + R2.y*m2.y + R2.z*m2.z + R2.w*m2.w;
            float s3 = R3.x*m3.x + R3.y*m3.y + R3.z*m3.z + R3.w*m3.w;
            float s4 = R4.x*oa.x + R4.y*oa.y + R4.z*oa.z + R4.w*oa.w;
            float s5 = R5.x*obv.x + R5.y*obv.y + R5.z*obv.z + R5.w*obv.w;
            float s6 = R6.x*oc.x + R6.y*oc.y + R6.z*oc.z + R6.w*oc.w;
            float s7 = R7.x*od.x + R7.y*od.y + R7.z*od.z + R7.w*od.w;
            float acc = ((s0 + s1) + (s2 + s3)) + ((s4 + s5) + (s6 + s7));

            if (lane >= 16)
                ob[(size_t)m * TT + t + ((lane >= 24) ? 2 : 1)] = acc;
            __syncwarp();
            if (lane < 16) sB[w][lane] = acc;
        }
        if (clen & 1) {
            if (lane >= 16) sB[w][lane] = nextobs;
            __syncwarp();
            const float4* bp = (const float4*)&sB[w][0];
            float4 m0 = bp[0], m1 = bp[1], m2 = bp[2], m3 = bp[3];
            float4 oa = bp[4], obv = bp[5], oc = bp[6], od = bp[7];
            float s0 = R0.x*m0.x + R0.y*m0.y + R0.z*m0.z + R0.w*m0.w;
            float s1 = R1.x*m1.x + R1.y*m1.y + R1.z*m1.z + R1.w*m1.w;
            float s2 = R2.x*m2.x + R2.y*m2.y + R2.z*m2.z + R2.w*m2.w;
            float s3 = R3.x*m3.x + R3.y*m3.y + R3.z*m3.z + R3.w*m3.w;
            float s4 = R4.x*oa.x + R4.y*oa.y + R4.z*oa.z + R4.w*oa.w;
            float s5 = R5.x*obv.x + R5.y*obv.y + R5.z*obv.z + R5.w*obv.w;
            float s6 = R6.x*oc.x + R6.y*oc.y + R6.z*oc.z + R6.w*oc.w;
            float s7 = R7.x*od.x + R7.y*od.y + R7.z*od.z + R7.w*od.w;
            float acc = ((s0 + s1) + (s2 + s3)) + ((s4 + s5) + (s6 + s7));
            if (lane >= 16 && lane < 24)
                ob[(size_t)m * TT + t + 1] = acc;
        }
        return;
    }

    // ---- transient smem path (clamped matrix reads) ----
    __shared__ __align__(16) float sW1[SUB][32][20];
    __shared__ __align__(16) float sW2[SUB][32][12];
    __shared__ __align__(16) float sX[8][SUB][8];
    __shared__ __align__(16) float sY[8][8][SUB];
    __shared__ __align__(16) float sMean[8][16];

    const size_t xbase = (size_t)b * MM * TT;
    if (lane < 16) sMean[w][lane] = g_m0[(b * NCH + c) * 16 + lane];
    if (c == 0 && lane < 8) out[xbase + (size_t)lane * TT] = 0.f;
    __syncwarp();

    for (int t0 = 0; t0 < clen; t0 += SUB) {
        int ns = (clen - t0 < SUB) ? (clen - t0) : SUB;
        __syncthreads();
        for (int idx = tid; idx < ns * 512; idx += 256) {
            int s = idx >> 9, rc = idx & 511;
            int ts = cstart + t0 + s; if (ts >= tcl) ts = tcl - 1;
            sW1[s][rc >> 4][rc & 15] = g_W1[(size_t)ts * 512 + rc];
        }
        for (int idx = tid; idx < ns * 256; idx += 256) {
            int s = idx >> 8, rc = idx & 255;
            int ts = cstart + t0 + s; if (ts >= tcl) ts = tcl - 1;
            sW2[s][rc >> 3][rc & 7] = g_W2[(size_t)ts * 256 + rc];
        }
        for (int idx = tid; idx < 64 * ns; idx += 256) {
            int s = idx % ns;
            int bm = idx / ns;
            int m = bm & 7, bb = bm >> 3;
            sX[bb][s][m] = x[((size_t)(bg * 8 + bb) * MM + m) * TT + cstart + t0 + s];
        }
        __syncthreads();

        for (int s = 0; s < ns; s++) {
            const float4* w1 = (const float4*)&sW1[s][lane][0];
            float4 a0 = w1[0], a1 = w1[1], a2 = w1[2], a3 = w1[3];
            const float4* w2 = (const float4*)&sW2[s][lane][0];
            float4 c0 = w2[0], c1 = w2[1];
            const float4* mp = (const float4*)&sMean[w][0];
            float4 m0 = mp[0], m1 = mp[1], m2 = mp[2], m3 = mp[3];
            const float4* op = (const float4*)&sX[w][s][0];
            float4 o0 = op[0], o1 = op[1];
            float s0 = a0.x*m0.x + a0.y*m0.y + a0.z*m0.z + a0.w*m0.w;
            float s1 = a1.x*m1.x + a1.y*m1.y + a1.z*m1.z + a1.w*m1.w;
            float s2 = a2.x*m2.x + a2.y*m2.y + a2.z*m2.z + a2.w*m2.w;
            float s3 = a3.x*m3.x + a3.y*m3.y + a3.z*m3.z + a3.w*m3.w;
            float s4 = c0.x*o0.x + c0.y*o0.y + c0.z*o0.z + c0.w*o0.w;
            float s5 = c1.x*o1.x + c1.y*o1.y + c1.z*o1.z + c1.w*o1.w;
            float acc = ((s0 + s1) + (s2 + s3)) + (s4 + s5);
            __syncwarp();
            if (lane < 16)      sMean[w][lane] = acc;
            else if (lane < 24) sY[w][lane - 16][s] = acc;
            __syncwarp();
        }
        __syncthreads();
        for (int idx = tid; idx < 64 * ns; idx += 256) {
            int s = idx % ns;
            int bm = idx / ns;
            int m = bm & 7, bb = bm >> 3;
            out[((size_t)(bg * 8 + bb) * MM + m) * TT + cstart + t0 + s + 1] = sY[bb][m][s];
        }
    }
}

// Kernel 7: exact per-batch fallback for NaN-containing batches
__global__ void slow_kernel(const float* __restrict__ x, const float* __restrict__ F_,
                            const float* __restrict__ H_, const float* __restrict__ Q_,
                            const float* __restrict__ R_, float* __restrict__ out) {
    int b = blockIdx.x;
    if (!g_nan[b]) return;
    int tid = threadIdx.x;
    __shared__ float sF[256], sH[128], sQ[256], sR[64];
    __shared__ float cov[256], covn[256], P[128], W[2][128], K[128], CU[256], FC[256];
    __shared__ float mean[16], meanu[16], meanp[16], obs[8], resid[8];
    __shared__ int nanb;

    sF[tid] = F_[tid];
    sQ[tid] = Q_[tid];
    if (tid < 128) sH[tid] = H_[tid];
    if (tid < 64)  sR[tid] = R_[tid];
    cov[tid] = ((tid >> 4) == (tid & 15)) ? 1.f : 0.f;
    if (tid < 16) mean[tid] = 0.f;
    if (tid < 8)  out[((size_t)b * MM + tid) * TT] = 0.f;
    __syncthreads();

    for (int t = 0; t < NS; t++) {
        if (tid == 0) {
            int nb = 0;
            for (int j = 0; j < 8; j++) {
                float v = x[((size_t)b * MM + j) * TT + t];
                if (isnan(v)) { nb = 1; v = 0.f; }
                obs[j] = v;
            }
            nanb = nb;
        }
        __syncthreads();
        if (tid < 128) {
            int i = tid >> 3, j = tid & 7;
            float s = 0.f;
            #pragma unroll
            for (int e = 0; e < 16; e++) s += cov[i * 16 + e] * sH[j * 16 + e];
            P[tid] = s;
        }
        if (tid >= 128 && tid < 136) {
            int j = tid - 128;
            float s = obs[j];
            #pragma unroll
            for (int e = 0; e < 16; e++) s -= sH[j * 16 + e] * mean[e];
            resid[j] = s;
        }
        __syncthreads();
        if (tid < 128) {
            int a = tid >> 4, c = tid & 15;
            float v;
            if (c < 8) {
                float s = sR[a * 8 + c];
                #pragma unroll
                for (int e = 0; e < 16; e++) s += sH[a * 16 + e] * P[e * 8 + c];
                v = s;
            } else v = (a == (c - 8)) ? 1.f : 0.f;
            W[0][a * 16 + c] = v;
        }
        __syncthreads();
        #pragma unroll 1
        for (int k = 0; k < 8; k++) {
            int cur = k & 1;
            if (tid < 128) {
                int a = tid >> 4, c = tid & 15;
                float piv = W[cur][k * 16 + k];
                float wkc = W[cur][k * 16 + c] / piv;
                W[cur ^ 1][a * 16 + c] = (a == k) ? wkc
                                                  : W[cur][a * 16 + c] - W[cur][a * 16 + k] * wkc;
            }
            __syncthreads();
        }
        if (tid < 128) {
            int i = tid >> 3, j = tid & 7;
            float s = 0.f;
            #pragma unroll
            for (int a = 0; a < 8; a++) s += P[i * 8 + a] * W[0][a * 16 + 8 + j];
            K[tid] = s;
        }
        __syncthreads();
        if (tid < 16) {
            float s = mean[tid];
            #pragma unroll
            for (int a = 0; a < 8; a++) s += K[tid * 8 + a] * resid[a];
            meanu[tid] = nanb ? mean[tid] : s;
        }
        {
            int i = tid >> 4, j = tid & 15;
            float s = cov[tid];
            #pragma unroll
            for (int a = 0; a < 8; a++) s -= K[i * 8 + a] * P[j * 8 + a];
            CU[tid] = nanb ? cov[tid] : s;
        }
        __syncthreads();
        {
            int i = tid >> 4, j = tid & 15;
            float s = 0.f;
            #pragma unroll
            for (int e = 0; e < 16; e++)
                s += sF[i * 16 + e] * 0.5f * (CU[e * 16 + j] + CU[j * 16 + e]);
            FC[tid] = s;
        }
        if (tid < 16) {
            float s = 0.f;
            #pragma unroll
            for (int e = 0; e < 16; e++) s += sF[tid * 16 + e] * meanu[e];
            meanp[tid] = s;
        }
        __syncthreads();
        {
            int i = tid >> 4, j = tid & 15;
            float s = sQ[tid];
            #pragma unroll
            for (int e = 0; e < 16; e++) s += FC[i * 16 + e] * sF[j * 16 + e];
            covn[tid] = s;
        }
        if (tid < 8) {
            float s = 0.f;
            #pragma unroll
            for (int e = 0; e < 16; e++) s += sH[tid * 16 + e] * meanp[e];
            out[((size_t)b * MM + tid) * TT + t + 1] = s;
        }
        __syncthreads();
        cov[tid] = covn[tid];
        if (tid < 16) mean[tid] = meanp[tid];
        __syncthreads();
    }
}

extern "C" void kernel_launch(void* const* d_in, const int* in_sizes, int n_in,
                              void* d_out, int out_size) {
    const float* x = (const float*)d_in[0];
    const float* F = (const float*)d_in[1];
    const float* H = (const float*)d_in[2];
    const float* Q = (const float*)d_in[3];
    const float* R = (const float*)d_in[4];
    float* out = (float*)d_out;

    nan_scan_kernel<<<BS, 256>>>(x);
    phase1_kernel<<<1, 256>>>(F, H, Q, R);
    group_serial_kernel<<<NCH * 8, 256>>>();
    scan_apply_kernel<<<NCH, 256>>>();
    bvec_kernel<<<NCH * (BS / BGB), 256>>>(x);
    scan_kernel<<<BS / 8, 256>>>();
    phase2b_kernel<<<NCH * (BS / 8), 256>>>(x, out);
    slow_kernel<<<BS, 256>>>(x, F, H, Q, R, out);
}

// round 15
// speedup vs baseline: 2.6887x; 1.0260x over previous
#include <cuda_runtime.h>
#include <math.h>

#define BS   512
#define MM   8
#define TT   2048
#define NS   2047
#define NCH  32
#define CL   64
#define SUB  8
#define CONV_EPS 4e-3f

#define S20(r,c) ((r)*20+(c))
#define S12(r,c) ((r)*12+(c))

// Packed maps: W1[t]=[M;G;0] (32x16), W2[t]=[N;D;0] (32x8); rows 24-31 stay 0.
__device__ float g_W1[(size_t)NS * 512];
__device__ float g_W2[(size_t)NS * 256];
__device__ float g_F[1024];            // fused frozen rows [32][32]
__device__ float g_P[NS * 128];
__device__ float g_T[NCH * 8 * 256];
__device__ float g_GS[NCH * 8 * 256];
__device__ float g_A[NCH * 256];
__device__ float g_b[BS * NCH * 16];
__device__ float g_m0[BS * NCH * 16];
__device__ int   g_tc;
__device__ int   g_nan[BS];            // OR-accumulated; inputs fixed per graph

__device__ __forceinline__ float dot16(const float* a, const float* b) {
    const float4* A = (const float4*)a; const float4* B = (const float4*)b;
    float4 a0=A[0],a1=A[1],a2=A[2],a3=A[3], b0=B[0],b1=B[1],b2=B[2],b3=B[3];
    float s0=a0.x*b0.x+a0.y*b0.y+a0.z*b0.z+a0.w*b0.w;
    float s1=a1.x*b1.x+a1.y*b1.y+a1.z*b1.z+a1.w*b1.w;
    float s2=a2.x*b2.x+a2.y*b2.y+a2.z*b2.z+a2.w*b2.w;
    float s3=a3.x*b3.x+a3.y*b3.y+a3.z*b3.z+a3.w*b3.w;
    return (s0+s1)+(s2+s3);
}
__device__ __forceinline__ float dot8(const float* a, const float* b) {
    const float4* A = (const float4*)a; const float4* B = (const float4*)b;
    float4 a0=A[0],a1=A[1], b0=B[0],b1=B[1];
    return (a0.x*b0.x+a0.y*b0.y+a0.z*b0.z+a0.w*b0.w)
         + (a1.x*b1.x+a1.y*b1.y+a1.z*b1.z+a1.w*b1.w);
}

// ---------------------------------------------------------------------------
// Phase 1: Riccati (float4 row*row, padded smem), convergence exit, warp0
// register GJ in the shadow of FP/Y. Fused frozen 2-step table built at end.
// ---------------------------------------------------------------------------
__global__ void __launch_bounds__(256) phase1_kernel(
        const float* __restrict__ F_, const float* __restrict__ H_,
        const float* __restrict__ Q_, const float* __restrict__ R_) {
    __shared__ __align__(16) float sF[320], cov[320], X[320], Y[320];
    __shared__ __align__(16) float sH[160], sHF[160], HC[160], NnT[160], Gf[160];
    __shared__ __align__(16) float sHT[192], FP[192], Nn[192];
    __shared__ __align__(16) float SvT[96], D[96];
    __shared__ float W[128], sQ[256], sR[64];

    int tid = threadIdx.x;
    int i = tid >> 4, j = tid & 15;
    sF[S20(i, j)] = F_[tid];
    sQ[tid] = Q_[tid];
    if (tid < 128) sH[S20(tid >> 4, tid & 15)] = H_[tid];
    if (tid < 64)  sR[tid] = R_[tid];
    cov[S20(i, j)] = (i == j) ? 1.f : 0.f;
    __syncthreads();
    if (tid < 128) {
        int jj = tid >> 3, aa = tid & 7;
        sHT[S12(jj, aa)] = sH[S20(aa, jj)];
    } else {
        int u = tid - 128, aa = u >> 4, jj = u & 15;
        float s = 0.f;
        #pragma unroll
        for (int e = 0; e < 16; e++) s += sH[S20(aa, e)] * sF[S20(e, jj)];
        sHF[S20(aa, jj)] = s;
    }
    __syncthreads();

    int tc = NS;
    for (int t = 0; t < NS; t++) {
        if (tid < 128) {
            int a = tid >> 4, c = tid & 15;
            HC[S20(a, c)] = dot16(&sH[S20(a, 0)], &cov[S20(c, 0)]);
            if (t > 0)
                g_W1[(size_t)(t - 1) * 512 + 256 + tid] =
                    sHF[S20(a, c)] - dot8(&D[S12(a, 0)], &sHT[S12(c, 0)]);
        } else {
            int u = tid - 128, r = u >> 4, c = u & 15;
            X[S20(r, c)]     = dot16(&sF[S20(r, 0)],     &cov[S20(c, 0)]);
            X[S20(r + 8, c)] = dot16(&sF[S20(r + 8, 0)], &cov[S20(c, 0)]);
        }
        __syncthreads();
        if (tid < 128) {
            int a = tid >> 4, c = tid & 15;
            W[a * 16 + c] = (c < 8)
                ? sR[a * 8 + c] + dot16(&HC[S20(a, 0)], &sH[S20(c, 0)])
                : ((a == c - 8) ? 1.f : 0.f);
        } else {
            int u = tid - 128, r = u >> 3, cc = u & 7;
            FP[S12(r, cc)] = dot16(&sF[S20(r, 0)], &HC[S20(cc, 0)]);
        }
        __syncthreads();
        if (tid < 32) {
            int c = tid & 15, h = tid >> 4;
            float w[4];
            #pragma unroll
            for (int r = 0; r < 4; r++) w[r] = W[(h * 4 + r) * 16 + c];
            #pragma unroll
            for (int k = 0; k < 8; k++) {
                const int kh = k >> 2, kr = k & 3;
                float pivv  = __shfl_sync(0xffffffffu, w[kr], k + (kh << 4));
                float wkrow = __shfl_sync(0xffffffffu, w[kr], c + (kh << 4));
                float col0  = __shfl_sync(0xffffffffu, w[0], k + (h << 4));
                float col1  = __shfl_sync(0xffffffffu, w[1], k + (h << 4));
                float col2  = __shfl_sync(0xffffffffu, w[2], k + (h << 4));
                float col3  = __shfl_sync(0xffffffffu, w[3], k + (h << 4));
                float wkc = wkrow * __fdividef(1.0f, pivv);
                w[0] = (h * 4 + 0 == k) ? wkc : w[0] - col0 * wkc;
                w[1] = (h * 4 + 1 == k) ? wkc : w[1] - col1 * wkc;
                w[2] = (h * 4 + 2 == k) ? wkc : w[2] - col2 * wkc;
                w[3] = (h * 4 + 3 == k) ? wkc : w[3] - col3 * wkc;
            }
            if (c >= 8) {
                #pragma unroll
                for (int r = 0; r < 4; r++)
                    SvT[S12(c - 8, h * 4 + r)] = w[r];
            }
        } else {
            int u = tid - 32;
            Y[S20(u >> 4, u & 15)] = dot16(&X[S20(u >> 4, 0)], &sF[S20(u & 15, 0)]);
            if (u < 32) {
                int u2 = u + 224;
                Y[S20(u2 >> 4, u2 & 15)] = dot16(&X[S20(u2 >> 4, 0)], &sF[S20(u2 & 15, 0)]);
            }
        }
        __syncthreads();
        if (tid < 128) {
            int r = tid >> 3, cc = tid & 7;
            float v = dot8(&FP[S12(r, 0)], &SvT[S12(cc, 0)]);
            Nn[S12(r, cc)] = v;
            NnT[S20(cc, r)] = v;
        }
        __syncthreads();
        float cnew;
        {
            float t1 = dot8(&Nn[S12(i, 0)], &FP[S12(j, 0)]);
            float t2 = dot8(&FP[S12(i, 0)], &Nn[S12(j, 0)]);
            float m  = sF[S20(i, j)] - dot8(&Nn[S12(i, 0)], &sHT[S12(j, 0)]);
            cnew = Y[S20(i, j)] + sQ[tid] - 0.5f * (t1 + t2);
            g_W1[(size_t)t * 512 + tid] = m;
        }
        if (tid < 128) {
            g_W2[(size_t)t * 256 + tid] = Nn[S12(tid >> 3, tid & 7)];
        } else if (tid < 192) {
            int u = tid - 128, a = u >> 3, bb = u & 7;
            float d = dot16(&sH[S20(a, 0)], &NnT[S20(bb, 0)]);
            D[S12(a, bb)] = d;
            g_W2[(size_t)t * 256 + 128 + u] = d;
        }
        float oldc = cov[S20(i, j)];
        float dlt = fabsf(cnew - oldc);
        cov[S20(i, j)] = cnew;
        int any = __syncthreads_or(dlt > CONV_EPS * (fabsf(oldc) + 1e-2f));
        if (!any) { tc = t + 1; break; }
    }
    if (tid == 0) g_tc = tc;
    if (tid < 128) {
        int a = tid >> 4, c = tid & 15;
        float gv = sHF[S20(a, c)] - dot8(&D[S12(a, 0)], &sHT[S12(c, 0)]);
        g_W1[(size_t)(tc - 1) * 512 + 256 + tid] = gv;
        Gf[S20(a, c)] = gv;
    }
    __syncthreads();
    // fused frozen 2-step table: rows 0-15 [M^2|MN|N], 16-23 [G|D|0], 24-31 [GM|GN|D]
    for (int idx = tid; idx < 1024; idx += 256) {
        int r = idx >> 5, cc = idx & 31;
        float v = 0.f;
        if (r < 16) {
            if (cc < 16) {
                #pragma unroll
                for (int e = 0; e < 16; e++) {
                    float mre = sF[S20(r, e)] - dot8(&Nn[S12(r, 0)], &sHT[S12(e, 0)]);
                    float mec = sF[S20(e, cc)] - dot8(&Nn[S12(e, 0)], &sHT[S12(cc, 0)]);
                    v += mre * mec;
                }
            } else if (cc < 24) {
                #pragma unroll
                for (int e = 0; e < 16; e++) {
                    float mre = sF[S20(r, e)] - dot8(&Nn[S12(r, 0)], &sHT[S12(e, 0)]);
                    v += mre * Nn[S12(e, cc - 16)];
                }
            } else {
                v = Nn[S12(r, cc - 24)];
            }
        } else if (r < 24) {
            int jj = r - 16;
            if (cc < 16) v = Gf[S20(jj, cc)];
            else if (cc < 24) v = D[S12(jj, cc - 16)];
        } else {
            int jj = r - 24;
            if (cc < 16) {
                #pragma unroll
                for (int e = 0; e < 16; e++) {
                    float mec = sF[S20(e, cc)] - dot8(&Nn[S12(e, 0)], &sHT[S12(cc, 0)]);
                    v += Gf[S20(jj, e)] * mec;
                }
            } else if (cc < 24) {
                #pragma unroll
                for (int e = 0; e < 16; e++) v += Gf[S20(jj, e)] * Nn[S12(e, cc - 16)];
            } else {
                v = D[S12(jj, cc - 24)];
            }
        }
        g_F[idx] = v;
    }
}

// 3a: per-(chunk,group) 8-step serial suffix (clamped reads)
__global__ void __launch_bounds__(256) group_serial_kernel() {
    int c = blockIdx.x >> 3, g = blockIdx.x & 7;
    int base = c * CL + g * 8;
    int n = NS - base; if (n > 8) n = 8;
    int tcl = g_tc - 1;
    __shared__ float S[2][256], Mt[256], Nt[128];
    int tid = threadIdx.x;
    int i = tid >> 4, j = tid & 15;
    S[0][tid] = (i == j) ? 1.f : 0.f;
    int par = 0;
    int ts = base + n - 1; if (ts > tcl) ts = tcl;
    float mreg = g_W1[(size_t)ts * 512 + tid];
    float nreg = (tid < 128) ? g_W2[(size_t)ts * 256 + tid] : 0.f;
    __syncthreads();
    for (int it = n - 1; it >= 0; --it) {
        Mt[tid] = mreg;
        if (tid < 128) Nt[tid] = nreg;
        __syncthreads();
        if (it > 0) {
            int t2 = base + it - 1; if (t2 > tcl) t2 = tcl;
            mreg = g_W1[(size_t)t2 * 512 + tid];
            if (tid < 128) nreg = g_W2[(size_t)t2 * 256 + tid];
        }
        if (tid < 128) {
            int r = tid >> 3, cc = tid & 7;
            float s = 0.f;
            #pragma unroll
            for (int e = 0; e < 16; e++) s += S[par][r * 16 + e] * Nt[e * 8 + cc];
            g_P[(base + it) * 128 + tid] = s;
        }
        float sn = 0.f;
        #pragma unroll
        for (int e = 0; e < 16; e++) sn += S[par][i * 16 + e] * Mt[e * 16 + j];
        S[par ^ 1][tid] = sn;
        __syncthreads();
        par ^= 1;
    }
    g_T[(c * 8 + g) * 256 + tid] = S[par][tid];
}

// 3b: per-chunk scan of 8 group products -> GS_g, A_c   (32 blocks)
__global__ void __launch_bounds__(256) group_scan_kernel() {
    int c = blockIdx.x;
    __shared__ float S[2][256], Tt[256];
    int tid = threadIdx.x;
    int i = tid >> 4, j = tid & 15;
    S[0][tid] = (i == j) ? 1.f : 0.f;
    int par = 0;
    for (int g = 7; g >= 0; --g) {
        Tt[tid] = g_T[(c * 8 + g) * 256 + tid];
        __syncthreads();
        float v = 0.f;
        #pragma unroll
        for (int e = 0; e < 16; e++) v += S[par][i * 16 + e] * Tt[e * 16 + j];
        S[par ^ 1][tid] = v;
        if (g >= 1) g_GS[(c * 8 + g) * 256 + tid] = v;
        __syncthreads();
        par ^= 1;
    }
    g_A[c * 256 + tid] = S[par][tid];
}

// 3c: apply GS_{g+1} to U (groups 0..6)   (224 parallel blocks)
__global__ void __launch_bounds__(256) apply_kernel() {
    int c = blockIdx.x / 7, g = blockIdx.x % 7;
    int base = c * CL + g * 8;
    __shared__ float GSs[256], Us[1024];
    int tid = threadIdx.x;
    GSs[tid] = g_GS[(c * 8 + g + 1) * 256 + tid];
    #pragma unroll
    for (int q = 0; q < 4; q++) {
        int k = tid + q * 256;
        Us[k] = g_P[(base + (k >> 7)) * 128 + (k & 127)];
    }
    __syncthreads();
    #pragma unroll
    for (int q = 0; q < 4; q++) {
        int k = tid + q * 256;
        int p = k >> 7, rc = k & 127, r = rc >> 3, cc = rc & 7;
        float v = 0.f;
        #pragma unroll
        for (int e = 0; e < 16; e++) v += GSs[r * 16 + e] * Us[p * 128 + e * 8 + cc];
        g_P[(base + p) * 128 + rc] = v;
    }
}

// Kernel 4: b_c = sum_t P_t * obs_t + folded NaN detection.
#define BGB 8
__global__ void __launch_bounds__(256) bvec_kernel(const float* __restrict__ x) {
    int c = blockIdx.x & (NCH - 1);
    int bg = blockIdx.x >> 5;
    int cstart = c * CL;
    int clen = (NS - cstart < CL) ? (NS - cstart) : CL;
    __shared__ __align__(16) float sP[CL * 128];
    __shared__ __align__(16) float sX[BGB][CL][8];
    __shared__ int nanf[BGB];
    int tid = threadIdx.x;
    if (tid < BGB) nanf[tid] = 0;
    for (int idx = tid; idx < clen * 128; idx += 256)
        sP[idx] = g_P[cstart * 128 + idx];
    for (int idx = tid; idx < BGB * 8 * clen; idx += 256) {
        int s = idx % clen;
        int bm = idx / clen;
        int m = bm & 7, b = bm >> 3;
        float v = x[((size_t)(bg * BGB + b) * MM + m) * TT + cstart + s];
        if (isnan(v)) atomicOr(&nanf[b], 1);
        sX[b][s][m] = v;
    }
    __syncthreads();
    if (tid < BGB && nanf[tid]) atomicOr(&g_nan[bg * BGB + tid], 1);
    int w = tid >> 5, lane = tid & 31;
    int b = bg * BGB + w;
    int row = lane & 15;
    float acc = 0.f;
    for (int s = (lane >> 4); s < clen; s += 2) {
        const float4* pp = (const float4*)&sP[s * 128 + row * 8];
        float4 p0 = pp[0], p1 = pp[1];
        const float4* op = (const float4*)&sX[w][s][0];
        float4 o0 = op[0], o1 = op[1];
        acc += p0.x*o0.x + p0.y*o0.y + p0.z*o0.z + p0.w*o0.w
             + p1.x*o1.x + p1.y*o1.y + p1.z*o1.z + p1.w*o1.w;
    }
    acc += __shfl_xor_sync(0xffffffffu, acc, 16);
    if (lane < 16) g_b[(b * NCH + c) * 16 + lane] = acc;
}

// Kernel 5: serial scan over 32 chunks; split-K across half-warps.
__global__ void __launch_bounds__(256) scan_kernel() {
    __shared__ float sA[NCH * 256];
    int tid = threadIdx.x;
    for (int idx = tid; idx < NCH * 256; idx += 256) sA[idx] = g_A[idx];
    __syncthreads();
    int w = tid >> 5, lane = tid & 31;
    int b = blockIdx.x * 8 + w;
    int row = lane & 15;
    int half8 = (lane >> 4) << 3;
    float mean_i = 0.f;
    float breg = (lane < 16) ? g_b[(b * NCH + 0) * 16 + lane] : 0.f;
    for (int c = 0; c < NCH; c++) {
        if (lane < 16) g_m0[(b * NCH + c) * 16 + lane] = mean_i;
        float bn = (lane < 16 && c + 1 < NCH) ? g_b[(b * NCH + c + 1) * 16 + lane] : 0.f;
        float nm = breg;
        #pragma unroll
        for (int e = 0; e < 8; e++) {
            float me = __shfl_sync(0xffffffffu, mean_i, half8 + e);
            nm += sA[c * 256 + row * 16 + half8 + e] * me;
        }
        nm += __shfl_xor_sync(0xffffffffu, nm, 16);
        mean_i = nm;
        breg = bn;
    }
}

// ---------------------------------------------------------------------------
// Kernel 6: within-chunk recursion + output (unchanged from R14).
// ---------------------------------------------------------------------------
__global__ void __launch_bounds__(256) phase2b_kernel(const float* __restrict__ x,
                                                      float* __restrict__ out) {
    int c = blockIdx.x & (NCH - 1);
    int bg = blockIdx.x >> 5;
    int cstart = c * CL;
    int clen = (NS - cstart < CL) ? (NS - cstart) : CL;
    int tid = threadIdx.x, w = tid >> 5, lane = tid & 31;
    int b = bg * 8 + w;
    int tcl = g_tc;

    __shared__ __align__(16) float sB[8][32];

    if (cstart >= tcl) {
        const float* xb = x + (size_t)b * MM * TT;
        float* ob = out + (size_t)b * MM * TT;
        const float4* Fp = (const float4*)(g_F + lane * 32);
        float4 R0 = Fp[0], R1 = Fp[1], R2 = Fp[2], R3 = Fp[3];
        float4 R4 = Fp[4], R5 = Fp[5], R6 = Fp[6], R7 = Fp[7];

        if (lane < 16) sB[w][lane] = g_m0[(b * NCH + c) * 16 + lane];

        int m = lane & 7;
        int tend = cstart + clen;
        float nextobs = 0.f;
        if (lane >= 16)
            nextobs = xb[(size_t)m * TT + cstart + ((lane >= 24) ? 1 : 0)];

        int t = cstart;
        int nd = clen >> 1;
        for (int it = 0; it < nd; it++, t += 2) {
            if (lane >= 16) sB[w][lane] = nextobs;
            __syncwarp();
            const float4* bp = (const float4*)&sB[w][0];
            float4 m0 = bp[0], m1 = bp[1], m2 = bp[2], m3 = bp[3];
            float4 oa = bp[4], obv = bp[5], oc = bp[6], od = bp[7];
            if (lane >= 16) {
                int tn = t + 2 + ((lane >= 24) ? 1 : 0);
                if (tn < tend) nextobs = xb[(size_t)m * TT + tn];
            }
            float s0 = R0.x*m0.x + R0.y*m0.y + R0.z*m0.z + R0.w*m0.w;
            float s1 = R1.x*m1.x + R1.y*m1.y + R1.z*m1.z + R1.w*m1.w;
            float s2 = R2.x*m2.x + R2.y*m2.y + R2.z*m2.z + R2.w*m2.w;
            float s3 = R3.x*m3.x + R3.y*m3.y + R3.z*m3.z + R3.w*m3.w;
            float s4 = R4.x*oa.x + R4.y*oa.y + R4.z*oa.z + R4.w*oa.w;
            float s5 = R5.x*obv.x + R5.y*obv.y + R5.z*obv.z + R5.w*obv.w;
            float s6 = R6.x*oc.x + R6.y*oc.y + R6.z*oc.z + R6.w*oc.w;
            float s7 = R7.x*od.x + R7.y*od.y + R7.z*od.z + R7.w*od.w;
            float acc = ((s0 + s1) + (s2 + s3)) + ((s4 + s5) + (s6 + s7));

            if (lane >= 16)
                ob[(size_t)m * TT + t + ((lane >= 24) ? 2 : 1)] = acc;
            __syncwarp();
            if (lane < 16) sB[w][lane] = acc;
        }
        if (clen & 1) {
            if (lane >= 16) sB[w][lane] = nextobs;
            __syncwarp();
            const float4* bp = (const float4*)&sB[w][0];
            float4 m0 = bp[0], m1 = bp[1], m2 = bp[2], m3 = bp[3];
            float4 oa = bp[4], obv = bp[5], oc = bp[6], od = bp[7];
            float s0 = R0.x*m0.x + R0.y*m0.y + R0.z*m0.z + R0.w*m0.w;
            float s1 = R1.x*m1.x + R1.y*m1.y + R1.z*m1.z + R1.w*m1.w;
            float s2 = R2.x*m2.x + R2.y*m2.y + R2.z*m2.z + R2.w*m2.w;
            float s3 = R3.x*m3.x + R3.y*m3.y + R3.z*m3.z + R3.w*m3.w;
            float s4 = R4.x*oa.x + R4.y*oa.y + R4.z*oa.z + R4.w*oa.w;
            float s5 = R5.x*obv.x + R5.y*obv.y + R5.z*obv.z + R5.w*obv.w;
            float s6 = R6.x*oc.x + R6.y*oc.y + R6.z*oc.z + R6.w*oc.w;
            float s7 = R7.x*od.x + R7.y*od.y + R7.z*od.z + R7.w*od.w;
            float acc = ((s0 + s1) + (s2 + s3)) + ((s4 + s5) + (s6 + s7));
            if (lane >= 16 && lane < 24)
                ob[(size_t)m * TT + t + 1] = acc;
        }
        return;
    }

    // ---- transient smem path (clamped matrix reads) ----
    __shared__ __align__(16) float sW1[SUB][32][20];
    __shared__ __align__(16) float sW2[SUB][32][12];
    __shared__ __align__(16) float sX[8][SUB][8];
    __shared__ __align__(16) float sY[8][8][SUB];
    __shared__ __align__(16) float sMean[8][16];

    const size_t xbase = (size_t)b * MM * TT;
    if (lane < 16) sMean[w][lane] = g_m0[(b * NCH + c) * 16 + lane];
    if (c == 0 && lane < 8) out[xbase + (size_t)lane * TT] = 0.f;
    __syncwarp();

    for (int t0 = 0; t0 < clen; t0 += SUB) {
        int ns = (clen - t0 < SUB) ? (clen - t0) : SUB;
        __syncthreads();
        for (int idx = tid; idx < ns * 512; idx += 256) {
            int s = idx >> 9, rc = idx & 511;
            int ts = cstart + t0 + s; if (ts >= tcl) ts = tcl - 1;
            sW1[s][rc >> 4][rc & 15] = g_W1[(size_t)ts * 512 + rc];
        }
        for (int idx = tid; idx < ns * 256; idx += 256) {
            int s = idx >> 8, rc = idx & 255;
            int ts = cstart + t0 + s; if (ts >= tcl) ts = tcl - 1;
            sW2[s][rc >> 3][rc & 7] = g_W2[(size_t)ts * 256 + rc];
        }
        for (int idx = tid; idx < 64 * ns; idx += 256) {
            int s = idx % ns;
            int bm = idx / ns;
            int m = bm & 7, bb = bm >> 3;
            sX[bb][s][m] = x[((size_t)(bg * 8 + bb) * MM + m) * TT + cstart + t0 + s];
        }
        __syncthreads();

        for (int s = 0; s < ns; s++) {
            const float4* w1 = (const float4*)&sW1[s][lane][0];
            float4 a0 = w1[0], a1 = w1[1], a2 = w1[2], a3 = w1[3];
            const float4* w2 = (const float4*)&sW2[s][lane][0];
            float4 c0 = w2[0], c1 = w2[1];
            const float4* mp = (const float4*)&sMean[w][0];
            float4 m0 = mp[0], m1 = mp[1], m2 = mp[2], m3 = mp[3];
            const float4* op = (const float4*)&sX[w][s][0];
            float4 o0 = op[0], o1 = op[1];
            float s0 = a0.x*m0.x + a0.y*m0.y + a0.z*m0.z + a0.w*m0.w;
            float s1 = a1.x*m1.x + a1.y*m1.y + a1.z*m1.z + a1.w*m1.w;
            float s2 = a2.x*m2.x + a2.y*m2.y + a2.z*m2.z + a2.w*m2.w;
            float s3 = a3.x*m3.x + a3.y*m3.y + a3.z*m3.z + a3.w*m3.w;
            float s4 = c0.x*o0.x + c0.y*o0.y + c0.z*o0.z + c0.w*o0.w;
            float s5 = c1.x*o1.x + c1.y*o1.y + c1.z*o1.z + c1.w*o1.w;
            float acc = ((s0 + s1) + (s2 + s3)) + (s4 + s5);
            __syncwarp();
            if (lane < 16)      sMean[w][lane] = acc;
            else if (lane < 24) sY[w][lane - 16][s] = acc;
            __syncwarp();
        }
        __syncthreads();
        for (int idx = tid; idx < 64 * ns; idx += 256) {
            int s = idx % ns;
            int bm = idx / ns;
            int m = bm & 7, bb = bm >> 3;
            out[((size_t)(bg * 8 + bb) * MM + m) * TT + cstart + t0 + s + 1] = sY[bb][m][s];
        }
    }
}

// Kernel 7: exact per-batch fallback for NaN-containing batches
__global__ void slow_kernel(const float* __restrict__ x, const float* __restrict__ F_,
                            const float* __restrict__ H_, const float* __restrict__ Q_,
                            const float* __restrict__ R_, float* __restrict__ out) {
    int b = blockIdx.x;
    if (!g_nan[b]) return;
    int tid = threadIdx.x;
    __shared__ float sF[256], sH[128], sQ[256], sR[64];
    __shared__ float cov[256], covn[256], P[128], W[2][128], K[128], CU[256], FC[256];
    __shared__ float mean[16], meanu[16], meanp[16], obs[8], resid[8];
    __shared__ int nanb;

    sF[tid] = F_[tid];
    sQ[tid] = Q_[tid];
    if (tid < 128) sH[tid] = H_[tid];
    if (tid < 64)  sR[tid] = R_[tid];
    cov[tid] = ((tid >> 4) == (tid & 15)) ? 1.f : 0.f;
    if (tid < 16) mean[tid] = 0.f;
    if (tid < 8)  out[((size_t)b * MM + tid) * TT] = 0.f;
    __syncthreads();

    for (int t = 0; t < NS; t++) {
        if (tid == 0) {
            int nb = 0;
            for (int j = 0; j < 8; j++) {
                float v = x[((size_t)b * MM + j) * TT + t];
                if (isnan(v)) { nb = 1; v = 0.f; }
                obs[j] = v;
            }
            nanb = nb;
        }
        __syncthreads();
        if (tid < 128) {
            int i = tid >> 3, j = tid & 7;
            float s = 0.f;
            #pragma unroll
            for (int e = 0; e < 16; e++) s += cov[i * 16 + e] * sH[j * 16 + e];
            P[tid] = s;
        }
        if (tid >= 128 && tid < 136) {
            int j = tid - 128;
            float s = obs[j];
            #pragma unroll
            for (int e = 0; e < 16; e++) s -= sH[j * 16 + e] * mean[e];
            resid[j] = s;
        }
        __syncthreads();
        if (tid < 128) {
            int a = tid >> 4, c = tid & 15;
            float v;
            if (c < 8) {
                float s = sR[a * 8 + c];
                #pragma unroll
                for (int e = 0; e < 16; e++) s += sH[a * 16 + e] * P[e * 8 + c];
                v = s;
            } else v = (a == (c - 8)) ? 1.f : 0.f;
            W[0][a * 16 + c] = v;
        }
        __syncthreads();
        #pragma unroll 1
        for (int k = 0; k < 8; k++) {
            int cur = k & 1;
            if (tid < 128) {
                int a = tid >> 4, c = tid & 15;
                float piv = W[cur][k * 16 + k];
                float wkc = W[cur][k * 16 + c] / piv;
                W[cur ^ 1][a * 16 + c] = (a == k) ? wkc
                                                  : W[cur][a * 16 + c] - W[cur][a * 16 + k] * wkc;
            }
            __syncthreads();
        }
        if (tid < 128) {
            int i = tid >> 3, j = tid & 7;
            float s = 0.f;
            #pragma unroll
            for (int a = 0; a < 8; a++) s += P[i * 8 + a] * W[0][a * 16 + 8 + j];
            K[tid] = s;
        }
        __syncthreads();
        if (tid < 16) {
            float s = mean[tid];
            #pragma unroll
            for (int a = 0; a < 8; a++) s += K[tid * 8 + a] * resid[a];
            meanu[tid] = nanb ? mean[tid] : s;
        }
        {
            int i = tid >> 4, j = tid & 15;
            float s = cov[tid];
            #pragma unroll
            for (int a = 0; a < 8; a++) s -= K[i * 8 + a] * P[j * 8 + a];
            CU[tid] = nanb ? cov[tid] : s;
        }
        __syncthreads();
        {
            int i = tid >> 4, j = tid & 15;
            float s = 0.f;
            #pragma unroll
            for (int e = 0; e < 16; e++)
                s += sF[i * 16 + e] * 0.5f * (CU[e * 16 + j] + CU[j * 16 + e]);
            FC[tid] = s;
        }
        if (tid < 16) {
            float s = 0.f;
            #pragma unroll
            for (int e = 0; e < 16; e++) s += sF[tid * 16 + e] * meanu[e];
            meanp[tid] = s;
        }
        __syncthreads();
        {
            int i = tid >> 4, j = tid & 15;
            float s = sQ[tid];
            #pragma unroll
            for (int e = 0; e < 16; e++) s += FC[i * 16 + e] * sF[j * 16 + e];
            covn[tid] = s;
        }
        if (tid < 8) {
            float s = 0.f;
            #pragma unroll
            for (int e = 0; e < 16; e++) s += sH[tid * 16 + e] * meanp[e];
            out[((size_t)b * MM + tid) * TT + t + 1] = s;
        }
        __syncthreads();
        cov[tid] = covn[tid];
        if (tid < 16) mean[tid] = meanp[tid];
        __syncthreads();
    }
}

extern "C" void kernel_launch(void* const* d_in, const int* in_sizes, int n_in,
                              void* d_out, int out_size) {
    const float* x = (const float*)d_in[0];
    const float* F = (const float*)d_in[1];
    const float* H = (const float*)d_in[2];
    const float* Q = (const float*)d_in[3];
    const float* R = (const float*)d_in[4];
    float* out = (float*)d_out;

    phase1_kernel<<<1, 256>>>(F, H, Q, R);
    group_serial_kernel<<<NCH * 8, 256>>>();
    group_scan_kernel<<<NCH, 256>>>();
    apply_kernel<<<NCH * 7, 256>>>();
    bvec_kernel<<<NCH * (BS / BGB), 256>>>(x);   // also folds NaN detection
    scan_kernel<<<BS / 8, 256>>>();
    phase2b_kernel<<<NCH * (BS / 8), 256>>>(x, out);
    slow_kernel<<<BS, 256>>>(x, F, H, Q, R, out);
}

// round 16
// speedup vs baseline: 2.7133x; 1.0091x over previous
#include <cuda_runtime.h>
#include <math.h>

#define BS   512
#define MM   8
#define TT   2048
#define NS   2047
#define NCH  32
#define CL   64
#define SUB  8
#define CONV_EPS 4e-3f

#define S20(r,c) ((r)*20+(c))
#define S12(r,c) ((r)*12+(c))

// Packed maps: W1[t]=[M;G;0] (32x16), W2[t]=[N;D;0] (32x8); rows 24-31 stay 0.
__device__ float g_W1[(size_t)NS * 512];
__device__ float g_W2[(size_t)NS * 256];
__device__ float g_F[1024];            // fused frozen rows [32][32]
__device__ float g_P[NS * 128];
__device__ float g_T[NCH * 8 * 256];
__device__ float g_GS[NCH * 8 * 256];
__device__ float g_A[NCH * 256];
__device__ float g_b[BS * NCH * 16];
__device__ float g_m0[BS * NCH * 16];
__device__ int   g_tc;
__device__ int   g_nan[BS];            // OR-accumulated; inputs fixed per graph

__device__ __forceinline__ float dot16(const float* a, const float* b) {
    const float4* A = (const float4*)a; const float4* B = (const float4*)b;
    float4 a0=A[0],a1=A[1],a2=A[2],a3=A[3], b0=B[0],b1=B[1],b2=B[2],b3=B[3];
    float s0=a0.x*b0.x+a0.y*b0.y+a0.z*b0.z+a0.w*b0.w;
    float s1=a1.x*b1.x+a1.y*b1.y+a1.z*b1.z+a1.w*b1.w;
    float s2=a2.x*b2.x+a2.y*b2.y+a2.z*b2.z+a2.w*b2.w;
    float s3=a3.x*b3.x+a3.y*b3.y+a3.z*b3.z+a3.w*b3.w;
    return (s0+s1)+(s2+s3);
}
__device__ __forceinline__ float dot8(const float* a, const float* b) {
    const float4* A = (const float4*)a; const float4* B = (const float4*)b;
    float4 a0=A[0],a1=A[1], b0=B[0],b1=B[1];
    return (a0.x*b0.x+a0.y*b0.y+a0.z*b0.z+a0.w*b0.w)
         + (a1.x*b1.x+a1.y*b1.y+a1.z*b1.z+a1.w*b1.w);
}

// ---------------------------------------------------------------------------
// Phase 1: Riccati, 4 barriers/step.
//  s0: HC = H*cov (+deferred G store)      | X = F*cov
//  s1: S = HC*H^T + R                      | FP = rowdot(F,HC) | Y rows 0-3
//  s2: warp0: augmented GJ [S | FP^T] -> Nn (S SPD => Sinv sym => aug = Nn^T)
//      others: Y rows 4-15
//  s3: cov' = Y + Q - 0.5(Nn FP^T + FP Nn^T) ; M,N,D stores ; conv-or
// Fused frozen 2-step table built at the end.
// ---------------------------------------------------------------------------
__global__ void __launch_bounds__(256) phase1_kernel(
        const float* __restrict__ F_, const float* __restrict__ H_,
        const float* __restrict__ Q_, const float* __restrict__ R_) {
    __shared__ __align__(16) float sF[320], cov[320], X[320], Y[320];
    __shared__ __align__(16) float sH[160], sHF[160], HC[160], NnT[160], Gf[160];
    __shared__ __align__(16) float sHT[192], FP[192], Nn[192];
    __shared__ __align__(16) float D[96];
    __shared__ float W[64], sQ[256], sR[64];

    int tid = threadIdx.x;
    int i = tid >> 4, j = tid & 15;
    sF[S20(i, j)] = F_[tid];
    sQ[tid] = Q_[tid];
    if (tid < 128) sH[S20(tid >> 4, tid & 15)] = H_[tid];
    if (tid < 64)  sR[tid] = R_[tid];
    cov[S20(i, j)] = (i == j) ? 1.f : 0.f;
    __syncthreads();
    if (tid < 128) {
        int jj = tid >> 3, aa = tid & 7;
        sHT[S12(jj, aa)] = sH[S20(aa, jj)];
    } else {
        int u = tid - 128, aa = u >> 4, jj = u & 15;
        float s = 0.f;
        #pragma unroll
        for (int e = 0; e < 16; e++) s += sH[S20(aa, e)] * sF[S20(e, jj)];
        sHF[S20(aa, jj)] = s;
    }
    __syncthreads();

    int tc = NS;
    for (int t = 0; t < NS; t++) {
        // ---- s0
        if (tid < 128) {
            int a = tid >> 4, c = tid & 15;
            HC[S20(a, c)] = dot16(&sH[S20(a, 0)], &cov[S20(c, 0)]);
            if (t > 0)
                g_W1[(size_t)(t - 1) * 512 + 256 + tid] =
                    sHF[S20(a, c)] - dot8(&D[S12(a, 0)], &sHT[S12(c, 0)]);
        } else {
            int u = tid - 128, r = u >> 4, c = u & 15;
            X[S20(r, c)]     = dot16(&sF[S20(r, 0)],     &cov[S20(c, 0)]);
            X[S20(r + 8, c)] = dot16(&sF[S20(r + 8, 0)], &cov[S20(c, 0)]);
        }
        __syncthreads();
        // ---- s1
        if (tid < 64) {
            int a = tid >> 3, c = tid & 7;
            W[a * 8 + c] = sR[a * 8 + c] + dot16(&HC[S20(a, 0)], &sH[S20(c, 0)]);
        } else if (tid < 192) {
            int u = tid - 64, r = u >> 3, cc = u & 7;
            FP[S12(r, cc)] = dot16(&sF[S20(r, 0)], &HC[S20(cc, 0)]);
        } else {
            int u = tid - 192;                 // Y outputs 0..63 (rows 0-3)
            Y[S20(u >> 4, u & 15)] = dot16(&X[S20(u >> 4, 0)], &sF[S20(u & 15, 0)]);
        }
        __syncthreads();
        // ---- s2: warp0 augmented GJ ; others Y rows 4-15
        if (tid < 32) {
            int lane = tid;
            float w[8];
            if (lane < 8) {
                #pragma unroll
                for (int r = 0; r < 8; r++) w[r] = W[r * 8 + lane];
            } else {
                int jj = (lane - 8) & 15;       // lanes 24-31 duplicate rows 0-7
                #pragma unroll
                for (int r = 0; r < 8; r++) w[r] = FP[S12(jj, r)];
            }
            #pragma unroll
            for (int k = 0; k < 8; k++) {
                float a[8];
                #pragma unroll
                for (int r = 0; r < 8; r++)
                    a[r] = __shfl_sync(0xffffffffu, w[r], k);   // col k (pre-scale)
                float rp = __fdividef(1.0f, a[k]);
                w[k] *= rp;
                #pragma unroll
                for (int r = 0; r < 8; r++)
                    if (r != k) w[r] -= a[r] * w[k];
            }
            if (lane >= 8 && lane < 24) {
                int jj = lane - 8;               // w[a] = Nn[jj][a]
                #pragma unroll
                for (int a2 = 0; a2 < 8; a2++) {
                    Nn[S12(jj, a2)] = w[a2];
                    NnT[S20(a2, jj)] = w[a2];
                }
            }
        } else if (tid < 224) {
            int u = tid - 32 + 64;               // Y outputs 64..255 (rows 4-15)
            Y[S20(u >> 4, u & 15)] = dot16(&X[S20(u >> 4, 0)], &sF[S20(u & 15, 0)]);
        }
        __syncthreads();
        // ---- s3: cov update + M/N/D stores + convergence
        float cnew;
        {
            float t1 = dot8(&Nn[S12(i, 0)], &FP[S12(j, 0)]);
            float t2 = dot8(&FP[S12(i, 0)], &Nn[S12(j, 0)]);
            float m  = sF[S20(i, j)] - dot8(&Nn[S12(i, 0)], &sHT[S12(j, 0)]);
            cnew = Y[S20(i, j)] + sQ[tid] - 0.5f * (t1 + t2);
            g_W1[(size_t)t * 512 + tid] = m;
        }
        if (tid < 128) {
            g_W2[(size_t)t * 256 + tid] = Nn[S12(tid >> 3, tid & 7)];
        } else if (tid < 192) {
            int u = tid - 128, a = u >> 3, bb = u & 7;
            float d = dot16(&sH[S20(a, 0)], &NnT[S20(bb, 0)]);
            D[S12(a, bb)] = d;
            g_W2[(size_t)t * 256 + 128 + u] = d;
        }
        float oldc = cov[S20(i, j)];
        float dlt = fabsf(cnew - oldc);
        cov[S20(i, j)] = cnew;
        int any = __syncthreads_or(dlt > CONV_EPS * (fabsf(oldc) + 1e-2f));
        if (!any) { tc = t + 1; break; }
    }
    if (tid == 0) g_tc = tc;
    if (tid < 128) {
        int a = tid >> 4, c = tid & 15;
        float gv = sHF[S20(a, c)] - dot8(&D[S12(a, 0)], &sHT[S12(c, 0)]);
        g_W1[(size_t)(tc - 1) * 512 + 256 + tid] = gv;
        Gf[S20(a, c)] = gv;
    }
    __syncthreads();
    // fused frozen 2-step table: rows 0-15 [M^2|MN|N], 16-23 [G|D|0], 24-31 [GM|GN|D]
    for (int idx = tid; idx < 1024; idx += 256) {
        int r = idx >> 5, cc = idx & 31;
        float v = 0.f;
        if (r < 16) {
            if (cc < 16) {
                #pragma unroll
                for (int e = 0; e < 16; e++) {
                    float mre = sF[S20(r, e)] - dot8(&Nn[S12(r, 0)], &sHT[S12(e, 0)]);
                    float mec = sF[S20(e, cc)] - dot8(&Nn[S12(e, 0)], &sHT[S12(cc, 0)]);
                    v += mre * mec;
                }
            } else if (cc < 24) {
                #pragma unroll
                for (int e = 0; e < 16; e++) {
                    float mre = sF[S20(r, e)] - dot8(&Nn[S12(r, 0)], &sHT[S12(e, 0)]);
                    v += mre * Nn[S12(e, cc - 16)];
                }
            } else {
                v = Nn[S12(r, cc - 24)];
            }
        } else if (r < 24) {
            int jj = r - 16;
            if (cc < 16) v = Gf[S20(jj, cc)];
            else if (cc < 24) v = D[S12(jj, cc - 16)];
        } else {
            int jj = r - 24;
            if (cc < 16) {
                #pragma unroll
                for (int e = 0; e < 16; e++) {
                    float mec = sF[S20(e, cc)] - dot8(&Nn[S12(e, 0)], &sHT[S12(cc, 0)]);
                    v += Gf[S20(jj, e)] * mec;
                }
            } else if (cc < 24) {
                #pragma unroll
                for (int e = 0; e < 16; e++) v += Gf[S20(jj, e)] * Nn[S12(e, cc - 16)];
            } else {
                v = D[S12(jj, cc - 24)];
            }
        }
        g_F[idx] = v;
    }
}

// 3a: per-(chunk,group) 8-step serial suffix (clamped reads)
__global__ void __launch_bounds__(256) group_serial_kernel() {
    int c = blockIdx.x >> 3, g = blockIdx.x & 7;
    int base = c * CL + g * 8;
    int n = NS - base; if (n > 8) n = 8;
    int tcl = g_tc - 1;
    __shared__ float S[2][256], Mt[256], Nt[128];
    int tid = threadIdx.x;
    int i = tid >> 4, j = tid & 15;
    S[0][tid] = (i == j) ? 1.f : 0.f;
    int par = 0;
    int ts = base + n - 1; if (ts > tcl) ts = tcl;
    float mreg = g_W1[(size_t)ts * 512 + tid];
    float nreg = (tid < 128) ? g_W2[(size_t)ts * 256 + tid] : 0.f;
    __syncthreads();
    for (int it = n - 1; it >= 0; --it) {
        Mt[tid] = mreg;
        if (tid < 128) Nt[tid] = nreg;
        __syncthreads();
        if (it > 0) {
            int t2 = base + it - 1; if (t2 > tcl) t2 = tcl;
            mreg = g_W1[(size_t)t2 * 512 + tid];
            if (tid < 128) nreg = g_W2[(size_t)t2 * 256 + tid];
        }
        if (tid < 128) {
            int r = tid >> 3, cc = tid & 7;
            float s = 0.f;
            #pragma unroll
            for (int e = 0; e < 16; e++) s += S[par][r * 16 + e] * Nt[e * 8 + cc];
            g_P[(base + it) * 128 + tid] = s;
        }
        float sn = 0.f;
        #pragma unroll
        for (int e = 0; e < 16; e++) sn += S[par][i * 16 + e] * Mt[e * 16 + j];
        S[par ^ 1][tid] = sn;
        __syncthreads();
        par ^= 1;
    }
    g_T[(c * 8 + g) * 256 + tid] = S[par][tid];
}

// 3b: per-chunk scan of 8 group products -> GS_g, A_c   (32 blocks)
__global__ void __launch_bounds__(256) group_scan_kernel() {
    int c = blockIdx.x;
    __shared__ float S[2][256], Tt[256];
    int tid = threadIdx.x;
    int i = tid >> 4, j = tid & 15;
    S[0][tid] = (i == j) ? 1.f : 0.f;
    int par = 0;
    for (int g = 7; g >= 0; --g) {
        Tt[tid] = g_T[(c * 8 + g) * 256 + tid];
        __syncthreads();
        float v = 0.f;
        #pragma unroll
        for (int e = 0; e < 16; e++) v += S[par][i * 16 + e] * Tt[e * 16 + j];
        S[par ^ 1][tid] = v;
        if (g >= 1) g_GS[(c * 8 + g) * 256 + tid] = v;
        __syncthreads();
        par ^= 1;
    }
    g_A[c * 256 + tid] = S[par][tid];
}

// 3c: apply GS_{g+1} to U (groups 0..6)   (224 parallel blocks)
__global__ void __launch_bounds__(256) apply_kernel() {
    int c = blockIdx.x / 7, g = blockIdx.x % 7;
    int base = c * CL + g * 8;
    __shared__ float GSs[256], Us[1024];
    int tid = threadIdx.x;
    GSs[tid] = g_GS[(c * 8 + g + 1) * 256 + tid];
    #pragma unroll
    for (int q = 0; q < 4; q++) {
        int k = tid + q * 256;
        Us[k] = g_P[(base + (k >> 7)) * 128 + (k & 127)];
    }
    __syncthreads();
    #pragma unroll
    for (int q = 0; q < 4; q++) {
        int k = tid + q * 256;
        int p = k >> 7, rc = k & 127, r = rc >> 3, cc = rc & 7;
        float v = 0.f;
        #pragma unroll
        for (int e = 0; e < 16; e++) v += GSs[r * 16 + e] * Us[p * 128 + e * 8 + cc];
        g_P[(base + p) * 128 + rc] = v;
    }
}

// Kernel 4: b_c = sum_t P_t * obs_t + folded NaN detection.
#define BGB 8
__global__ void __launch_bounds__(256) bvec_kernel(const float* __restrict__ x) {
    int c = blockIdx.x & (NCH - 1);
    int bg = blockIdx.x >> 5;
    int cstart = c * CL;
    int clen = (NS - cstart < CL) ? (NS - cstart) : CL;
    __shared__ __align__(16) float sP[CL * 128];
    __shared__ __align__(16) float sX[BGB][CL][8];
    __shared__ int nanf[BGB];
    int tid = threadIdx.x;
    if (tid < BGB) nanf[tid] = 0;
    for (int idx = tid; idx < clen * 128; idx += 256)
        sP[idx] = g_P[cstart * 128 + idx];
    for (int idx = tid; idx < BGB * 8 * clen; idx += 256) {
        int s = idx % clen;
        int bm = idx / clen;
        int m = bm & 7, b = bm >> 3;
        float v = x[((size_t)(bg * BGB + b) * MM + m) * TT + cstart + s];
        if (isnan(v)) atomicOr(&nanf[b], 1);
        sX[b][s][m] = v;
    }
    __syncthreads();
    if (tid < BGB && nanf[tid]) atomicOr(&g_nan[bg * BGB + tid], 1);
    int w = tid >> 5, lane = tid & 31;
    int b = bg * BGB + w;
    int row = lane & 15;
    float acc = 0.f;
    for (int s = (lane >> 4); s < clen; s += 2) {
        const float4* pp = (const float4*)&sP[s * 128 + row * 8];
        float4 p0 = pp[0], p1 = pp[1];
        const float4* op = (const float4*)&sX[w][s][0];
        float4 o0 = op[0], o1 = op[1];
        acc += p0.x*o0.x + p0.y*o0.y + p0.z*o0.z + p0.w*o0.w
             + p1.x*o1.x + p1.y*o1.y + p1.z*o1.z + p1.w*o1.w;
    }
    acc += __shfl_xor_sync(0xffffffffu, acc, 16);
    if (lane < 16) g_b[(b * NCH + c) * 16 + lane] = acc;
}

// Kernel 5: serial scan over 32 chunks; split-K across half-warps.
__global__ void __launch_bounds__(256) scan_kernel() {
    __shared__ float sA[NCH * 256];
    int tid = threadIdx.x;
    for (int idx = tid; idx < NCH * 256; idx += 256) sA[idx] = g_A[idx];
    __syncthreads();
    int w = tid >> 5, lane = tid & 31;
    int b = blockIdx.x * 8 + w;
    int row = lane & 15;
    int half8 = (lane >> 4) << 3;
    float mean_i = 0.f;
    float breg = (lane < 16) ? g_b[(b * NCH + 0) * 16 + lane] : 0.f;
    for (int c = 0; c < NCH; c++) {
        if (lane < 16) g_m0[(b * NCH + c) * 16 + lane] = mean_i;
        float bn = (lane < 16 && c + 1 < NCH) ? g_b[(b * NCH + c + 1) * 16 + lane] : 0.f;
        float nm = breg;
        #pragma unroll
        for (int e = 0; e < 8; e++) {
            float me = __shfl_sync(0xffffffffu, mean_i, half8 + e);
            nm += sA[c * 256 + row * 16 + half8 + e] * me;
        }
        nm += __shfl_xor_sync(0xffffffffu, nm, 16);
        mean_i = nm;
        breg = bn;
    }
}

// ---------------------------------------------------------------------------
// Kernel 6: within-chunk recursion + output (unchanged).
// ---------------------------------------------------------------------------
__global__ void __launch_bounds__(256) phase2b_kernel(const float* __restrict__ x,
                                                      float* __restrict__ out) {
    int c = blockIdx.x & (NCH - 1);
    int bg = blockIdx.x >> 5;
    int cstart = c * CL;
    int clen = (NS - cstart < CL) ? (NS - cstart) : CL;
    int tid = threadIdx.x, w = tid >> 5, lane = tid & 31;
    int b = bg * 8 + w;
    int tcl = g_tc;

    __shared__ __align__(16) float sB[8][32];

    if (cstart >= tcl) {
        const float* xb = x + (size_t)b * MM * TT;
        float* ob = out + (size_t)b * MM * TT;
        const float4* Fp = (const float4*)(g_F + lane * 32);
        float4 R0 = Fp[0], R1 = Fp[1], R2 = Fp[2], R3 = Fp[3];
        float4 R4 = Fp[4], R5 = Fp[5], R6 = Fp[6], R7 = Fp[7];

        if (lane < 16) sB[w][lane] = g_m0[(b * NCH + c) * 16 + lane];

        int m = lane & 7;
        int tend = cstart + clen;
        float nextobs = 0.f;
        if (lane >= 16)
            nextobs = xb[(size_t)m * TT + cstart + ((lane >= 24) ? 1 : 0)];

        int t = cstart;
        int nd = clen >> 1;
        for (int it = 0; it < nd; it++, t += 2) {
            if (lane >= 16) sB[w][lane] = nextobs;
            __syncwarp();
            const float4* bp = (const float4*)&sB[w][0];
            float4 m0 = bp[0], m1 = bp[1], m2 = bp[2], m3 = bp[3];
            float4 oa = bp[4], obv = bp[5], oc = bp[6], od = bp[7];
            if (lane >= 16) {
                int tn = t + 2 + ((lane >= 24) ? 1 : 0);
                if (tn < tend) nextobs = xb[(size_t)m * TT + tn];
            }
            float s0 = R0.x*m0.x + R0.y*m0.y + R0.z*m0.z + R0.w*m0.w;
            float s1 = R1.x*m1.x + R1.y*m1.y + R1.z*m1.z + R1.w*m1.w;
            float s2 = R2.x*m2.x + R2.y*m2.y + R2.z*m2.z + R2.w*m2.w;
            float s3 = R3.x*m3.x + R3.y*m3.y + R3.z*m3.z + R3.w*m3.w;
            float s4 = R4.x*oa.x + R4.y*oa.y + R4.z*oa.z + R4.w*oa.w;
            float s5 = R5.x*obv.x + R5.y*obv.y + R5.z*obv.z + R5.w*obv.w;
            float s6 = R6.x*oc.x + R6.y*oc.y + R6.z*oc.z + R6.w*oc.w;
            float s7 = R7.x*od.x + R7.y*od.y + R7.z*od.z + R7.w*od.w;
            float acc = ((s0 + s1) + (s2 + s3)) + ((s4 + s5) + (s6 + s7));

            if (lane >= 16)
                ob[(size_t)m * TT + t + ((lane >= 24) ? 2 : 1)] = acc;
            __syncwarp();
            if (lane < 16) sB[w][lane] = acc;
        }
        if (clen & 1) {
            if (lane >= 16) sB[w][lane] = nextobs;
            __syncwarp();
            const float4* bp = (const float4*)&sB[w][0];
            float4 m0 = bp[0], m1 = bp[1], m2 = bp[2], m3 = bp[3];
            float4 oa = bp[4], obv = bp[5], oc = bp[6], od = bp[7];
            float s0 = R0.x*m0.x + R0.y*m0.y + R0.z*m0.z + R0.w*m0.w;
            float s1 = R1.x*m1.x + R1.y*m1.y + R1.z*m1.z + R1.w*m1.w;
            float s2 = R2.x*m2.x + R2.y*m2.y + R2.z*m2.z + R2.w*m2.w;
            float s3 = R3.x*m3.x + R3.y*m3.y + R3.z*m3.z + R3.w*m3.w;
            float s4 = R4.x*oa.x + R4.y*oa.y + R4.z*oa.z + R4.w*oa.w;
            float s5 = R5.x*obv.x + R5.y*obv.y + R5.z*obv.z + R5.w*obv.w;
            float s6 = R6.x*oc.x + R6.y*oc.y + R6.z*oc.z + R6.w*oc.w;
            float s7 = R7.x*od.x + R7.y*od.y + R7.z*od.z + R7.w*od.w;
            float acc = ((s0 + s1) + (s2 + s3)) + ((s4 + s5) + (s6 + s7));
            if (lane >= 16 && lane < 24)
                ob[(size_t)m * TT + t + 1] = acc;
        }
        return;
    }

    // ---- transient smem path (clamped matrix reads) ----
    __shared__ __align__(16) float sW1[SUB][32][20];
    __shared__ __align__(16) float sW2[SUB][32][12];
    __shared__ __align__(16) float sX[8][SUB][8];
    __shared__ __align__(16) float sY[8][8][SUB];
    __shared__ __align__(16) float sMean[8][16];

    const size_t xbase = (size_t)b * MM * TT;
    if (lane < 16) sMean[w][lane] = g_m0[(b * NCH + c) * 16 + lane];
    if (c == 0 && lane < 8) out[xbase + (size_t)lane * TT] = 0.f;
    __syncwarp();

    for (int t0 = 0; t0 < clen; t0 += SUB) {
        int ns = (clen - t0 < SUB) ? (clen - t0) : SUB;
        __syncthreads();
        for (int idx = tid; idx < ns * 512; idx += 256) {
            int s = idx >> 9, rc = idx & 511;
            int ts = cstart + t0 + s; if (ts >= tcl) ts = tcl - 1;
            sW1[s][rc >> 4][rc & 15] = g_W1[(size_t)ts * 512 + rc];
        }
        for (int idx = tid; idx < ns * 256; idx += 256) {
            int s = idx >> 8, rc = idx & 255;
            int ts = cstart + t0 + s; if (ts >= tcl) ts = tcl - 1;
            sW2[s][rc >> 3][rc & 7] = g_W2[(size_t)ts * 256 + rc];
        }
        for (int idx = tid; idx < 64 * ns; idx += 256) {
            int s = idx % ns;
            int bm = idx / ns;
            int m = bm & 7, bb = bm >> 3;
            sX[bb][s][m] = x[((size_t)(bg * 8 + bb) * MM + m) * TT + cstart + t0 + s];
        }
        __syncthreads();

        for (int s = 0; s < ns; s++) {
            const float4* w1 = (const float4*)&sW1[s][lane][0];
            float4 a0 = w1[0], a1 = w1[1], a2 = w1[2], a3 = w1[3];
            const float4* w2 = (const float4*)&sW2[s][lane][0];
            float4 c0 = w2[0], c1 = w2[1];
            const float4* mp = (const float4*)&sMean[w][0];
            float4 m0 = mp[0], m1 = mp[1], m2 = mp[2], m3 = mp[3];
            const float4* op = (const float4*)&sX[w][s][0];
            float4 o0 = op[0], o1 = op[1];
            float s0 = a0.x*m0.x + a0.y*m0.y + a0.z*m0.z + a0.w*m0.w;
            float s1 = a1.x*m1.x + a1.y*m1.y + a1.z*m1.z + a1.w*m1.w;
            float s2 = a2.x*m2.x + a2.y*m2.y + a2.z*m2.z + a2.w*m2.w;
            float s3 = a3.x*m3.x + a3.y*m3.y + a3.z*m3.z + a3.w*m3.w;
            float s4 = c0.x*o0.x + c0.y*o0.y + c0.z*o0.z + c0.w*o0.w;
            float s5 = c1.x*o1.x + c1.y*o1.y + c1.z*o1.z + c1.w*o1.w;
            float acc = ((s0 + s1) + (s2 + s3)) + (s4 + s5);
            __syncwarp();
            if (lane < 16)      sMean[w][lane] = acc;
            else if (lane < 24) sY[w][lane - 16][s] = acc;
            __syncwarp();
        }
        __syncthreads();
        for (int idx = tid; idx < 64 * ns; idx += 256) {
            int s = idx % ns;
            int bm = idx / ns;
            int m = bm & 7, bb = bm >> 3;
            out[((size_t)(bg * 8 + bb) * MM + m) * TT + cstart + t0 + s + 1] = sY[bb][m][s];
        }
    }
}

// Kernel 7: exact per-batch fallback for NaN-containing batches
__global__ void slow_kernel(const float* __restrict__ x, const float* __restrict__ F_,
                            const float* __restrict__ H_, const float* __restrict__ Q_,
                            const float* __restrict__ R_, float* __restrict__ out) {
    int b = blockIdx.x;
    if (!g_nan[b]) return;
    int tid = threadIdx.x;
    __shared__ float sF[256], sH[128], sQ[256], sR[64];
    __shared__ float cov[256], covn[256], P[128], W[2][128], K[128], CU[256], FC[256];
    __shared__ float mean[16], meanu[16], meanp[16], obs[8], resid[8];
    __shared__ int nanb;

    sF[tid] = F_[tid];
    sQ[tid] = Q_[tid];
    if (tid < 128) sH[tid] = H_[tid];
    if (tid < 64)  sR[tid] = R_[tid];
    cov[tid] = ((tid >> 4) == (tid & 15)) ? 1.f : 0.f;
    if (tid < 16) mean[tid] = 0.f;
    if (tid < 8)  out[((size_t)b * MM + tid) * TT] = 0.f;
    __syncthreads();

    for (int t = 0; t < NS; t++) {
        if (tid == 0) {
            int nb = 0;
            for (int j = 0; j < 8; j++) {
                float v = x[((size_t)b * MM + j) * TT + t];
                if (isnan(v)) { nb = 1; v = 0.f; }
                obs[j] = v;
            }
            nanb = nb;
        }
        __syncthreads();
        if (tid < 128) {
            int i = tid >> 3, j = tid & 7;
            float s = 0.f;
            #pragma unroll
            for (int e = 0; e < 16; e++) s += cov[i * 16 + e] * sH[j * 16 + e];
            P[tid] = s;
        }
        if (tid >= 128 && tid < 136) {
            int j = tid - 128;
            float s = obs[j];
            #pragma unroll
            for (int e = 0; e < 16; e++) s -= sH[j * 16 + e] * mean[e];
            resid[j] = s;
        }
        __syncthreads();
        if (tid < 128) {
            int a = tid >> 4, c = tid & 15;
            float v;
            if (c < 8) {
                float s = sR[a * 8 + c];
                #pragma unroll
                for (int e = 0; e < 16; e++) s += sH[a * 16 + e] * P[e * 8 + c];
                v = s;
            } else v = (a == (c - 8)) ? 1.f : 0.f;
            W[0][a * 16 + c] = v;
        }
        __syncthreads();
        #pragma unroll 1
        for (int k = 0; k < 8; k++) {
            int cur = k & 1;
            if (tid < 128) {
                int a = tid >> 4, c = tid & 15;
                float piv = W[cur][k * 16 + k];
                float wkc = W[cur][k * 16 + c] / piv;
                W[cur ^ 1][a * 16 + c] = (a == k) ? wkc
                                                  : W[cur][a * 16 + c] - W[cur][a * 16 + k] * wkc;
            }
            __syncthreads();
        }
        if (tid < 128) {
            int i = tid >> 3, j = tid & 7;
            float s = 0.f;
            #pragma unroll
            for (int a = 0; a < 8; a++) s += P[i * 8 + a] * W[0][a * 16 + 8 + j];
            K[tid] = s;
        }
        __syncthreads();
        if (tid < 16) {
            float s = mean[tid];
            #pragma unroll
            for (int a = 0; a < 8; a++) s += K[tid * 8 + a] * resid[a];
            meanu[tid] = nanb ? mean[tid] : s;
        }
        {
            int i = tid >> 4, j = tid & 15;
            float s = cov[tid];
            #pragma unroll
            for (int a = 0; a < 8; a++) s -= K[i * 8 + a] * P[j * 8 + a];
            CU[tid] = nanb ? cov[tid] : s;
        }
        __syncthreads();
        {
            int i = tid >> 4, j = tid & 15;
            float s = 0.f;
            #pragma unroll
            for (int e = 0; e < 16; e++)
                s += sF[i * 16 + e] * 0.5f * (CU[e * 16 + j] + CU[j * 16 + e]);
            FC[tid] = s;
        }
        if (tid < 16) {
            float s = 0.f;
            #pragma unroll
            for (int e = 0; e < 16; e++) s += sF[tid * 16 + e] * meanu[e];
            meanp[tid] = s;
        }
        __syncthreads();
        {
            int i = tid >> 4, j = tid & 15;
            float s = sQ[tid];
            #pragma unroll
            for (int e = 0; e < 16; e++) s += FC[i * 16 + e] * sF[j * 16 + e];
            covn[tid] = s;
        }
        if (tid < 8) {
            float s = 0.f;
            #pragma unroll
            for (int e = 0; e < 16; e++) s += sH[tid * 16 + e] * meanp[e];
            out[((size_t)b * MM + tid) * TT + t + 1] = s;
        }
        __syncthreads();
        cov[tid] = covn[tid];
        if (tid < 16) mean[tid] = meanp[tid];
        __syncthreads();
    }
}

extern "C" void kernel_launch(void* const* d_in, const int* in_sizes, int n_in,
                              void* d_out, int out_size) {
    const float* x = (const float*)d_in[0];
    const float* F = (const float*)d_in[1];
    const float* H = (const float*)d_in[2];
    const float* Q = (const float*)d_in[3];
    const float* R = (const float*)d_in[4];
    float* out = (float*)d_out;

    phase1_kernel<<<1, 256>>>(F, H, Q, R);
    group_serial_kernel<<<NCH * 8, 256>>>();
    group_scan_kernel<<<NCH, 256>>>();
    apply_kernel<<<NCH * 7, 256>>>();
    bvec_kernel<<<NCH * (BS / BGB), 256>>>(x);   // also folds NaN detection
    scan_kernel<<<BS / 8, 256>>>();
    phase2b_kernel<<<NCH * (BS / 8), 256>>>(x, out);
    slow_kernel<<<BS, 256>>>(x, F, H, Q, R, out);
}